// round 1
// baseline (speedup 1.0000x reference)
#include <cuda_runtime.h>
#include <math.h>

#define L_SEQ 2048
#define D_MODEL 768
#define D_INNER 1536
#define E2 3072
#define DS 16
#define DR 48
#define XD 80
#define BSZ 2
#define NCH 16
#define CHL 128
#define NTOK 4096

// ---------------- scratch (static device allocations; no cudaMalloc) ----------------
__device__ float g_xz[BSZ * E2 * L_SEQ];              // [b][e][l]
__device__ float g_xc[2][BSZ * D_INNER * L_SEQ];      // conv+silu x, per branch (br1 time-reversed)
__device__ float g_xdbl[2][BSZ * XD * L_SEQ];         // [br][b][k][l]
__device__ float g_dt[2][BSZ * D_INNER * L_SEQ];      // softplus(dt)
__device__ float g_hfin[2 * BSZ * D_INNER * NCH * DS];
__device__ float g_P[2 * BSZ * D_INNER * NCH * DS];
__device__ float g_Hinit[2 * BSZ * D_INNER * NCH * DS];
__device__ float g_acc[2][BSZ * D_INNER * L_SEQ];     // y*silu(z) per branch

__device__ __forceinline__ float siluf(float v) {
    return v * (1.f / (1.f + __expf(-v)));
}
__device__ __forceinline__ float softplusf(float v) {
    return v > 15.f ? v : log1pf(__expf(v));
}

// ---------------- GEMM1: xz[b,e,l] = sum_d hid[b,l,d] * Win[e,d] ----------------
__global__ __launch_bounds__(256) void k_gemm_xz(const float* __restrict__ hid,
                                                 const float* __restrict__ Win) {
    __shared__ float As[2][8][128];
    __shared__ float Bs[2][8][128];
    const int tid = threadIdx.x;
    const int e0 = blockIdx.x * 128;
    const int t0 = blockIdx.y * 128;
    const int bb = t0 >> 11;
    const int l0 = t0 & (L_SEQ - 1);
    const int lr = tid >> 1;
    const int lc = (tid & 1) * 4;
    const int tx = tid & 15, ty = tid >> 4;

    const float* Ap = Win + (e0 + lr) * D_MODEL + lc;
    const float* Bp = hid + (t0 + lr) * D_MODEL + lc;

    float4 ra = *(const float4*)Ap;
    float4 rb = *(const float4*)Bp;
    As[0][lc + 0][lr] = ra.x; As[0][lc + 1][lr] = ra.y; As[0][lc + 2][lr] = ra.z; As[0][lc + 3][lr] = ra.w;
    Bs[0][lc + 0][lr] = rb.x; Bs[0][lc + 1][lr] = rb.y; Bs[0][lc + 2][lr] = rb.z; Bs[0][lc + 3][lr] = rb.w;
    __syncthreads();

    float acc[8][8];
#pragma unroll
    for (int i = 0; i < 8; i++)
#pragma unroll
        for (int j = 0; j < 8; j++) acc[i][j] = 0.f;

    int buf = 0;
    const int NK = D_MODEL / 8;
    for (int kt = 0; kt < NK; ++kt) {
        if (kt + 1 < NK) {
            ra = *(const float4*)(Ap + (kt + 1) * 8);
            rb = *(const float4*)(Bp + (kt + 1) * 8);
        }
#pragma unroll
        for (int kk = 0; kk < 8; kk++) {
            float4 a0 = *(const float4*)&As[buf][kk][ty * 8];
            float4 a1 = *(const float4*)&As[buf][kk][ty * 8 + 4];
            float4 b0 = *(const float4*)&Bs[buf][kk][tx * 8];
            float4 b1 = *(const float4*)&Bs[buf][kk][tx * 8 + 4];
            float av[8] = {a0.x, a0.y, a0.z, a0.w, a1.x, a1.y, a1.z, a1.w};
            float bv[8] = {b0.x, b0.y, b0.z, b0.w, b1.x, b1.y, b1.z, b1.w};
#pragma unroll
            for (int i = 0; i < 8; i++)
#pragma unroll
                for (int j = 0; j < 8; j++) acc[i][j] = fmaf(av[i], bv[j], acc[i][j]);
        }
        if (kt + 1 < NK) {
            buf ^= 1;
            As[buf][lc + 0][lr] = ra.x; As[buf][lc + 1][lr] = ra.y; As[buf][lc + 2][lr] = ra.z; As[buf][lc + 3][lr] = ra.w;
            Bs[buf][lc + 0][lr] = rb.x; Bs[buf][lc + 1][lr] = rb.y; Bs[buf][lc + 2][lr] = rb.z; Bs[buf][lc + 3][lr] = rb.w;
            __syncthreads();
        }
    }

#pragma unroll
    for (int i = 0; i < 8; i++) {
        int e = e0 + ty * 8 + i;
        float* cp = g_xz + ((bb * E2 + e) * L_SEQ + l0 + tx * 8);
        *(float4*)cp = make_float4(acc[i][0], acc[i][1], acc[i][2], acc[i][3]);
        *(float4*)(cp + 4) = make_float4(acc[i][4], acc[i][5], acc[i][6], acc[i][7]);
    }
}

// ---------------- depthwise causal conv (fwd) + anticausal (bwd, stored reversed) + SiLU --------
__global__ __launch_bounds__(256) void k_conv(const float* __restrict__ cw, const float* __restrict__ cb,
                                              const float* __restrict__ cwb, const float* __restrict__ cbb) {
    const int tid = threadIdx.x;
    const int l0 = blockIdx.x * 256;
    const int d = blockIdx.y;
    const int b = blockIdx.z;
    __shared__ float xs[262];
    const float* xp = g_xz + (b * E2 + d) * L_SEQ;
    for (int i = tid; i < 262; i += 256) {
        int l = l0 - 3 + i;
        xs[i] = (l >= 0 && l < L_SEQ) ? xp[l] : 0.f;
    }
    __syncthreads();
    float wf0 = cw[d * 4 + 0], wf1 = cw[d * 4 + 1], wf2 = cw[d * 4 + 2], wf3 = cw[d * 4 + 3];
    float wb0 = cwb[d * 4 + 0], wb1 = cwb[d * 4 + 1], wb2 = cwb[d * 4 + 2], wb3 = cwb[d * 4 + 3];
    float bf = cb[d], bback = cbb[d];
    int l = l0 + tid;
    float sf = bf + wf0 * xs[tid] + wf1 * xs[tid + 1] + wf2 * xs[tid + 2] + wf3 * xs[tid + 3];
    float sb = bback + wb0 * xs[tid + 6] + wb1 * xs[tid + 5] + wb2 * xs[tid + 4] + wb3 * xs[tid + 3];
    g_xc[0][(b * D_INNER + d) * L_SEQ + l] = siluf(sf);
    g_xc[1][(b * D_INNER + d) * L_SEQ + (L_SEQ - 1 - l)] = siluf(sb);
}

// ---------------- x_dbl[br][b,k,l] = sum_d xc[br][b,d,l] * Wx[k,d]  (M=80) ----------------
__global__ __launch_bounds__(256) void k_xdbl(const float* __restrict__ Wx, const float* __restrict__ Wxb) {
    __shared__ float As[16][80];
    __shared__ float Bs[16][128];
    const int tid = threadIdx.x;
    const int l0 = blockIdx.x * 128;
    const int b = blockIdx.y;
    const int br = blockIdx.z;
    const float* W = br ? Wxb : Wx;
    const float* xc = g_xc[br];
    const int tx = tid & 15, ty = tid >> 4;

    float acc[5][8];
#pragma unroll
    for (int i = 0; i < 5; i++)
#pragma unroll
        for (int j = 0; j < 8; j++) acc[i][j] = 0.f;

    for (int kt = 0; kt < D_INNER / 16; ++kt) {
        __syncthreads();
        for (int lin = tid; lin < 1280; lin += 256) {
            int k = lin >> 4, i = lin & 15;
            As[i][k] = W[k * D_INNER + kt * 16 + i];
        }
        for (int lin = tid; lin < 2048; lin += 256) {
            int r = lin >> 7, c = lin & 127;
            Bs[r][c] = xc[(b * D_INNER + kt * 16 + r) * L_SEQ + l0 + c];
        }
        __syncthreads();
#pragma unroll
        for (int kk = 0; kk < 16; kk++) {
            float av[5], bv[8];
#pragma unroll
            for (int i = 0; i < 5; i++) av[i] = As[kk][ty * 5 + i];
            float4 b0 = *(const float4*)&Bs[kk][tx * 8];
            float4 b1 = *(const float4*)&Bs[kk][tx * 8 + 4];
            bv[0] = b0.x; bv[1] = b0.y; bv[2] = b0.z; bv[3] = b0.w;
            bv[4] = b1.x; bv[5] = b1.y; bv[6] = b1.z; bv[7] = b1.w;
#pragma unroll
            for (int i = 0; i < 5; i++)
#pragma unroll
                for (int j = 0; j < 8; j++) acc[i][j] = fmaf(av[i], bv[j], acc[i][j]);
        }
    }
#pragma unroll
    for (int i = 0; i < 5; i++) {
        float* op = g_xdbl[br] + (b * XD + ty * 5 + i) * L_SEQ + l0 + tx * 8;
        *(float4*)op = make_float4(acc[i][0], acc[i][1], acc[i][2], acc[i][3]);
        *(float4*)(op + 4) = make_float4(acc[i][4], acc[i][5], acc[i][6], acc[i][7]);
    }
}

// ---------------- dt[br][b,d,l] = softplus(sum_r xdbl[br][b,r,l] * Wdt[d,r] + bdt[d]) ----------
__global__ __launch_bounds__(256) void k_dt(const float* __restrict__ Wdt, const float* __restrict__ bdt,
                                            const float* __restrict__ Wdtb, const float* __restrict__ bdtb) {
    __shared__ float As[48][128];
    __shared__ float Bs[48][64];
    const int tid = threadIdx.x;
    const int d0 = blockIdx.x * 128;
    const int l0 = blockIdx.y * 64;
    const int zb = blockIdx.z;
    const int br = zb >> 1, b = zb & 1;
    const float* W = br ? Wdtb : Wdt;
    const float* bias = br ? bdtb : bdt;
    const float* xd = g_xdbl[br];

    for (int lin = tid * 4; lin < 6144; lin += 1024) {
        int row = lin / 48, c = lin % 48;
        float4 v = *(const float4*)(W + (d0 + row) * DR + c);
        As[c + 0][row] = v.x; As[c + 1][row] = v.y; As[c + 2][row] = v.z; As[c + 3][row] = v.w;
    }
    for (int lin = tid * 4; lin < 3072; lin += 1024) {
        int r = lin >> 6, c = lin & 63;
        *(float4*)&Bs[r][c] = *(const float4*)(xd + (b * XD + r) * L_SEQ + l0 + c);
    }
    __syncthreads();

    const int tx = tid & 15, ty = tid >> 4;
    float acc[8][4];
#pragma unroll
    for (int i = 0; i < 8; i++)
#pragma unroll
        for (int j = 0; j < 4; j++) acc[i][j] = 0.f;

#pragma unroll 4
    for (int k = 0; k < 48; k++) {
        float4 a0 = *(const float4*)&As[k][ty * 8];
        float4 a1 = *(const float4*)&As[k][ty * 8 + 4];
        float av[8] = {a0.x, a0.y, a0.z, a0.w, a1.x, a1.y, a1.z, a1.w};
        float4 bq = *(const float4*)&Bs[k][tx * 4];
        float bv[4] = {bq.x, bq.y, bq.z, bq.w};
#pragma unroll
        for (int i = 0; i < 8; i++)
#pragma unroll
            for (int j = 0; j < 4; j++) acc[i][j] = fmaf(av[i], bv[j], acc[i][j]);
    }
#pragma unroll
    for (int i = 0; i < 8; i++) {
        int d = d0 + ty * 8 + i;
        float bi = bias[d];
        float4 o;
        o.x = softplusf(acc[i][0] + bi);
        o.y = softplusf(acc[i][1] + bi);
        o.z = softplusf(acc[i][2] + bi);
        o.w = softplusf(acc[i][3] + bi);
        *(float4*)(g_dt[br] + (b * D_INNER + d) * L_SEQ + l0 + tx * 4) = o;
    }
}

// ---------------- scan pass 1: per-chunk local scan from h=0; record final h and decay product --
__global__ __launch_bounds__(128) void k_scan1(const float* __restrict__ Alog, const float* __restrict__ Alogb) {
    const int tid = threadIdx.x;
    const int d = blockIdx.x * 128 + tid;
    const int chunk = blockIdx.y;
    const int zb = blockIdx.z;
    const int br = zb >> 1, b = zb & 1;
    const float* Al = br ? Alogb : Alog;
    float a[DS];
#pragma unroll
    for (int n = 0; n < DS; n++) a[n] = -expf(Al[d * DS + n]);

    __shared__ float Bsh[CHL][DS + 1];
    const int l0 = chunk * CHL;
    const float* xd = g_xdbl[br] + (b * XD) * L_SEQ;
    for (int i = tid; i < CHL * DS; i += 128) {
        int n = i >> 7, t = i & (CHL - 1);
        Bsh[t][n] = xd[(DR + n) * L_SEQ + l0 + t];
    }
    __syncthreads();

    const float* dtp = g_dt[br] + (b * D_INNER + d) * L_SEQ + l0;
    const float* xp = g_xc[br] + (b * D_INNER + d) * L_SEQ + l0;
    float h[DS], P[DS];
#pragma unroll
    for (int n = 0; n < DS; n++) { h[n] = 0.f; P[n] = 1.f; }

#pragma unroll 2
    for (int t = 0; t < CHL; t++) {
        float dt = dtp[t], x = xp[t];
        float dtx = dt * x;
#pragma unroll
        for (int n = 0; n < DS; n++) {
            float dA = __expf(dt * a[n]);
            h[n] = fmaf(dA, h[n], dtx * Bsh[t][n]);
            P[n] *= dA;
        }
    }
    size_t base = ((size_t)(zb * D_INNER + d) * NCH + chunk) * DS;
#pragma unroll
    for (int n = 0; n < DS; n++) { g_hfin[base + n] = h[n]; g_P[base + n] = P[n]; }
}

// ---------------- scan pass 2: cross-chunk prefix (tiny) ----------------
__global__ void k_scan2() {
    int id = blockIdx.x * blockDim.x + threadIdx.x;
    if (id >= 2 * BSZ * D_INNER * DS) return;
    int n = id & 15;
    int rest = id >> 4;
    int d = rest % D_INNER;
    int zb = rest / D_INNER;
    size_t base = ((size_t)(zb * D_INNER + d)) * (NCH * DS) + n;
    float H = 0.f;
#pragma unroll
    for (int c = 0; c < NCH; c++) {
        g_Hinit[base + c * DS] = H;
        H = g_P[base + c * DS] * H + g_hfin[base + c * DS];
    }
}

// ---------------- scan pass 3: replay with correct init, emit y = (C.h + D*x)*silu(z) ----------
__global__ __launch_bounds__(128) void k_scan3(const float* __restrict__ Alog, const float* __restrict__ Alogb,
                                               const float* __restrict__ Dp, const float* __restrict__ Dpb) {
    const int tid = threadIdx.x;
    const int d = blockIdx.x * 128 + tid;
    const int chunk = blockIdx.y;
    const int zb = blockIdx.z;
    const int br = zb >> 1, b = zb & 1;
    const float* Al = br ? Alogb : Alog;
    float a[DS];
#pragma unroll
    for (int n = 0; n < DS; n++) a[n] = -expf(Al[d * DS + n]);

    __shared__ float Bsh[CHL][DS + 1];
    __shared__ float Csh[CHL][DS + 1];
    const int l0 = chunk * CHL;
    const float* xd = g_xdbl[br] + (b * XD) * L_SEQ;
    for (int i = tid; i < CHL * DS; i += 128) {
        int n = i >> 7, t = i & (CHL - 1);
        Bsh[t][n] = xd[(DR + n) * L_SEQ + l0 + t];
        Csh[t][n] = xd[(DR + DS + n) * L_SEQ + l0 + t];
    }
    __syncthreads();

    size_t sbase = ((size_t)(zb * D_INNER + d) * NCH + chunk) * DS;
    float h[DS];
#pragma unroll
    for (int n = 0; n < DS; n++) h[n] = g_Hinit[sbase + n];
    float Dd = (br ? Dpb : Dp)[d];

    const float* dtp = g_dt[br] + (b * D_INNER + d) * L_SEQ + l0;
    const float* xp = g_xc[br] + (b * D_INNER + d) * L_SEQ + l0;
    const float* zp = g_xz + (b * E2 + D_INNER + d) * L_SEQ;
    float* op = g_acc[br] + (b * D_INNER + d) * L_SEQ + l0;

#pragma unroll 2
    for (int t = 0; t < CHL; t++) {
        float dt = dtp[t], x = xp[t];
        float dtx = dt * x;
        float y = 0.f;
#pragma unroll
        for (int n = 0; n < DS; n++) {
            float dA = __expf(dt * a[n]);
            h[n] = fmaf(dA, h[n], dtx * Bsh[t][n]);
            y = fmaf(h[n], Csh[t][n], y);
        }
        int l = l0 + t;
        float zv = br ? zp[(L_SEQ - 1) - l] : zp[l];
        op[t] = (y + Dd * x) * siluf(zv);
    }
}

// ---------------- GEMM out: out[b,l,m] = sum_d 0.5*(accF[b,d,l]+accB[b,d,L-1-l]) * Wout[m,d] ----
__global__ __launch_bounds__(256) void k_gemm_out(const float* __restrict__ Wout, float* __restrict__ out) {
    __shared__ float As[2][8][128];
    __shared__ float Bs[2][8][128];
    const int tid = threadIdx.x;
    const int t0 = blockIdx.x * 128;
    const int m0 = blockIdx.y * 128;
    const int bb = t0 >> 11;
    const int l0 = t0 & (L_SEQ - 1);
    const int dof = tid >> 5;
    const int t4 = (tid & 31) * 4;
    const int mr = tid >> 1, mc = (tid & 1) * 4;
    const int tx = tid & 15, ty = tid >> 4;
    const float* accF = g_acc[0] + (size_t)bb * D_INNER * L_SEQ;
    const float* accB = g_acc[1] + (size_t)bb * D_INNER * L_SEQ;

    // prologue loads
    float4 va, vb;
    {
        int dd = dof;
        float4 f = *(const float4*)(accF + dd * L_SEQ + l0 + t4);
        float4 r = *(const float4*)(accB + dd * L_SEQ + (L_SEQ - 4 - l0 - t4));
        va.x = 0.5f * (f.x + r.w); va.y = 0.5f * (f.y + r.z);
        va.z = 0.5f * (f.z + r.y); va.w = 0.5f * (f.w + r.x);
        vb = *(const float4*)(Wout + (m0 + mr) * D_INNER + mc);
    }
    *(float4*)&As[0][dof][t4] = va;
    Bs[0][mc + 0][mr] = vb.x; Bs[0][mc + 1][mr] = vb.y; Bs[0][mc + 2][mr] = vb.z; Bs[0][mc + 3][mr] = vb.w;
    __syncthreads();

    float acc[8][8];
#pragma unroll
    for (int i = 0; i < 8; i++)
#pragma unroll
        for (int j = 0; j < 8; j++) acc[i][j] = 0.f;

    int buf = 0;
    const int NK = D_INNER / 8;
    for (int kt = 0; kt < NK; ++kt) {
        if (kt + 1 < NK) {
            int dd = (kt + 1) * 8 + dof;
            float4 f = *(const float4*)(accF + dd * L_SEQ + l0 + t4);
            float4 r = *(const float4*)(accB + dd * L_SEQ + (L_SEQ - 4 - l0 - t4));
            va.x = 0.5f * (f.x + r.w); va.y = 0.5f * (f.y + r.z);
            va.z = 0.5f * (f.z + r.y); va.w = 0.5f * (f.w + r.x);
            vb = *(const float4*)(Wout + (m0 + mr) * D_INNER + (kt + 1) * 8 + mc);
        }
#pragma unroll
        for (int kk = 0; kk < 8; kk++) {
            float4 a0 = *(const float4*)&As[buf][kk][ty * 8];
            float4 a1 = *(const float4*)&As[buf][kk][ty * 8 + 4];
            float4 b0 = *(const float4*)&Bs[buf][kk][tx * 8];
            float4 b1 = *(const float4*)&Bs[buf][kk][tx * 8 + 4];
            float av[8] = {a0.x, a0.y, a0.z, a0.w, a1.x, a1.y, a1.z, a1.w};
            float bv[8] = {b0.x, b0.y, b0.z, b0.w, b1.x, b1.y, b1.z, b1.w};
#pragma unroll
            for (int i = 0; i < 8; i++)
#pragma unroll
                for (int j = 0; j < 8; j++) acc[i][j] = fmaf(av[i], bv[j], acc[i][j]);
        }
        if (kt + 1 < NK) {
            buf ^= 1;
            *(float4*)&As[buf][dof][t4] = va;
            Bs[buf][mc + 0][mr] = vb.x; Bs[buf][mc + 1][mr] = vb.y; Bs[buf][mc + 2][mr] = vb.z; Bs[buf][mc + 3][mr] = vb.w;
            __syncthreads();
        }
    }

#pragma unroll
    for (int i = 0; i < 8; i++) {
        int token = t0 + ty * 8 + i;
        float* cp = out + (size_t)token * D_MODEL + m0 + tx * 8;
        *(float4*)cp = make_float4(acc[i][0], acc[i][1], acc[i][2], acc[i][3]);
        *(float4*)(cp + 4) = make_float4(acc[i][4], acc[i][5], acc[i][6], acc[i][7]);
    }
}

// ---------------- launch ----------------
extern "C" void kernel_launch(void* const* d_in, const int* in_sizes, int n_in,
                              void* d_out, int out_size) {
    const float* hid  = (const float*)d_in[0];
    const float* Win  = (const float*)d_in[1];
    const float* cw   = (const float*)d_in[2];
    const float* cb   = (const float*)d_in[3];
    const float* cwb  = (const float*)d_in[4];
    const float* cbb  = (const float*)d_in[5];
    const float* Wx   = (const float*)d_in[6];
    const float* Wxb  = (const float*)d_in[7];
    const float* Wdt  = (const float*)d_in[8];
    const float* bdt  = (const float*)d_in[9];
    const float* Wdtb = (const float*)d_in[10];
    const float* bdtb = (const float*)d_in[11];
    const float* Alog = (const float*)d_in[12];
    const float* Alogb= (const float*)d_in[13];
    const float* Dp   = (const float*)d_in[14];
    const float* Dpb  = (const float*)d_in[15];
    const float* Wout = (const float*)d_in[16];
    float* out = (float*)d_out;

    k_gemm_xz<<<dim3(E2 / 128, NTOK / 128), 256>>>(hid, Win);
    k_conv<<<dim3(L_SEQ / 256, D_INNER, BSZ), 256>>>(cw, cb, cwb, cbb);
    k_xdbl<<<dim3(L_SEQ / 128, BSZ, 2), 256>>>(Wx, Wxb);
    k_dt<<<dim3(D_INNER / 128, L_SEQ / 64, 4), 256>>>(Wdt, bdt, Wdtb, bdtb);
    k_scan1<<<dim3(D_INNER / 128, NCH, 4), 128>>>(Alog, Alogb);
    k_scan2<<<(2 * BSZ * D_INNER * DS + 255) / 256, 256>>>();
    k_scan3<<<dim3(D_INNER / 128, NCH, 4), 128>>>(Alog, Alogb, Dp, Dpb);
    k_gemm_out<<<dim3(NTOK / 128, D_MODEL / 128), 256>>>(Wout, out);
}

// round 2
// speedup vs baseline: 1.3169x; 1.3169x over previous
#include <cuda_runtime.h>
#include <cuda_bf16.h>
#include <math.h>
#include <stdint.h>

#define L_SEQ 2048
#define D_MODEL 768
#define D_INNER 1536
#define E2 3072
#define DS 16
#define DR 48
#define XD 80
#define BSZ 2
#define NCH 16
#define CHL 128
#define NTOK 4096

// ---------------- scratch ----------------
__device__ float g_xz[BSZ * E2 * L_SEQ];              // [b][e][l]
__device__ float g_xc[2][BSZ * D_INNER * L_SEQ];      // conv+silu x (br1 time-reversed)
__device__ float g_xdbl[2][BSZ * XD * L_SEQ];
__device__ float g_dt[2][BSZ * D_INNER * L_SEQ];
__device__ float g_hfin[2 * BSZ * D_INNER * NCH * DS];
__device__ float g_P[2 * BSZ * D_INNER * NCH * DS];
__device__ float g_Hinit[2 * BSZ * D_INNER * NCH * DS];
__device__ float g_acc[2][BSZ * D_INNER * L_SEQ];

// bf16 hi/lo packed operands (hi in low 16 bits, lo in high 16 bits)
__device__ uint32_t g_WinP[E2 * D_MODEL];
__device__ uint32_t g_hidP[NTOK * D_MODEL];
__device__ uint32_t g_WoutP[D_MODEL * D_INNER];
__device__ uint32_t g_midP[NTOK * D_INNER];

__device__ __forceinline__ float siluf(float v) {
    return v * (1.f / (1.f + __expf(-v)));
}
__device__ __forceinline__ float softplusf(float v) {
    return v > 15.f ? v : log1pf(__expf(v));
}
__device__ __forceinline__ uint32_t pack2f(float x) {
    __nv_bfloat16 h = __float2bfloat16(x);
    float hf = __bfloat162float(h);
    __nv_bfloat16 l = __float2bfloat16(x - hf);
    return (uint32_t)__bfloat16_as_ushort(h) | ((uint32_t)__bfloat16_as_ushort(l) << 16);
}

// ---------------- pack float -> (bf16 hi, bf16 lo) ----------------
__global__ __launch_bounds__(256) void k_pack4(const float4* __restrict__ s, uint4* __restrict__ d, int n4) {
    int i = blockIdx.x * blockDim.x + threadIdx.x;
    if (i < n4) {
        float4 v = s[i];
        uint4 o;
        o.x = pack2f(v.x); o.y = pack2f(v.y); o.z = pack2f(v.z); o.w = pack2f(v.w);
        d[i] = o;
    }
}

// ---------------- mid transpose + combine + pack: mid[token][d] ----------------
__global__ __launch_bounds__(256) void k_midT() {
    __shared__ float t[32][33];
    int b = blockIdx.z;
    int l0 = blockIdx.x * 32, d0 = blockIdx.y * 32;
    int tx = threadIdx.x, ty = threadIdx.y;
    const float* F = g_acc[0] + (size_t)b * D_INNER * L_SEQ;
    const float* Bk = g_acc[1] + (size_t)b * D_INNER * L_SEQ;
#pragma unroll
    for (int i = 0; i < 4; i++) {
        int d = d0 + ty + i * 8;
        float f = F[(size_t)d * L_SEQ + l0 + tx];
        float r = Bk[(size_t)d * L_SEQ + (L_SEQ - 1) - (l0 + tx)];
        t[ty + i * 8][tx] = 0.5f * (f + r);
    }
    __syncthreads();
#pragma unroll
    for (int i = 0; i < 4; i++) {
        int l = l0 + ty + i * 8;
        g_midP[((size_t)(b * L_SEQ) + l) * D_INNER + d0 + tx] = pack2f(t[tx][ty + i * 8]);
    }
}

// ---------------- tensor-core GEMM: C[m,n] = sum_k A[m,k]*B[n,k] ----------------
// A, B: packed hi/lo bf16 (uint32 per element). 3-pass split: hi*hi + hi*lo + lo*hi.
// MODE 0: C -> g_xz layout  (m = e row, n = token; store at (bb*E2+e)*L + l)
// MODE 1: C -> out[token*768 + m_col]  (m = token row, n = model col)

#define LDSM4(R, addr) \
    asm volatile("ldmatrix.sync.aligned.m8n8.x4.shared.b16 {%0,%1,%2,%3},[%4];" \
                 : "=r"(R[0]), "=r"(R[1]), "=r"(R[2]), "=r"(R[3]) : "r"(addr))

#define MMA16816(c, a, b0_, b1_) \
    asm volatile("mma.sync.aligned.m16n8k16.row.col.f32.bf16.bf16.f32 " \
                 "{%0,%1,%2,%3},{%4,%5,%6,%7},{%8,%9},{%0,%1,%2,%3};" \
                 : "+f"(c[0]), "+f"(c[1]), "+f"(c[2]), "+f"(c[3]) \
                 : "r"(a[0]), "r"(a[1]), "r"(a[2]), "r"(a[3]), "r"(b0_), "r"(b1_))

#define PK_HI(u, v) __byte_perm(u, v, 0x5410)
#define PK_LO(u, v) __byte_perm(u, v, 0x7632)

template <int MODE>
__global__ __launch_bounds__(256, 1) void k_mma(const uint32_t* __restrict__ Ag,
                                                const uint32_t* __restrict__ Bg,
                                                float* __restrict__ Cg, int K) {
    __shared__ __align__(16) uint16_t Ash[2][2][128][24];  // [buf][hi/lo][row][k(16)+pad8]
    __shared__ __align__(16) uint16_t Bsh[2][2][128][24];

    const int tid = threadIdx.x;
    const int lane = tid & 31, wid = tid >> 5;
    const int wm = wid >> 2, wn = wid & 3;  // warp grid 2 x 4 -> warp tile 64 x 32
    const int m0 = blockIdx.y * 128, n0 = blockIdx.x * 128;
    const int r0 = tid >> 2, kq = (tid & 3) * 4;  // staging: row, k-offset (u32 elems)

    const uint32_t* Ap = Ag + (size_t)(m0 + r0) * K + kq;
    const uint32_t* Bp = Bg + (size_t)(n0 + r0) * K + kq;
    const size_t rstep = (size_t)64 * K;

    float acc[4][4][4];
#pragma unroll
    for (int i = 0; i < 4; i++)
#pragma unroll
        for (int j = 0; j < 4; j++)
#pragma unroll
            for (int q = 0; q < 4; q++) acc[i][j][q] = 0.f;

    uint4 ra0, ra1, rb0, rb1;
    const int NK = K >> 4;

    // prologue
    ra0 = *(const uint4*)(Ap);
    ra1 = *(const uint4*)(Ap + rstep);
    rb0 = *(const uint4*)(Bp);
    rb1 = *(const uint4*)(Bp + rstep);
    {
        *(uint2*)&Ash[0][0][r0][kq]      = make_uint2(PK_HI(ra0.x, ra0.y), PK_HI(ra0.z, ra0.w));
        *(uint2*)&Ash[0][1][r0][kq]      = make_uint2(PK_LO(ra0.x, ra0.y), PK_LO(ra0.z, ra0.w));
        *(uint2*)&Ash[0][0][r0 + 64][kq] = make_uint2(PK_HI(ra1.x, ra1.y), PK_HI(ra1.z, ra1.w));
        *(uint2*)&Ash[0][1][r0 + 64][kq] = make_uint2(PK_LO(ra1.x, ra1.y), PK_LO(ra1.z, ra1.w));
        *(uint2*)&Bsh[0][0][r0][kq]      = make_uint2(PK_HI(rb0.x, rb0.y), PK_HI(rb0.z, rb0.w));
        *(uint2*)&Bsh[0][1][r0][kq]      = make_uint2(PK_LO(rb0.x, rb0.y), PK_LO(rb0.z, rb0.w));
        *(uint2*)&Bsh[0][0][r0 + 64][kq] = make_uint2(PK_HI(rb1.x, rb1.y), PK_HI(rb1.z, rb1.w));
        *(uint2*)&Bsh[0][1][r0 + 64][kq] = make_uint2(PK_LO(rb1.x, rb1.y), PK_LO(rb1.z, rb1.w));
    }
    __syncthreads();

    const int lr = lane & 15, lc = lane >> 4;
    const int brow = wn * 32 + (lane & 7) + ((lane >> 3) & 1) * 8;

    for (int kt = 0; kt < NK; ++kt) {
        const int buf = kt & 1;
        if (kt + 1 < NK) {
            ra0 = *(const uint4*)(Ap + (kt + 1) * 16);
            ra1 = *(const uint4*)(Ap + rstep + (kt + 1) * 16);
            rb0 = *(const uint4*)(Bp + (kt + 1) * 16);
            rb1 = *(const uint4*)(Bp + rstep + (kt + 1) * 16);
        }

        // ---- compute from buf ----
        uint32_t ah[4][4], al[4][4], bh[2][4], bl[2][4];
        {
            uint32_t aH = (uint32_t)__cvta_generic_to_shared(&Ash[buf][0][wm * 64 + lr][0]) + lc * 16;
            uint32_t aL = (uint32_t)__cvta_generic_to_shared(&Ash[buf][1][wm * 64 + lr][0]) + lc * 16;
#pragma unroll
            for (int mt = 0; mt < 4; mt++) {
                LDSM4(ah[mt], aH + mt * 16 * 48);
                LDSM4(al[mt], aL + mt * 16 * 48);
            }
            uint32_t bH = (uint32_t)__cvta_generic_to_shared(&Bsh[buf][0][brow][0]) + lc * 16;
            uint32_t bL = (uint32_t)__cvta_generic_to_shared(&Bsh[buf][1][brow][0]) + lc * 16;
#pragma unroll
            for (int np = 0; np < 2; np++) {
                LDSM4(bh[np], bH + np * 16 * 48);
                LDSM4(bl[np], bL + np * 16 * 48);
            }
        }
#pragma unroll
        for (int mt = 0; mt < 4; mt++) {
#pragma unroll
            for (int nt = 0; nt < 4; nt++) {
                const int np = nt >> 1, sel = nt & 1;
                MMA16816(acc[mt][nt], ah[mt], bh[np][sel], bh[np][sel + 2]);
                MMA16816(acc[mt][nt], ah[mt], bl[np][sel], bl[np][sel + 2]);
                MMA16816(acc[mt][nt], al[mt], bh[np][sel], bh[np][sel + 2]);
            }
        }

        if (kt + 1 < NK) {
            const int nb = buf ^ 1;
            *(uint2*)&Ash[nb][0][r0][kq]      = make_uint2(PK_HI(ra0.x, ra0.y), PK_HI(ra0.z, ra0.w));
            *(uint2*)&Ash[nb][1][r0][kq]      = make_uint2(PK_LO(ra0.x, ra0.y), PK_LO(ra0.z, ra0.w));
            *(uint2*)&Ash[nb][0][r0 + 64][kq] = make_uint2(PK_HI(ra1.x, ra1.y), PK_HI(ra1.z, ra1.w));
            *(uint2*)&Ash[nb][1][r0 + 64][kq] = make_uint2(PK_LO(ra1.x, ra1.y), PK_LO(ra1.z, ra1.w));
            *(uint2*)&Bsh[nb][0][r0][kq]      = make_uint2(PK_HI(rb0.x, rb0.y), PK_HI(rb0.z, rb0.w));
            *(uint2*)&Bsh[nb][1][r0][kq]      = make_uint2(PK_LO(rb0.x, rb0.y), PK_LO(rb0.z, rb0.w));
            *(uint2*)&Bsh[nb][0][r0 + 64][kq] = make_uint2(PK_HI(rb1.x, rb1.y), PK_HI(rb1.z, rb1.w));
            *(uint2*)&Bsh[nb][1][r0 + 64][kq] = make_uint2(PK_LO(rb1.x, rb1.y), PK_LO(rb1.z, rb1.w));
            __syncthreads();
        }
    }

    // ---- epilogue ----
    float* Cbase;
    int ldc;
    if (MODE == 0) {
        const int bb = n0 >> 11;
        const int l0c = n0 & (L_SEQ - 1);
        Cbase = Cg + ((size_t)bb * E2 + m0) * L_SEQ + l0c;
        ldc = L_SEQ;
    } else {
        Cbase = Cg + (size_t)m0 * D_MODEL + n0;
        ldc = D_MODEL;
    }
#pragma unroll
    for (int mt = 0; mt < 4; mt++) {
        int row = wm * 64 + mt * 16 + (lane >> 2);
#pragma unroll
        for (int nt = 0; nt < 4; nt++) {
            int col = wn * 32 + nt * 8 + (lane & 3) * 2;
            float2 v0 = make_float2(acc[mt][nt][0], acc[mt][nt][1]);
            float2 v1 = make_float2(acc[mt][nt][2], acc[mt][nt][3]);
            *(float2*)(Cbase + (size_t)row * ldc + col) = v0;
            *(float2*)(Cbase + (size_t)(row + 8) * ldc + col) = v1;
        }
    }
}

// ---------------- depthwise causal conv (fwd) + anticausal (bwd, stored reversed) + SiLU --------
__global__ __launch_bounds__(256) void k_conv(const float* __restrict__ cw, const float* __restrict__ cb,
                                              const float* __restrict__ cwb, const float* __restrict__ cbb) {
    const int tid = threadIdx.x;
    const int l0 = blockIdx.x * 256;
    const int d = blockIdx.y;
    const int b = blockIdx.z;
    __shared__ float xs[262];
    const float* xp = g_xz + (b * E2 + d) * L_SEQ;
    for (int i = tid; i < 262; i += 256) {
        int l = l0 - 3 + i;
        xs[i] = (l >= 0 && l < L_SEQ) ? xp[l] : 0.f;
    }
    __syncthreads();
    float wf0 = cw[d * 4 + 0], wf1 = cw[d * 4 + 1], wf2 = cw[d * 4 + 2], wf3 = cw[d * 4 + 3];
    float wb0 = cwb[d * 4 + 0], wb1 = cwb[d * 4 + 1], wb2 = cwb[d * 4 + 2], wb3 = cwb[d * 4 + 3];
    float bf = cb[d], bback = cbb[d];
    int l = l0 + tid;
    float sf = bf + wf0 * xs[tid] + wf1 * xs[tid + 1] + wf2 * xs[tid + 2] + wf3 * xs[tid + 3];
    float sb = bback + wb0 * xs[tid + 6] + wb1 * xs[tid + 5] + wb2 * xs[tid + 4] + wb3 * xs[tid + 3];
    g_xc[0][(b * D_INNER + d) * L_SEQ + l] = siluf(sf);
    g_xc[1][(b * D_INNER + d) * L_SEQ + (L_SEQ - 1 - l)] = siluf(sb);
}

// ---------------- x_dbl ----------------
__global__ __launch_bounds__(256) void k_xdbl(const float* __restrict__ Wx, const float* __restrict__ Wxb) {
    __shared__ float As[16][80];
    __shared__ float Bs[16][128];
    const int tid = threadIdx.x;
    const int l0 = blockIdx.x * 128;
    const int b = blockIdx.y;
    const int br = blockIdx.z;
    const float* W = br ? Wxb : Wx;
    const float* xc = g_xc[br];
    const int tx = tid & 15, ty = tid >> 4;

    float acc[5][8];
#pragma unroll
    for (int i = 0; i < 5; i++)
#pragma unroll
        for (int j = 0; j < 8; j++) acc[i][j] = 0.f;

    for (int kt = 0; kt < D_INNER / 16; ++kt) {
        __syncthreads();
        for (int lin = tid; lin < 1280; lin += 256) {
            int k = lin >> 4, i = lin & 15;
            As[i][k] = W[k * D_INNER + kt * 16 + i];
        }
        for (int lin = tid; lin < 2048; lin += 256) {
            int r = lin >> 7, c = lin & 127;
            Bs[r][c] = xc[(b * D_INNER + kt * 16 + r) * L_SEQ + l0 + c];
        }
        __syncthreads();
#pragma unroll
        for (int kk = 0; kk < 16; kk++) {
            float av[5], bv[8];
#pragma unroll
            for (int i = 0; i < 5; i++) av[i] = As[kk][ty * 5 + i];
            float4 b0 = *(const float4*)&Bs[kk][tx * 8];
            float4 b1 = *(const float4*)&Bs[kk][tx * 8 + 4];
            bv[0] = b0.x; bv[1] = b0.y; bv[2] = b0.z; bv[3] = b0.w;
            bv[4] = b1.x; bv[5] = b1.y; bv[6] = b1.z; bv[7] = b1.w;
#pragma unroll
            for (int i = 0; i < 5; i++)
#pragma unroll
                for (int j = 0; j < 8; j++) acc[i][j] = fmaf(av[i], bv[j], acc[i][j]);
        }
    }
#pragma unroll
    for (int i = 0; i < 5; i++) {
        float* op = g_xdbl[br] + (b * XD + ty * 5 + i) * L_SEQ + l0 + tx * 8;
        *(float4*)op = make_float4(acc[i][0], acc[i][1], acc[i][2], acc[i][3]);
        *(float4*)(op + 4) = make_float4(acc[i][4], acc[i][5], acc[i][6], acc[i][7]);
    }
}

// ---------------- dt projection + softplus ----------------
__global__ __launch_bounds__(256) void k_dt(const float* __restrict__ Wdt, const float* __restrict__ bdt,
                                            const float* __restrict__ Wdtb, const float* __restrict__ bdtb) {
    __shared__ float As[48][128];
    __shared__ float Bs[48][64];
    const int tid = threadIdx.x;
    const int d0 = blockIdx.x * 128;
    const int l0 = blockIdx.y * 64;
    const int zb = blockIdx.z;
    const int br = zb >> 1, b = zb & 1;
    const float* W = br ? Wdtb : Wdt;
    const float* bias = br ? bdtb : bdt;
    const float* xd = g_xdbl[br];

    for (int lin = tid * 4; lin < 6144; lin += 1024) {
        int row = lin / 48, c = lin % 48;
        float4 v = *(const float4*)(W + (d0 + row) * DR + c);
        As[c + 0][row] = v.x; As[c + 1][row] = v.y; As[c + 2][row] = v.z; As[c + 3][row] = v.w;
    }
    for (int lin = tid * 4; lin < 3072; lin += 1024) {
        int r = lin >> 6, c = lin & 63;
        *(float4*)&Bs[r][c] = *(const float4*)(xd + (b * XD + r) * L_SEQ + l0 + c);
    }
    __syncthreads();

    const int tx = tid & 15, ty = tid >> 4;
    float acc[8][4];
#pragma unroll
    for (int i = 0; i < 8; i++)
#pragma unroll
        for (int j = 0; j < 4; j++) acc[i][j] = 0.f;

#pragma unroll 4
    for (int k = 0; k < 48; k++) {
        float4 a0 = *(const float4*)&As[k][ty * 8];
        float4 a1 = *(const float4*)&As[k][ty * 8 + 4];
        float av[8] = {a0.x, a0.y, a0.z, a0.w, a1.x, a1.y, a1.z, a1.w};
        float4 bq = *(const float4*)&Bs[k][tx * 4];
        float bv[4] = {bq.x, bq.y, bq.z, bq.w};
#pragma unroll
        for (int i = 0; i < 8; i++)
#pragma unroll
            for (int j = 0; j < 4; j++) acc[i][j] = fmaf(av[i], bv[j], acc[i][j]);
    }
#pragma unroll
    for (int i = 0; i < 8; i++) {
        int d = d0 + ty * 8 + i;
        float bi = bias[d];
        float4 o;
        o.x = softplusf(acc[i][0] + bi);
        o.y = softplusf(acc[i][1] + bi);
        o.z = softplusf(acc[i][2] + bi);
        o.w = softplusf(acc[i][3] + bi);
        *(float4*)(g_dt[br] + (b * D_INNER + d) * L_SEQ + l0 + tx * 4) = o;
    }
}

// ---------------- scan pass 1 ----------------
__global__ __launch_bounds__(128) void k_scan1(const float* __restrict__ Alog, const float* __restrict__ Alogb) {
    const int tid = threadIdx.x;
    const int d = blockIdx.x * 128 + tid;
    const int chunk = blockIdx.y;
    const int zb = blockIdx.z;
    const int br = zb >> 1, b = zb & 1;
    const float* Al = br ? Alogb : Alog;
    float a[DS];
#pragma unroll
    for (int n = 0; n < DS; n++) a[n] = -expf(Al[d * DS + n]);

    __shared__ float Bsh[CHL][DS + 1];
    const int l0 = chunk * CHL;
    const float* xd = g_xdbl[br] + (b * XD) * L_SEQ;
    for (int i = tid; i < CHL * DS; i += 128) {
        int n = i >> 7, t = i & (CHL - 1);
        Bsh[t][n] = xd[(DR + n) * L_SEQ + l0 + t];
    }
    __syncthreads();

    const float* dtp = g_dt[br] + (b * D_INNER + d) * L_SEQ + l0;
    const float* xp = g_xc[br] + (b * D_INNER + d) * L_SEQ + l0;
    float h[DS], P[DS];
#pragma unroll
    for (int n = 0; n < DS; n++) { h[n] = 0.f; P[n] = 1.f; }

#pragma unroll 2
    for (int t = 0; t < CHL; t++) {
        float dt = dtp[t], x = xp[t];
        float dtx = dt * x;
#pragma unroll
        for (int n = 0; n < DS; n++) {
            float dA = __expf(dt * a[n]);
            h[n] = fmaf(dA, h[n], dtx * Bsh[t][n]);
            P[n] *= dA;
        }
    }
    size_t base = ((size_t)(zb * D_INNER + d) * NCH + chunk) * DS;
#pragma unroll
    for (int n = 0; n < DS; n++) { g_hfin[base + n] = h[n]; g_P[base + n] = P[n]; }
}

// ---------------- scan pass 2 ----------------
__global__ void k_scan2() {
    int id = blockIdx.x * blockDim.x + threadIdx.x;
    if (id >= 2 * BSZ * D_INNER * DS) return;
    int n = id & 15;
    int rest = id >> 4;
    int d = rest % D_INNER;
    int zb = rest / D_INNER;
    size_t base = ((size_t)(zb * D_INNER + d)) * (NCH * DS) + n;
    float H = 0.f;
#pragma unroll
    for (int c = 0; c < NCH; c++) {
        g_Hinit[base + c * DS] = H;
        H = g_P[base + c * DS] * H + g_hfin[base + c * DS];
    }
}

// ---------------- scan pass 3 ----------------
__global__ __launch_bounds__(128) void k_scan3(const float* __restrict__ Alog, const float* __restrict__ Alogb,
                                               const float* __restrict__ Dp, const float* __restrict__ Dpb) {
    const int tid = threadIdx.x;
    const int d = blockIdx.x * 128 + tid;
    const int chunk = blockIdx.y;
    const int zb = blockIdx.z;
    const int br = zb >> 1, b = zb & 1;
    const float* Al = br ? Alogb : Alog;
    float a[DS];
#pragma unroll
    for (int n = 0; n < DS; n++) a[n] = -expf(Al[d * DS + n]);

    __shared__ float Bsh[CHL][DS + 1];
    __shared__ float Csh[CHL][DS + 1];
    const int l0 = chunk * CHL;
    const float* xd = g_xdbl[br] + (b * XD) * L_SEQ;
    for (int i = tid; i < CHL * DS; i += 128) {
        int n = i >> 7, t = i & (CHL - 1);
        Bsh[t][n] = xd[(DR + n) * L_SEQ + l0 + t];
        Csh[t][n] = xd[(DR + DS + n) * L_SEQ + l0 + t];
    }
    __syncthreads();

    size_t sbase = ((size_t)(zb * D_INNER + d) * NCH + chunk) * DS;
    float h[DS];
#pragma unroll
    for (int n = 0; n < DS; n++) h[n] = g_Hinit[sbase + n];
    float Dd = (br ? Dpb : Dp)[d];

    const float* dtp = g_dt[br] + (b * D_INNER + d) * L_SEQ + l0;
    const float* xp = g_xc[br] + (b * D_INNER + d) * L_SEQ + l0;
    const float* zp = g_xz + (b * E2 + D_INNER + d) * L_SEQ;
    float* op = g_acc[br] + (b * D_INNER + d) * L_SEQ + l0;

#pragma unroll 2
    for (int t = 0; t < CHL; t++) {
        float dt = dtp[t], x = xp[t];
        float dtx = dt * x;
        float y = 0.f;
#pragma unroll
        for (int n = 0; n < DS; n++) {
            float dA = __expf(dt * a[n]);
            h[n] = fmaf(dA, h[n], dtx * Bsh[t][n]);
            y = fmaf(h[n], Csh[t][n], y);
        }
        int l = l0 + t;
        float zv = br ? zp[(L_SEQ - 1) - l] : zp[l];
        op[t] = (y + Dd * x) * siluf(zv);
    }
}

// ---------------- launch ----------------
extern "C" void kernel_launch(void* const* d_in, const int* in_sizes, int n_in,
                              void* d_out, int out_size) {
    const float* hid  = (const float*)d_in[0];
    const float* Win  = (const float*)d_in[1];
    const float* cw   = (const float*)d_in[2];
    const float* cb   = (const float*)d_in[3];
    const float* cwb  = (const float*)d_in[4];
    const float* cbb  = (const float*)d_in[5];
    const float* Wx   = (const float*)d_in[6];
    const float* Wxb  = (const float*)d_in[7];
    const float* Wdt  = (const float*)d_in[8];
    const float* bdt  = (const float*)d_in[9];
    const float* Wdtb = (const float*)d_in[10];
    const float* bdtb = (const float*)d_in[11];
    const float* Alog = (const float*)d_in[12];
    const float* Alogb= (const float*)d_in[13];
    const float* Dp   = (const float*)d_in[14];
    const float* Dpb  = (const float*)d_in[15];
    const float* Wout = (const float*)d_in[16];
    float* out = (float*)d_out;

    uint32_t *WinP, *hidP, *WoutP, *midP;
    float *xzP;
    cudaGetSymbolAddress((void**)&WinP, g_WinP);
    cudaGetSymbolAddress((void**)&hidP, g_hidP);
    cudaGetSymbolAddress((void**)&WoutP, g_WoutP);
    cudaGetSymbolAddress((void**)&midP, g_midP);
    cudaGetSymbolAddress((void**)&xzP, g_xz);

    // pack operands to bf16 hi/lo
    k_pack4<<<(E2 * D_MODEL / 4 + 255) / 256, 256>>>((const float4*)Win, (uint4*)WinP, E2 * D_MODEL / 4);
    k_pack4<<<(NTOK * D_MODEL / 4 + 255) / 256, 256>>>((const float4*)hid, (uint4*)hidP, NTOK * D_MODEL / 4);
    k_pack4<<<(D_MODEL * D_INNER / 4 + 255) / 256, 256>>>((const float4*)Wout, (uint4*)WoutP, D_MODEL * D_INNER / 4);

    // xz = Win @ hid^T   (M=3072 rows e, N=4096 tokens, K=768)
    k_mma<0><<<dim3(NTOK / 128, E2 / 128), 256>>>(WinP, hidP, xzP, D_MODEL);

    k_conv<<<dim3(L_SEQ / 256, D_INNER, BSZ), 256>>>(cw, cb, cwb, cbb);
    k_xdbl<<<dim3(L_SEQ / 128, BSZ, 2), 256>>>(Wx, Wxb);
    k_dt<<<dim3(D_INNER / 128, L_SEQ / 64, 4), 256>>>(Wdt, bdt, Wdtb, bdtb);
    k_scan1<<<dim3(D_INNER / 128, NCH, 4), 128>>>(Alog, Alogb);
    k_scan2<<<(2 * BSZ * D_INNER * DS + 255) / 256, 256>>>();
    k_scan3<<<dim3(D_INNER / 128, NCH, 4), 128>>>(Alog, Alogb, Dp, Dpb);

    // combine branches, transpose to [token][d], pack
    k_midT<<<dim3(L_SEQ / 32, D_INNER / 32, BSZ), dim3(32, 8)>>>();

    // out = mid @ Wout^T  (M=4096 tokens, N=768, K=1536)
    k_mma<1><<<dim3(D_MODEL / 128, NTOK / 128), 256>>>(midP, WoutP, out, D_INNER);
}

// round 3
// speedup vs baseline: 1.5440x; 1.1725x over previous
#include <cuda_runtime.h>
#include <cuda_bf16.h>
#include <math.h>
#include <stdint.h>

#define L_SEQ 2048
#define D_MODEL 768
#define D_INNER 1536
#define E2 3072
#define DS 16
#define DR 48
#define XD 80
#define BSZ 2
#define NCH 16
#define CHL 128
#define NTOK 4096

// ---------------- scratch ----------------
__device__ float g_xz[BSZ * E2 * L_SEQ];
__device__ float g_xc[2][BSZ * D_INNER * L_SEQ];
__device__ float g_xdbl[2][BSZ * XD * L_SEQ];
__device__ float g_dt[2][BSZ * D_INNER * L_SEQ];
__device__ float g_hfin[2 * BSZ * D_INNER * NCH * DS];
__device__ float g_P[2 * BSZ * D_INNER * NCH * DS];
__device__ float g_Hinit[2 * BSZ * D_INNER * NCH * DS];
__device__ float g_acc[2][BSZ * D_INNER * L_SEQ];

// bf16 hi/lo planes
__device__ uint16_t g_WinH[E2 * D_MODEL],   g_WinL[E2 * D_MODEL];
__device__ uint16_t g_hidH[NTOK * D_MODEL], g_hidL[NTOK * D_MODEL];
__device__ uint16_t g_WoutH[D_MODEL * D_INNER], g_WoutL[D_MODEL * D_INNER];
__device__ uint16_t g_midH[NTOK * D_INNER], g_midL[NTOK * D_INNER];

__device__ __forceinline__ float siluf(float v) {
    return v * (1.f / (1.f + __expf(-v)));
}
__device__ __forceinline__ float softplusf(float v) {
    return v > 15.f ? v : log1pf(__expf(v));
}
__device__ __forceinline__ void split2(float x, uint16_t& h, uint16_t& l) {
    __nv_bfloat16 hb = __float2bfloat16(x);
    h = __bfloat16_as_ushort(hb);
    l = __bfloat16_as_ushort(__float2bfloat16(x - __bfloat162float(hb)));
}

// ---------------- pack float -> separate hi/lo bf16 planes ----------------
__global__ __launch_bounds__(256) void k_packsplit(const float4* __restrict__ s,
                                                   ushort4* __restrict__ hi,
                                                   ushort4* __restrict__ lo, int n4) {
    int i = blockIdx.x * blockDim.x + threadIdx.x;
    if (i < n4) {
        float4 v = s[i];
        ushort4 h, l;
        split2(v.x, h.x, l.x); split2(v.y, h.y, l.y);
        split2(v.z, h.z, l.z); split2(v.w, h.w, l.w);
        hi[i] = h; lo[i] = l;
    }
}

// ---------------- mid transpose + combine + pack ----------------
__global__ __launch_bounds__(256) void k_midT() {
    __shared__ float t[32][33];
    int b = blockIdx.z;
    int l0 = blockIdx.x * 32, d0 = blockIdx.y * 32;
    int tx = threadIdx.x, ty = threadIdx.y;
    const float* F = g_acc[0] + (size_t)b * D_INNER * L_SEQ;
    const float* Bk = g_acc[1] + (size_t)b * D_INNER * L_SEQ;
#pragma unroll
    for (int i = 0; i < 4; i++) {
        int d = d0 + ty + i * 8;
        float f = F[(size_t)d * L_SEQ + l0 + tx];
        float r = Bk[(size_t)d * L_SEQ + (L_SEQ - 1) - (l0 + tx)];
        t[ty + i * 8][tx] = 0.5f * (f + r);
    }
    __syncthreads();
#pragma unroll
    for (int i = 0; i < 4; i++) {
        int l = l0 + ty + i * 8;
        uint16_t h, lw;
        split2(t[tx][ty + i * 8], h, lw);
        size_t idx = ((size_t)(b * L_SEQ) + l) * D_INNER + d0 + tx;
        g_midH[idx] = h; g_midL[idx] = lw;
    }
}

// ---------------- tensor-core GEMM, cp.async pipelined ----------------
#define LDSM4(R, addr) \
    asm volatile("ldmatrix.sync.aligned.m8n8.x4.shared.b16 {%0,%1,%2,%3},[%4];" \
                 : "=r"(R[0]), "=r"(R[1]), "=r"(R[2]), "=r"(R[3]) : "r"(addr))

#define MMA16816(c, a, b0_, b1_) \
    asm volatile("mma.sync.aligned.m16n8k16.row.col.f32.bf16.bf16.f32 " \
                 "{%0,%1,%2,%3},{%4,%5,%6,%7},{%8,%9},{%0,%1,%2,%3};" \
                 : "+f"(c[0]), "+f"(c[1]), "+f"(c[2]), "+f"(c[3]) \
                 : "r"(a[0]), "r"(a[1]), "r"(a[2]), "r"(a[3]), "r"(b0_), "r"(b1_))

#define CPASYNC16(smem_u32, gptr) \
    asm volatile("cp.async.ca.shared.global [%0], [%1], 16;" :: "r"(smem_u32), "l"(gptr))

// CTA tile 128(m) x 64(n); warps 4x2, warp tile 32x32.
// MODE 0: C[(bb*E2+m)*L + l]   MODE 1: C[m*768 + n]
template <int MODE>
__global__ __launch_bounds__(256, 2) void k_mma(const uint16_t* __restrict__ AgH,
                                                const uint16_t* __restrict__ AgL,
                                                const uint16_t* __restrict__ BgH,
                                                const uint16_t* __restrict__ BgL,
                                                float* __restrict__ Cg, int K) {
    __shared__ __align__(16) uint16_t Ash[2][2][128][24];
    __shared__ __align__(16) uint16_t Bsh[2][2][64][24];

    const int tid = threadIdx.x;
    const int lane = tid & 31, wid = tid >> 5;
    const int wm = wid >> 1, wn = wid & 1;   // 4 x 2 warps
    const int m0 = blockIdx.y * 128, n0 = blockIdx.x * 64;

    // staging roles
    const int arow = tid >> 1, ahalf = tid & 1;           // A: 128 rows x 2 halves
    const int brow_ = (tid & 127) >> 1, bhalf = tid & 1;  // B: 64 rows x 2 halves
    const int bplane = tid >> 7;

    const uint16_t* ApH = AgH + (size_t)(m0 + arow) * K + ahalf * 8;
    const uint16_t* ApL = AgL + (size_t)(m0 + arow) * K + ahalf * 8;
    const uint16_t* Bp = (bplane ? BgL : BgH) + (size_t)(n0 + brow_) * K + bhalf * 8;

    const int NK = K >> 4;

    float acc[2][4][4];
#pragma unroll
    for (int i = 0; i < 2; i++)
#pragma unroll
        for (int j = 0; j < 4; j++)
#pragma unroll
            for (int q = 0; q < 4; q++) acc[i][j][q] = 0.f;

    uint32_t sA0 = (uint32_t)__cvta_generic_to_shared(&Ash[0][0][arow][ahalf * 8]);
    uint32_t sA1 = (uint32_t)__cvta_generic_to_shared(&Ash[0][1][arow][ahalf * 8]);
    uint32_t sB  = (uint32_t)__cvta_generic_to_shared(&Bsh[0][bplane][brow_][bhalf * 8]);
    const uint32_t stgA = sizeof(uint16_t) * 2 * 128 * 24;  // stage stride for Ash
    const uint32_t stgB = sizeof(uint16_t) * 2 * 64 * 24;

    // prologue: stage 0
    CPASYNC16(sA0, ApH);
    CPASYNC16(sA1, ApL);
    CPASYNC16(sB, Bp);
    asm volatile("cp.async.commit_group;");

    const int lr = lane & 15, lc = lane >> 4;
    const int brow = (lane & 7) + ((lane >> 3) & 1) * 8;

    for (int kt = 0; kt < NK; ++kt) {
        const int buf = kt & 1;
        if (kt + 1 < NK) {
            const int nb = (kt + 1) & 1;
            CPASYNC16(sA0 + nb * stgA, ApH + (kt + 1) * 16);
            CPASYNC16(sA1 + nb * stgA, ApL + (kt + 1) * 16);
            CPASYNC16(sB + nb * stgB, Bp + (kt + 1) * 16);
            asm volatile("cp.async.commit_group;");
            asm volatile("cp.async.wait_group 1;");
        } else {
            asm volatile("cp.async.wait_group 0;");
        }
        __syncthreads();

        // fragments
        uint32_t ah[2][4], al[2][4], bh[2][4], bl[2][4];
        {
            uint32_t aH = (uint32_t)__cvta_generic_to_shared(&Ash[buf][0][wm * 32 + lr][0]) + lc * 16;
            uint32_t aL = (uint32_t)__cvta_generic_to_shared(&Ash[buf][1][wm * 32 + lr][0]) + lc * 16;
#pragma unroll
            for (int mt = 0; mt < 2; mt++) {
                LDSM4(ah[mt], aH + mt * 16 * 48);
                LDSM4(al[mt], aL + mt * 16 * 48);
            }
            uint32_t bH = (uint32_t)__cvta_generic_to_shared(&Bsh[buf][0][wn * 32 + brow][0]) + lc * 16;
            uint32_t bL = (uint32_t)__cvta_generic_to_shared(&Bsh[buf][1][wn * 32 + brow][0]) + lc * 16;
#pragma unroll
            for (int np = 0; np < 2; np++) {
                LDSM4(bh[np], bH + np * 16 * 48);
                LDSM4(bl[np], bL + np * 16 * 48);
            }
        }
#pragma unroll
        for (int mt = 0; mt < 2; mt++) {
#pragma unroll
            for (int nt = 0; nt < 4; nt++) {
                const int np = nt >> 1, sel = nt & 1;
                MMA16816(acc[mt][nt], ah[mt], bh[np][sel], bh[np][sel + 2]);
                MMA16816(acc[mt][nt], ah[mt], bl[np][sel], bl[np][sel + 2]);
                MMA16816(acc[mt][nt], al[mt], bh[np][sel], bh[np][sel + 2]);
            }
        }
        __syncthreads();
    }

    // epilogue
    float* Cbase;
    int ldc;
    if (MODE == 0) {
        const int bb = n0 >> 11;
        const int l0c = n0 & (L_SEQ - 1);
        Cbase = Cg + ((size_t)bb * E2 + m0) * L_SEQ + l0c;
        ldc = L_SEQ;
    } else {
        Cbase = Cg + (size_t)m0 * D_MODEL + n0;
        ldc = D_MODEL;
    }
#pragma unroll
    for (int mt = 0; mt < 2; mt++) {
        int row = wm * 32 + mt * 16 + (lane >> 2);
#pragma unroll
        for (int nt = 0; nt < 4; nt++) {
            int col = wn * 32 + nt * 8 + (lane & 3) * 2;
            *(float2*)(Cbase + (size_t)row * ldc + col) = make_float2(acc[mt][nt][0], acc[mt][nt][1]);
            *(float2*)(Cbase + (size_t)(row + 8) * ldc + col) = make_float2(acc[mt][nt][2], acc[mt][nt][3]);
        }
    }
}

// ---------------- depthwise conv + SiLU ----------------
__global__ __launch_bounds__(256) void k_conv(const float* __restrict__ cw, const float* __restrict__ cb,
                                              const float* __restrict__ cwb, const float* __restrict__ cbb) {
    const int tid = threadIdx.x;
    const int l0 = blockIdx.x * 256;
    const int d = blockIdx.y;
    const int b = blockIdx.z;
    __shared__ float xs[262];
    const float* xp = g_xz + (b * E2 + d) * L_SEQ;
    for (int i = tid; i < 262; i += 256) {
        int l = l0 - 3 + i;
        xs[i] = (l >= 0 && l < L_SEQ) ? xp[l] : 0.f;
    }
    __syncthreads();
    float wf0 = cw[d * 4 + 0], wf1 = cw[d * 4 + 1], wf2 = cw[d * 4 + 2], wf3 = cw[d * 4 + 3];
    float wb0 = cwb[d * 4 + 0], wb1 = cwb[d * 4 + 1], wb2 = cwb[d * 4 + 2], wb3 = cwb[d * 4 + 3];
    float bf = cb[d], bback = cbb[d];
    int l = l0 + tid;
    float sf = bf + wf0 * xs[tid] + wf1 * xs[tid + 1] + wf2 * xs[tid + 2] + wf3 * xs[tid + 3];
    float sb = bback + wb0 * xs[tid + 6] + wb1 * xs[tid + 5] + wb2 * xs[tid + 4] + wb3 * xs[tid + 3];
    g_xc[0][(b * D_INNER + d) * L_SEQ + l] = siluf(sf);
    g_xc[1][(b * D_INNER + d) * L_SEQ + (L_SEQ - 1 - l)] = siluf(sb);
}

// ---------------- zero g_xdbl ----------------
__global__ __launch_bounds__(256) void k_zero(float4* p, int n4) {
    int i = blockIdx.x * blockDim.x + threadIdx.x;
    if (i < n4) p[i] = make_float4(0.f, 0.f, 0.f, 0.f);
}

// ---------------- x_dbl, split-K x4 with atomics ----------------
__global__ __launch_bounds__(256) void k_xdbl(const float* __restrict__ Wx, const float* __restrict__ Wxb) {
    __shared__ float As[16][80];
    __shared__ float Bs[16][128];
    const int tid = threadIdx.x;
    const int l0 = blockIdx.x * 128;
    const int b = blockIdx.y;
    const int br = blockIdx.z >> 2;
    const int ks = blockIdx.z & 3;
    const float* W = br ? Wxb : Wx;
    const float* xc = g_xc[br];
    const int tx = tid & 15, ty = tid >> 4;
    const int k0 = ks * (D_INNER / 4);

    float acc[5][8];
#pragma unroll
    for (int i = 0; i < 5; i++)
#pragma unroll
        for (int j = 0; j < 8; j++) acc[i][j] = 0.f;

    for (int kt = 0; kt < D_INNER / 64; ++kt) {
        __syncthreads();
        for (int lin = tid; lin < 1280; lin += 256) {
            int k = lin >> 4, i = lin & 15;
            As[i][k] = W[k * D_INNER + k0 + kt * 16 + i];
        }
        for (int lin = tid; lin < 2048; lin += 256) {
            int r = lin >> 7, c = lin & 127;
            Bs[r][c] = xc[(b * D_INNER + k0 + kt * 16 + r) * L_SEQ + l0 + c];
        }
        __syncthreads();
#pragma unroll
        for (int kk = 0; kk < 16; kk++) {
            float av[5], bv[8];
#pragma unroll
            for (int i = 0; i < 5; i++) av[i] = As[kk][ty * 5 + i];
            float4 b0 = *(const float4*)&Bs[kk][tx * 8];
            float4 b1 = *(const float4*)&Bs[kk][tx * 8 + 4];
            bv[0] = b0.x; bv[1] = b0.y; bv[2] = b0.z; bv[3] = b0.w;
            bv[4] = b1.x; bv[5] = b1.y; bv[6] = b1.z; bv[7] = b1.w;
#pragma unroll
            for (int i = 0; i < 5; i++)
#pragma unroll
                for (int j = 0; j < 8; j++) acc[i][j] = fmaf(av[i], bv[j], acc[i][j]);
        }
    }
#pragma unroll
    for (int i = 0; i < 5; i++) {
        float* op = g_xdbl[br] + (b * XD + ty * 5 + i) * L_SEQ + l0 + tx * 8;
#pragma unroll
        for (int j = 0; j < 8; j++) atomicAdd(op + j, acc[i][j]);
    }
}

// ---------------- dt projection + softplus ----------------
__global__ __launch_bounds__(256) void k_dt(const float* __restrict__ Wdt, const float* __restrict__ bdt,
                                            const float* __restrict__ Wdtb, const float* __restrict__ bdtb) {
    __shared__ float As[48][128];
    __shared__ float Bs[48][64];
    const int tid = threadIdx.x;
    const int d0 = blockIdx.x * 128;
    const int l0 = blockIdx.y * 64;
    const int zb = blockIdx.z;
    const int br = zb >> 1, b = zb & 1;
    const float* W = br ? Wdtb : Wdt;
    const float* bias = br ? bdtb : bdt;
    const float* xd = g_xdbl[br];

    for (int lin = tid * 4; lin < 6144; lin += 1024) {
        int row = lin / 48, c = lin % 48;
        float4 v = *(const float4*)(W + (d0 + row) * DR + c);
        As[c + 0][row] = v.x; As[c + 1][row] = v.y; As[c + 2][row] = v.z; As[c + 3][row] = v.w;
    }
    for (int lin = tid * 4; lin < 3072; lin += 1024) {
        int r = lin >> 6, c = lin & 63;
        *(float4*)&Bs[r][c] = *(const float4*)(xd + (b * XD + r) * L_SEQ + l0 + c);
    }
    __syncthreads();

    const int tx = tid & 15, ty = tid >> 4;
    float acc[8][4];
#pragma unroll
    for (int i = 0; i < 8; i++)
#pragma unroll
        for (int j = 0; j < 4; j++) acc[i][j] = 0.f;

#pragma unroll 4
    for (int k = 0; k < 48; k++) {
        float4 a0 = *(const float4*)&As[k][ty * 8];
        float4 a1 = *(const float4*)&As[k][ty * 8 + 4];
        float av[8] = {a0.x, a0.y, a0.z, a0.w, a1.x, a1.y, a1.z, a1.w};
        float4 bq = *(const float4*)&Bs[k][tx * 4];
        float bv[4] = {bq.x, bq.y, bq.z, bq.w};
#pragma unroll
        for (int i = 0; i < 8; i++)
#pragma unroll
            for (int j = 0; j < 4; j++) acc[i][j] = fmaf(av[i], bv[j], acc[i][j]);
    }
#pragma unroll
    for (int i = 0; i < 8; i++) {
        int d = d0 + ty * 8 + i;
        float bi = bias[d];
        float4 o;
        o.x = softplusf(acc[i][0] + bi);
        o.y = softplusf(acc[i][1] + bi);
        o.z = softplusf(acc[i][2] + bi);
        o.w = softplusf(acc[i][3] + bi);
        *(float4*)(g_dt[br] + (b * D_INNER + d) * L_SEQ + l0 + tx * 4) = o;
    }
}

// ---------------- scan pass 1 ----------------
__global__ __launch_bounds__(128) void k_scan1(const float* __restrict__ Alog, const float* __restrict__ Alogb) {
    const int tid = threadIdx.x;
    const int d = blockIdx.x * 128 + tid;
    const int chunk = blockIdx.y;
    const int zb = blockIdx.z;
    const int br = zb >> 1, b = zb & 1;
    const float* Al = br ? Alogb : Alog;
    float a[DS];
#pragma unroll
    for (int n = 0; n < DS; n++) a[n] = -expf(Al[d * DS + n]);

    __shared__ float Bsh[CHL][DS + 1];
    const int l0 = chunk * CHL;
    const float* xd = g_xdbl[br] + (b * XD) * L_SEQ;
    for (int i = tid; i < CHL * DS; i += 128) {
        int n = i >> 7, t = i & (CHL - 1);
        Bsh[t][n] = xd[(DR + n) * L_SEQ + l0 + t];
    }
    __syncthreads();

    const float* dtp = g_dt[br] + (b * D_INNER + d) * L_SEQ + l0;
    const float* xp = g_xc[br] + (b * D_INNER + d) * L_SEQ + l0;
    float h[DS], P[DS];
#pragma unroll
    for (int n = 0; n < DS; n++) { h[n] = 0.f; P[n] = 1.f; }

#pragma unroll 2
    for (int t = 0; t < CHL; t++) {
        float dt = dtp[t], x = xp[t];
        float dtx = dt * x;
#pragma unroll
        for (int n = 0; n < DS; n++) {
            float dA = __expf(dt * a[n]);
            h[n] = fmaf(dA, h[n], dtx * Bsh[t][n]);
            P[n] *= dA;
        }
    }
    size_t base = ((size_t)(zb * D_INNER + d) * NCH + chunk) * DS;
#pragma unroll
    for (int n = 0; n < DS; n++) { g_hfin[base + n] = h[n]; g_P[base + n] = P[n]; }
}

// ---------------- scan pass 2 ----------------
__global__ void k_scan2() {
    int id = blockIdx.x * blockDim.x + threadIdx.x;
    if (id >= 2 * BSZ * D_INNER * DS) return;
    int n = id & 15;
    int rest = id >> 4;
    int d = rest % D_INNER;
    int zb = rest / D_INNER;
    size_t base = ((size_t)(zb * D_INNER + d)) * (NCH * DS) + n;
    float H = 0.f;
#pragma unroll
    for (int c = 0; c < NCH; c++) {
        g_Hinit[base + c * DS] = H;
        H = g_P[base + c * DS] * H + g_hfin[base + c * DS];
    }
}

// ---------------- scan pass 3 ----------------
__global__ __launch_bounds__(128) void k_scan3(const float* __restrict__ Alog, const float* __restrict__ Alogb,
                                               const float* __restrict__ Dp, const float* __restrict__ Dpb) {
    const int tid = threadIdx.x;
    const int d = blockIdx.x * 128 + tid;
    const int chunk = blockIdx.y;
    const int zb = blockIdx.z;
    const int br = zb >> 1, b = zb & 1;
    const float* Al = br ? Alogb : Alog;
    float a[DS];
#pragma unroll
    for (int n = 0; n < DS; n++) a[n] = -expf(Al[d * DS + n]);

    __shared__ float Bsh[CHL][DS + 1];
    __shared__ float Csh[CHL][DS + 1];
    const int l0 = chunk * CHL;
    const float* xd = g_xdbl[br] + (b * XD) * L_SEQ;
    for (int i = tid; i < CHL * DS; i += 128) {
        int n = i >> 7, t = i & (CHL - 1);
        Bsh[t][n] = xd[(DR + n) * L_SEQ + l0 + t];
        Csh[t][n] = xd[(DR + DS + n) * L_SEQ + l0 + t];
    }
    __syncthreads();

    size_t sbase = ((size_t)(zb * D_INNER + d) * NCH + chunk) * DS;
    float h[DS];
#pragma unroll
    for (int n = 0; n < DS; n++) h[n] = g_Hinit[sbase + n];
    float Dd = (br ? Dpb : Dp)[d];

    const float* dtp = g_dt[br] + (b * D_INNER + d) * L_SEQ + l0;
    const float* xp = g_xc[br] + (b * D_INNER + d) * L_SEQ + l0;
    const float* zp = g_xz + (b * E2 + D_INNER + d) * L_SEQ;
    float* op = g_acc[br] + (b * D_INNER + d) * L_SEQ + l0;

#pragma unroll 2
    for (int t = 0; t < CHL; t++) {
        float dt = dtp[t], x = xp[t];
        float dtx = dt * x;
        float y = 0.f;
#pragma unroll
        for (int n = 0; n < DS; n++) {
            float dA = __expf(dt * a[n]);
            h[n] = fmaf(dA, h[n], dtx * Bsh[t][n]);
            y = fmaf(h[n], Csh[t][n], y);
        }
        int l = l0 + t;
        float zv = br ? zp[(L_SEQ - 1) - l] : zp[l];
        op[t] = (y + Dd * x) * siluf(zv);
    }
}

// ---------------- launch ----------------
extern "C" void kernel_launch(void* const* d_in, const int* in_sizes, int n_in,
                              void* d_out, int out_size) {
    const float* hid  = (const float*)d_in[0];
    const float* Win  = (const float*)d_in[1];
    const float* cw   = (const float*)d_in[2];
    const float* cb   = (const float*)d_in[3];
    const float* cwb  = (const float*)d_in[4];
    const float* cbb  = (const float*)d_in[5];
    const float* Wx   = (const float*)d_in[6];
    const float* Wxb  = (const float*)d_in[7];
    const float* Wdt  = (const float*)d_in[8];
    const float* bdt  = (const float*)d_in[9];
    const float* Wdtb = (const float*)d_in[10];
    const float* bdtb = (const float*)d_in[11];
    const float* Alog = (const float*)d_in[12];
    const float* Alogb= (const float*)d_in[13];
    const float* Dp   = (const float*)d_in[14];
    const float* Dpb  = (const float*)d_in[15];
    const float* Wout = (const float*)d_in[16];
    float* out = (float*)d_out;

    uint16_t *WinH, *WinL, *hidH, *hidL, *WoutH, *WoutL, *midH, *midL;
    float *xzP, *xdblP;
    cudaGetSymbolAddress((void**)&WinH, g_WinH);   cudaGetSymbolAddress((void**)&WinL, g_WinL);
    cudaGetSymbolAddress((void**)&hidH, g_hidH);   cudaGetSymbolAddress((void**)&hidL, g_hidL);
    cudaGetSymbolAddress((void**)&WoutH, g_WoutH); cudaGetSymbolAddress((void**)&WoutL, g_WoutL);
    cudaGetSymbolAddress((void**)&midH, g_midH);   cudaGetSymbolAddress((void**)&midL, g_midL);
    cudaGetSymbolAddress((void**)&xzP, g_xz);
    cudaGetSymbolAddress((void**)&xdblP, g_xdbl);

    k_packsplit<<<(E2 * D_MODEL / 4 + 255) / 256, 256>>>((const float4*)Win, (ushort4*)WinH, (ushort4*)WinL, E2 * D_MODEL / 4);
    k_packsplit<<<(NTOK * D_MODEL / 4 + 255) / 256, 256>>>((const float4*)hid, (ushort4*)hidH, (ushort4*)hidL, NTOK * D_MODEL / 4);
    k_packsplit<<<(D_MODEL * D_INNER / 4 + 255) / 256, 256>>>((const float4*)Wout, (ushort4*)WoutH, (ushort4*)WoutL, D_MODEL * D_INNER / 4);

    // xz = Win @ hid^T : M=3072(e), N=4096(tok), K=768
    k_mma<0><<<dim3(NTOK / 64, E2 / 128), 256>>>(WinH, WinL, hidH, hidL, xzP, D_MODEL);

    k_conv<<<dim3(L_SEQ / 256, D_INNER, BSZ), 256>>>(cw, cb, cwb, cbb);

    k_zero<<<(2 * BSZ * XD * L_SEQ / 4 + 255) / 256, 256>>>((float4*)xdblP, 2 * BSZ * XD * L_SEQ / 4);
    k_xdbl<<<dim3(L_SEQ / 128, BSZ, 8), 256>>>(Wx, Wxb);

    k_dt<<<dim3(D_INNER / 128, L_SEQ / 64, 4), 256>>>(Wdt, bdt, Wdtb, bdtb);
    k_scan1<<<dim3(D_INNER / 128, NCH, 4), 128>>>(Alog, Alogb);
    k_scan2<<<(2 * BSZ * D_INNER * DS + 255) / 256, 256>>>();
    k_scan3<<<dim3(D_INNER / 128, NCH, 4), 128>>>(Alog, Alogb, Dp, Dpb);

    k_midT<<<dim3(L_SEQ / 32, D_INNER / 32, BSZ), dim3(32, 8)>>>();

    // out = mid @ Wout^T : M=4096(tok), N=768, K=1536
    k_mma<1><<<dim3(D_MODEL / 64, NTOK / 128), 256>>>(midH, midL, WoutH, WoutL, out, D_INNER);
}

// round 8
// speedup vs baseline: 1.5492x; 1.0033x over previous
#include <cuda_runtime.h>
#include <cuda_bf16.h>
#include <math.h>
#include <stdint.h>

#define L_SEQ 2048
#define D_MODEL 768
#define D_INNER 1536
#define E2 3072
#define DS 16
#define DR 48
#define XD 80
#define BSZ 2
#define NCH 16
#define CHL 128
#define NTOK 4096

// ---------------- scratch ----------------
__device__ float g_xz[BSZ * E2 * L_SEQ];
__device__ float g_xc[2][BSZ * D_INNER * L_SEQ];
__device__ float g_xdbl[2][BSZ * XD * L_SEQ];
__device__ float g_dt[2][BSZ * D_INNER * L_SEQ];
__device__ float g_hfin[2 * BSZ * D_INNER * NCH * DS];
__device__ float g_P[2 * BSZ * D_INNER * NCH * DS];
__device__ float g_Hinit[2 * BSZ * D_INNER * NCH * DS];
__device__ float g_acc[2][BSZ * D_INNER * L_SEQ];

// bf16 hi/lo planes
__device__ uint16_t g_WinH[E2 * D_MODEL],   g_WinL[E2 * D_MODEL];
__device__ uint16_t g_hidH[NTOK * D_MODEL], g_hidL[NTOK * D_MODEL];
__device__ uint16_t g_WoutH[D_MODEL * D_INNER], g_WoutL[D_MODEL * D_INNER];
__device__ uint16_t g_midH[NTOK * D_INNER], g_midL[NTOK * D_INNER];

__device__ __forceinline__ float siluf(float v) {
    return v * (1.f / (1.f + __expf(-v)));
}
__device__ __forceinline__ float softplusf(float v) {
    return v > 15.f ? v : log1pf(__expf(v));
}
__device__ __forceinline__ void split2(float x, uint16_t& h, uint16_t& l) {
    __nv_bfloat16 hb = __float2bfloat16(x);
    h = __bfloat16_as_ushort(hb);
    l = __bfloat16_as_ushort(__float2bfloat16(x - __bfloat162float(hb)));
}

// ---------------- pack float -> separate hi/lo bf16 planes ----------------
__global__ __launch_bounds__(256) void k_packsplit(const float4* __restrict__ s,
                                                   ushort4* __restrict__ hi,
                                                   ushort4* __restrict__ lo, int n4) {
    int i = blockIdx.x * blockDim.x + threadIdx.x;
    if (i < n4) {
        float4 v = s[i];
        ushort4 h, l;
        split2(v.x, h.x, l.x); split2(v.y, h.y, l.y);
        split2(v.z, h.z, l.z); split2(v.w, h.w, l.w);
        hi[i] = h; lo[i] = l;
    }
}

// ---------------- mid transpose + combine + pack ----------------
__global__ __launch_bounds__(256) void k_midT() {
    __shared__ float t[32][33];
    int b = blockIdx.z;
    int l0 = blockIdx.x * 32, d0 = blockIdx.y * 32;
    int tx = threadIdx.x, ty = threadIdx.y;
    const float* F = g_acc[0] + (size_t)b * D_INNER * L_SEQ;
    const float* Bk = g_acc[1] + (size_t)b * D_INNER * L_SEQ;
#pragma unroll
    for (int i = 0; i < 4; i++) {
        int d = d0 + ty + i * 8;
        float f = F[(size_t)d * L_SEQ + l0 + tx];
        float r = Bk[(size_t)d * L_SEQ + (L_SEQ - 1) - (l0 + tx)];
        t[ty + i * 8][tx] = 0.5f * (f + r);
    }
    __syncthreads();
#pragma unroll
    for (int i = 0; i < 4; i++) {
        int l = l0 + ty + i * 8;
        uint16_t h, lw;
        split2(t[tx][ty + i * 8], h, lw);
        size_t idx = ((size_t)(b * L_SEQ) + l) * D_INNER + d0 + tx;
        g_midH[idx] = h; g_midL[idx] = lw;
    }
}

// ---------------- tensor-core GEMM (mma.sync), register-staged double buffer ----------------
#define LDSM4(R, addr) \
    asm volatile("ldmatrix.sync.aligned.m8n8.x4.shared.b16 {%0,%1,%2,%3},[%4];" \
                 : "=r"(R[0]), "=r"(R[1]), "=r"(R[2]), "=r"(R[3]) : "r"(addr))

#define MMA16816(c, a, b0_, b1_) \
    asm volatile("mma.sync.aligned.m16n8k16.row.col.f32.bf16.bf16.f32 " \
                 "{%0,%1,%2,%3},{%4,%5,%6,%7},{%8,%9},{%0,%1,%2,%3};" \
                 : "+f"(c[0]), "+f"(c[1]), "+f"(c[2]), "+f"(c[3]) \
                 : "r"(a[0]), "r"(a[1]), "r"(a[2]), "r"(a[3]), "r"(b0_), "r"(b1_))

// CTA tile 128x128, warps 2x4 (warp tile 64x32). 3-pass hi/lo split.
// MODE 0: C[(bb*E2+m)*L + l]   MODE 1: C[m*768 + n]
template <int MODE>
__global__ __launch_bounds__(256) void k_mma(const uint16_t* __restrict__ AgH,
                                             const uint16_t* __restrict__ AgL,
                                             const uint16_t* __restrict__ BgH,
                                             const uint16_t* __restrict__ BgL,
                                             float* __restrict__ Cg, int K) {
    __shared__ __align__(16) uint16_t Ash[2][2][128][24];  // [buf][hi/lo][row][16+pad8]
    __shared__ __align__(16) uint16_t Bsh[2][2][128][24];

    const int tid = threadIdx.x;
    const int lane = tid & 31, wid = tid >> 5;
    const int wm = wid >> 2, wn = wid & 3;  // 2 x 4 warps
    const int m0 = blockIdx.y * 128, n0 = blockIdx.x * 128;
    const int srow = tid >> 1, sseg = tid & 1;  // 128 rows x 2 16B-segments

    const uint16_t* pAH = AgH + (size_t)(m0 + srow) * K + sseg * 8;
    const uint16_t* pAL = AgL + (size_t)(m0 + srow) * K + sseg * 8;
    const uint16_t* pBH = BgH + (size_t)(n0 + srow) * K + sseg * 8;
    const uint16_t* pBL = BgL + (size_t)(n0 + srow) * K + sseg * 8;

    const int NK = K >> 4;

    float acc[4][4][4];
#pragma unroll
    for (int i = 0; i < 4; i++)
#pragma unroll
        for (int j = 0; j < 4; j++)
#pragma unroll
            for (int q = 0; q < 4; q++) acc[i][j][q] = 0.f;

    uint4 rah, ral, rbh, rbl;
    // prologue: stage 0
    rah = *(const uint4*)pAH; ral = *(const uint4*)pAL;
    rbh = *(const uint4*)pBH; rbl = *(const uint4*)pBL;
    *(uint4*)&Ash[0][0][srow][sseg * 8] = rah;
    *(uint4*)&Ash[0][1][srow][sseg * 8] = ral;
    *(uint4*)&Bsh[0][0][srow][sseg * 8] = rbh;
    *(uint4*)&Bsh[0][1][srow][sseg * 8] = rbl;
    __syncthreads();

    const int lr = lane & 15, lc = lane >> 4;
    const int brow = wn * 32 + (lane & 7) + ((lane >> 3) & 1) * 8;

    int buf = 0;
    for (int kt = 0; kt < NK; ++kt) {
        if (kt + 1 < NK) {
            rah = *(const uint4*)(pAH + (kt + 1) * 16);
            ral = *(const uint4*)(pAL + (kt + 1) * 16);
            rbh = *(const uint4*)(pBH + (kt + 1) * 16);
            rbl = *(const uint4*)(pBL + (kt + 1) * 16);
        }

        uint32_t ah[4][4], al[4][4], bh[2][4], bl[2][4];
        {
            uint32_t aH = (uint32_t)__cvta_generic_to_shared(&Ash[buf][0][wm * 64 + lr][0]) + lc * 16;
            uint32_t aL = (uint32_t)__cvta_generic_to_shared(&Ash[buf][1][wm * 64 + lr][0]) + lc * 16;
#pragma unroll
            for (int mt = 0; mt < 4; mt++) {
                LDSM4(ah[mt], aH + mt * 16 * 48);
                LDSM4(al[mt], aL + mt * 16 * 48);
            }
            uint32_t bH = (uint32_t)__cvta_generic_to_shared(&Bsh[buf][0][brow][0]) + lc * 16;
            uint32_t bL = (uint32_t)__cvta_generic_to_shared(&Bsh[buf][1][brow][0]) + lc * 16;
#pragma unroll
            for (int np = 0; np < 2; np++) {
                LDSM4(bh[np], bH + np * 16 * 48);
                LDSM4(bl[np], bL + np * 16 * 48);
            }
        }
#pragma unroll
        for (int mt = 0; mt < 4; mt++) {
#pragma unroll
            for (int nt = 0; nt < 4; nt++) {
                const int np = nt >> 1, sel = nt & 1;
                MMA16816(acc[mt][nt], ah[mt], bh[np][sel], bh[np][sel + 2]);
                MMA16816(acc[mt][nt], ah[mt], bl[np][sel], bl[np][sel + 2]);
                MMA16816(acc[mt][nt], al[mt], bh[np][sel], bh[np][sel + 2]);
            }
        }

        if (kt + 1 < NK) {
            buf ^= 1;
            *(uint4*)&Ash[buf][0][srow][sseg * 8] = rah;
            *(uint4*)&Ash[buf][1][srow][sseg * 8] = ral;
            *(uint4*)&Bsh[buf][0][srow][sseg * 8] = rbh;
            *(uint4*)&Bsh[buf][1][srow][sseg * 8] = rbl;
            __syncthreads();
        }
    }

    // epilogue
    float* Cbase;
    int ldc;
    if (MODE == 0) {
        const int bb = n0 >> 11;
        const int l0c = n0 & (L_SEQ - 1);
        Cbase = Cg + ((size_t)bb * E2 + m0) * L_SEQ + l0c;
        ldc = L_SEQ;
    } else {
        Cbase = Cg + (size_t)m0 * D_MODEL + n0;
        ldc = D_MODEL;
    }
#pragma unroll
    for (int mt = 0; mt < 4; mt++) {
        int row = wm * 64 + mt * 16 + (lane >> 2);
#pragma unroll
        for (int nt = 0; nt < 4; nt++) {
            int col = wn * 32 + nt * 8 + (lane & 3) * 2;
            *(float2*)(Cbase + (size_t)row * ldc + col) = make_float2(acc[mt][nt][0], acc[mt][nt][1]);
            *(float2*)(Cbase + (size_t)(row + 8) * ldc + col) = make_float2(acc[mt][nt][2], acc[mt][nt][3]);
        }
    }
}

// ---------------- depthwise conv + SiLU ----------------
__global__ __launch_bounds__(256) void k_conv(const float* __restrict__ cw, const float* __restrict__ cb,
                                              const float* __restrict__ cwb, const float* __restrict__ cbb) {
    const int tid = threadIdx.x;
    const int l0 = blockIdx.x * 256;
    const int d = blockIdx.y;
    const int b = blockIdx.z;
    __shared__ float xs[262];
    const float* xp = g_xz + (b * E2 + d) * L_SEQ;
    for (int i = tid; i < 262; i += 256) {
        int l = l0 - 3 + i;
        xs[i] = (l >= 0 && l < L_SEQ) ? xp[l] : 0.f;
    }
    __syncthreads();
    float wf0 = cw[d * 4 + 0], wf1 = cw[d * 4 + 1], wf2 = cw[d * 4 + 2], wf3 = cw[d * 4 + 3];
    float wb0 = cwb[d * 4 + 0], wb1 = cwb[d * 4 + 1], wb2 = cwb[d * 4 + 2], wb3 = cwb[d * 4 + 3];
    float bf = cb[d], bback = cbb[d];
    int l = l0 + tid;
    float sf = bf + wf0 * xs[tid] + wf1 * xs[tid + 1] + wf2 * xs[tid + 2] + wf3 * xs[tid + 3];
    float sb = bback + wb0 * xs[tid + 6] + wb1 * xs[tid + 5] + wb2 * xs[tid + 4] + wb3 * xs[tid + 3];
    g_xc[0][(b * D_INNER + d) * L_SEQ + l] = siluf(sf);
    g_xc[1][(b * D_INNER + d) * L_SEQ + (L_SEQ - 1 - l)] = siluf(sb);
}

// ---------------- zero g_xdbl ----------------
__global__ __launch_bounds__(256) void k_zero(float4* p, int n4) {
    int i = blockIdx.x * blockDim.x + threadIdx.x;
    if (i < n4) p[i] = make_float4(0.f, 0.f, 0.f, 0.f);
}

// ---------------- x_dbl, split-K x4 with atomics ----------------
__global__ __launch_bounds__(256) void k_xdbl(const float* __restrict__ Wx, const float* __restrict__ Wxb) {
    __shared__ float As[16][80];
    __shared__ float Bs[16][128];
    const int tid = threadIdx.x;
    const int l0 = blockIdx.x * 128;
    const int b = blockIdx.y;
    const int br = blockIdx.z >> 2;
    const int ks = blockIdx.z & 3;
    const float* W = br ? Wxb : Wx;
    const float* xc = g_xc[br];
    const int tx = tid & 15, ty = tid >> 4;
    const int k0 = ks * (D_INNER / 4);

    float acc[5][8];
#pragma unroll
    for (int i = 0; i < 5; i++)
#pragma unroll
        for (int j = 0; j < 8; j++) acc[i][j] = 0.f;

    for (int kt = 0; kt < D_INNER / 64; ++kt) {
        __syncthreads();
        for (int lin = tid; lin < 1280; lin += 256) {
            int k = lin >> 4, i = lin & 15;
            As[i][k] = W[k * D_INNER + k0 + kt * 16 + i];
        }
        for (int lin = tid; lin < 2048; lin += 256) {
            int r = lin >> 7, c = lin & 127;
            Bs[r][c] = xc[(b * D_INNER + k0 + kt * 16 + r) * L_SEQ + l0 + c];
        }
        __syncthreads();
#pragma unroll
        for (int kk = 0; kk < 16; kk++) {
            float av[5], bv[8];
#pragma unroll
            for (int i = 0; i < 5; i++) av[i] = As[kk][ty * 5 + i];
            float4 b0 = *(const float4*)&Bs[kk][tx * 8];
            float4 b1 = *(const float4*)&Bs[kk][tx * 8 + 4];
            bv[0] = b0.x; bv[1] = b0.y; bv[2] = b0.z; bv[3] = b0.w;
            bv[4] = b1.x; bv[5] = b1.y; bv[6] = b1.z; bv[7] = b1.w;
#pragma unroll
            for (int i = 0; i < 5; i++)
#pragma unroll
                for (int j = 0; j < 8; j++) acc[i][j] = fmaf(av[i], bv[j], acc[i][j]);
        }
    }
#pragma unroll
    for (int i = 0; i < 5; i++) {
        float* op = g_xdbl[br] + (b * XD + ty * 5 + i) * L_SEQ + l0 + tx * 8;
#pragma unroll
        for (int j = 0; j < 8; j++) atomicAdd(op + j, acc[i][j]);
    }
}

// ---------------- dt projection + softplus ----------------
__global__ __launch_bounds__(256) void k_dt(const float* __restrict__ Wdt, const float* __restrict__ bdt,
                                            const float* __restrict__ Wdtb, const float* __restrict__ bdtb) {
    __shared__ float As[48][128];
    __shared__ float Bs[48][64];
    const int tid = threadIdx.x;
    const int d0 = blockIdx.x * 128;
    const int l0 = blockIdx.y * 64;
    const int zb = blockIdx.z;
    const int br = zb >> 1, b = zb & 1;
    const float* W = br ? Wdtb : Wdt;
    const float* bias = br ? bdtb : bdt;
    const float* xd = g_xdbl[br];

    for (int lin = tid * 4; lin < 6144; lin += 1024) {
        int row = lin / 48, c = lin % 48;
        float4 v = *(const float4*)(W + (d0 + row) * DR + c);
        As[c + 0][row] = v.x; As[c + 1][row] = v.y; As[c + 2][row] = v.z; As[c + 3][row] = v.w;
    }
    for (int lin = tid * 4; lin < 3072; lin += 1024) {
        int r = lin >> 6, c = lin & 63;
        *(float4*)&Bs[r][c] = *(const float4*)(xd + (b * XD + r) * L_SEQ + l0 + c);
    }
    __syncthreads();

    const int tx = tid & 15, ty = tid >> 4;
    float acc[8][4];
#pragma unroll
    for (int i = 0; i < 8; i++)
#pragma unroll
        for (int j = 0; j < 4; j++) acc[i][j] = 0.f;

#pragma unroll 4
    for (int k = 0; k < 48; k++) {
        float4 a0 = *(const float4*)&As[k][ty * 8];
        float4 a1 = *(const float4*)&As[k][ty * 8 + 4];
        float av[8] = {a0.x, a0.y, a0.z, a0.w, a1.x, a1.y, a1.z, a1.w};
        float4 bq = *(const float4*)&Bs[k][tx * 4];
        float bv[4] = {bq.x, bq.y, bq.z, bq.w};
#pragma unroll
        for (int i = 0; i < 8; i++)
#pragma unroll
            for (int j = 0; j < 4; j++) acc[i][j] = fmaf(av[i], bv[j], acc[i][j]);
    }
#pragma unroll
    for (int i = 0; i < 8; i++) {
        int d = d0 + ty * 8 + i;
        float bi = bias[d];
        float4 o;
        o.x = softplusf(acc[i][0] + bi);
        o.y = softplusf(acc[i][1] + bi);
        o.z = softplusf(acc[i][2] + bi);
        o.w = softplusf(acc[i][3] + bi);
        *(float4*)(g_dt[br] + (b * D_INNER + d) * L_SEQ + l0 + tx * 4) = o;
    }
}

// ---------------- scan pass 1 (fast path: a[n] == -(n+1) -> one exp per step) ----------------
__global__ __launch_bounds__(128) void k_scan1(const float* __restrict__ Alog, const float* __restrict__ Alogb) {
    const int tid = threadIdx.x;
    const int d = blockIdx.x * 128 + tid;
    const int chunk = blockIdx.y;
    const int zb = blockIdx.z;
    const int br = zb >> 1, b = zb & 1;
    const float* Al = br ? Alogb : Alog;
    float a[DS];
    int fast = 1;
#pragma unroll
    for (int n = 0; n < DS; n++) {
        a[n] = -expf(Al[d * DS + n]);
        fast &= (fabsf(a[n] + (float)(n + 1)) < 1e-4f * (float)(n + 1));
    }

    __shared__ float Bsh[CHL][DS + 1];
    const int l0 = chunk * CHL;
    const float* xd = g_xdbl[br] + (b * XD) * L_SEQ;
    for (int i = tid; i < CHL * DS; i += 128) {
        int n = i >> 7, t = i & (CHL - 1);
        Bsh[t][n] = xd[(DR + n) * L_SEQ + l0 + t];
    }
    __syncthreads();

    const float* dtp = g_dt[br] + (b * D_INNER + d) * L_SEQ + l0;
    const float* xp = g_xc[br] + (b * D_INNER + d) * L_SEQ + l0;
    float h[DS];
    float S = 0.f;
#pragma unroll
    for (int n = 0; n < DS; n++) h[n] = 0.f;

    if (fast) {
#pragma unroll 2
        for (int t = 0; t < CHL; t++) {
            float dt = dtp[t], x = xp[t];
            float dtx = dt * x;
            float r = __expf(-dt);
            S += dt;
            float p = 1.f;
#pragma unroll
            for (int n = 0; n < DS; n++) {
                p *= r;  // p = exp(-(n+1)*dt) = exp(dt*a[n])
                h[n] = fmaf(p, h[n], dtx * Bsh[t][n]);
            }
        }
    } else {
#pragma unroll 2
        for (int t = 0; t < CHL; t++) {
            float dt = dtp[t], x = xp[t];
            float dtx = dt * x;
            S += dt;
#pragma unroll
            for (int n = 0; n < DS; n++) {
                float dA = __expf(dt * a[n]);
                h[n] = fmaf(dA, h[n], dtx * Bsh[t][n]);
            }
        }
    }
    size_t base = ((size_t)(zb * D_INNER + d) * NCH + chunk) * DS;
#pragma unroll
    for (int n = 0; n < DS; n++) {
        g_hfin[base + n] = h[n];
        g_P[base + n] = __expf(a[n] * S);  // prod_t exp(dt_t*a_n) = exp(a_n * sum dt)
    }
}

// ---------------- scan pass 2 ----------------
__global__ void k_scan2() {
    int id = blockIdx.x * blockDim.x + threadIdx.x;
    if (id >= 2 * BSZ * D_INNER * DS) return;
    int n = id & 15;
    int rest = id >> 4;
    int d = rest % D_INNER;
    int zb = rest / D_INNER;
    size_t base = ((size_t)(zb * D_INNER + d)) * (NCH * DS) + n;
    float H = 0.f;
#pragma unroll
    for (int c = 0; c < NCH; c++) {
        g_Hinit[base + c * DS] = H;
        H = g_P[base + c * DS] * H + g_hfin[base + c * DS];
    }
}

// ---------------- scan pass 3 ----------------
__global__ __launch_bounds__(128) void k_scan3(const float* __restrict__ Alog, const float* __restrict__ Alogb,
                                               const float* __restrict__ Dp, const float* __restrict__ Dpb) {
    const int tid = threadIdx.x;
    const int d = blockIdx.x * 128 + tid;
    const int chunk = blockIdx.y;
    const int zb = blockIdx.z;
    const int br = zb >> 1, b = zb & 1;
    const float* Al = br ? Alogb : Alog;
    float a[DS];
    int fast = 1;
#pragma unroll
    for (int n = 0; n < DS; n++) {
        a[n] = -expf(Al[d * DS + n]);
        fast &= (fabsf(a[n] + (float)(n + 1)) < 1e-4f * (float)(n + 1));
    }

    __shared__ float Bsh[CHL][DS + 1];
    __shared__ float Csh[CHL][DS + 1];
    const int l0 = chunk * CHL;
    const float* xd = g_xdbl[br] + (b * XD) * L_SEQ;
    for (int i = tid; i < CHL * DS; i += 128) {
        int n = i >> 7, t = i & (CHL - 1);
        Bsh[t][n] = xd[(DR + n) * L_SEQ + l0 + t];
        Csh[t][n] = xd[(DR + DS + n) * L_SEQ + l0 + t];
    }
    __syncthreads();

    size_t sbase = ((size_t)(zb * D_INNER + d) * NCH + chunk) * DS;
    float h[DS];
#pragma unroll
    for (int n = 0; n < DS; n++) h[n] = g_Hinit[sbase + n];
    float Dd = (br ? Dpb : Dp)[d];

    const float* dtp = g_dt[br] + (b * D_INNER + d) * L_SEQ + l0;
    const float* xp = g_xc[br] + (b * D_INNER + d) * L_SEQ + l0;
    const float* zp = g_xz + (b * E2 + D_INNER + d) * L_SEQ;
    float* op = g_acc[br] + (b * D_INNER + d) * L_SEQ + l0;

    if (fast) {
#pragma unroll 2
        for (int t = 0; t < CHL; t++) {
            float dt = dtp[t], x = xp[t];
            float dtx = dt * x;
            float r = __expf(-dt);
            float p = 1.f;
            float y = 0.f;
#pragma unroll
            for (int n = 0; n < DS; n++) {
                p *= r;
                h[n] = fmaf(p, h[n], dtx * Bsh[t][n]);
                y = fmaf(h[n], Csh[t][n], y);
            }
            int l = l0 + t;
            float zv = br ? zp[(L_SEQ - 1) - l] : zp[l];
            op[t] = (y + Dd * x) * siluf(zv);
        }
    } else {
#pragma unroll 2
        for (int t = 0; t < CHL; t++) {
            float dt = dtp[t], x = xp[t];
            float dtx = dt * x;
            float y = 0.f;
#pragma unroll
            for (int n = 0; n < DS; n++) {
                float dA = __expf(dt * a[n]);
                h[n] = fmaf(dA, h[n], dtx * Bsh[t][n]);
                y = fmaf(h[n], Csh[t][n], y);
            }
            int l = l0 + t;
            float zv = br ? zp[(L_SEQ - 1) - l] : zp[l];
            op[t] = (y + Dd * x) * siluf(zv);
        }
    }
}

// ---------------- launch ----------------
extern "C" void kernel_launch(void* const* d_in, const int* in_sizes, int n_in,
                              void* d_out, int out_size) {
    const float* hid  = (const float*)d_in[0];
    const float* Win  = (const float*)d_in[1];
    const float* cw   = (const float*)d_in[2];
    const float* cb   = (const float*)d_in[3];
    const float* cwb  = (const float*)d_in[4];
    const float* cbb  = (const float*)d_in[5];
    const float* Wx   = (const float*)d_in[6];
    const float* Wxb  = (const float*)d_in[7];
    const float* Wdt  = (const float*)d_in[8];
    const float* bdt  = (const float*)d_in[9];
    const float* Wdtb = (const float*)d_in[10];
    const float* bdtb = (const float*)d_in[11];
    const float* Alog = (const float*)d_in[12];
    const float* Alogb= (const float*)d_in[13];
    const float* Dp   = (const float*)d_in[14];
    const float* Dpb  = (const float*)d_in[15];
    const float* Wout = (const float*)d_in[16];
    float* out = (float*)d_out;

    uint16_t *WinH, *WinL, *hidH, *hidL, *WoutH, *WoutL, *midH, *midL;
    float *xzP, *xdblP;
    cudaGetSymbolAddress((void**)&WinH, g_WinH);   cudaGetSymbolAddress((void**)&WinL, g_WinL);
    cudaGetSymbolAddress((void**)&hidH, g_hidH);   cudaGetSymbolAddress((void**)&hidL, g_hidL);
    cudaGetSymbolAddress((void**)&WoutH, g_WoutH); cudaGetSymbolAddress((void**)&WoutL, g_WoutL);
    cudaGetSymbolAddress((void**)&midH, g_midH);   cudaGetSymbolAddress((void**)&midL, g_midL);
    cudaGetSymbolAddress((void**)&xzP, g_xz);
    cudaGetSymbolAddress((void**)&xdblP, g_xdbl);

    k_packsplit<<<(E2 * D_MODEL / 4 + 255) / 256, 256>>>((const float4*)Win, (ushort4*)WinH, (ushort4*)WinL, E2 * D_MODEL / 4);
    k_packsplit<<<(NTOK * D_MODEL / 4 + 255) / 256, 256>>>((const float4*)hid, (ushort4*)hidH, (ushort4*)hidL, NTOK * D_MODEL / 4);
    k_packsplit<<<(D_MODEL * D_INNER / 4 + 255) / 256, 256>>>((const float4*)Wout, (ushort4*)WoutH, (ushort4*)WoutL, D_MODEL * D_INNER / 4);

    // xz = Win @ hid^T : M=3072(e), N=4096(tok), K=768
    k_mma<0><<<dim3(NTOK / 128, E2 / 128), 256>>>(WinH, WinL, hidH, hidL, xzP, D_MODEL);

    k_conv<<<dim3(L_SEQ / 256, D_INNER, BSZ), 256>>>(cw, cb, cwb, cbb);

    k_zero<<<(2 * BSZ * XD * L_SEQ / 4 + 255) / 256, 256>>>((float4*)xdblP, 2 * BSZ * XD * L_SEQ / 4);
    k_xdbl<<<dim3(L_SEQ / 128, BSZ, 8), 256>>>(Wx, Wxb);

    k_dt<<<dim3(D_INNER / 128, L_SEQ / 64, 4), 256>>>(Wdt, bdt, Wdtb, bdtb);
    k_scan1<<<dim3(D_INNER / 128, NCH, 4), 128>>>(Alog, Alogb);
    k_scan2<<<(2 * BSZ * D_INNER * DS + 255) / 256, 256>>>();
    k_scan3<<<dim3(D_INNER / 128, NCH, 4), 128>>>(Alog, Alogb, Dp, Dpb);

    k_midT<<<dim3(L_SEQ / 32, D_INNER / 32, BSZ), dim3(32, 8)>>>();

    // out = mid @ Wout^T : M=4096(tok), N=768, K=1536
    k_mma<1><<<dim3(D_MODEL / 128, NTOK / 128), 256>>>(midH, midL, WoutH, WoutL, out, D_INNER);
}

// round 9
// speedup vs baseline: 1.9070x; 1.2310x over previous
#include <cuda_runtime.h>
#include <cuda_fp16.h>
#include <math.h>
#include <stdint.h>

#define L_SEQ 2048
#define D_MODEL 768
#define D_INNER 1536
#define E2 3072
#define DS 16
#define DR 48
#define XD 80
#define BSZ 2
#define NCH 16
#define CHL 128
#define NTOK 4096

// ---------------- scratch ----------------
__device__ float g_xz[BSZ * E2 * L_SEQ];
__device__ float g_xc[2][BSZ * D_INNER * L_SEQ];
__device__ float g_xdbl[2][BSZ * XD * L_SEQ];
__device__ float g_dt[2][BSZ * D_INNER * L_SEQ];
__device__ float g_hfin[2 * BSZ * D_INNER * NCH * DS];
__device__ float g_P[2 * BSZ * D_INNER * NCH * DS];
__device__ float g_Hinit[2 * BSZ * D_INNER * NCH * DS];
__device__ float g_acc[2][BSZ * D_INNER * L_SEQ];

// fp16 operands: A-side packed (hi,lo) pairs; B-side single fp16 plane
__device__ uint32_t g_WinP[E2 * D_MODEL];
__device__ uint16_t g_hidH[NTOK * D_MODEL];
__device__ uint16_t g_WoutH[D_MODEL * D_INNER];
__device__ uint32_t g_midP[NTOK * D_INNER];

__device__ __forceinline__ float siluf(float v) {
    return v * (1.f / (1.f + __expf(-v)));
}
__device__ __forceinline__ float softplusf(float v) {
    return v > 15.f ? v : log1pf(__expf(v));
}
__device__ __forceinline__ uint32_t pack2h(float x) {
    __half h = __float2half(x);
    __half l = __float2half(x - __half2float(h));
    return (uint32_t)__half_as_ushort(h) | ((uint32_t)__half_as_ushort(l) << 16);
}

// ---------------- pack float -> packed fp16 (hi,lo) pairs ----------------
__global__ __launch_bounds__(256) void k_packu32(const float4* __restrict__ s, uint4* __restrict__ d, int n4) {
    int i = blockIdx.x * blockDim.x + threadIdx.x;
    if (i < n4) {
        float4 v = s[i];
        d[i] = make_uint4(pack2h(v.x), pack2h(v.y), pack2h(v.z), pack2h(v.w));
    }
}

// ---------------- pack float -> single fp16 plane ----------------
__global__ __launch_bounds__(256) void k_packh(const float4* __restrict__ s, ushort4* __restrict__ d, int n4) {
    int i = blockIdx.x * blockDim.x + threadIdx.x;
    if (i < n4) {
        float4 v = s[i];
        ushort4 o;
        o.x = __half_as_ushort(__float2half(v.x));
        o.y = __half_as_ushort(__float2half(v.y));
        o.z = __half_as_ushort(__float2half(v.z));
        o.w = __half_as_ushort(__float2half(v.w));
        d[i] = o;
    }
}

// ---------------- mid transpose + combine + pack ----------------
__global__ __launch_bounds__(256) void k_midT() {
    __shared__ float t[32][33];
    int b = blockIdx.z;
    int l0 = blockIdx.x * 32, d0 = blockIdx.y * 32;
    int tx = threadIdx.x, ty = threadIdx.y;
    const float* F = g_acc[0] + (size_t)b * D_INNER * L_SEQ;
    const float* Bk = g_acc[1] + (size_t)b * D_INNER * L_SEQ;
#pragma unroll
    for (int i = 0; i < 4; i++) {
        int d = d0 + ty + i * 8;
        float f = F[(size_t)d * L_SEQ + l0 + tx];
        float r = Bk[(size_t)d * L_SEQ + (L_SEQ - 1) - (l0 + tx)];
        t[ty + i * 8][tx] = 0.5f * (f + r);
    }
    __syncthreads();
#pragma unroll
    for (int i = 0; i < 4; i++) {
        int l = l0 + ty + i * 8;
        g_midP[((size_t)(b * L_SEQ) + l) * D_INNER + d0 + tx] = pack2h(t[tx][ty + i * 8]);
    }
}

// ---------------- tensor-core GEMM: fp16 2-pass (Ah*Bh + Al*Bh) ----------------
#define LDSM4(R, addr) \
    asm volatile("ldmatrix.sync.aligned.m8n8.x4.shared.b16 {%0,%1,%2,%3},[%4];" \
                 : "=r"(R[0]), "=r"(R[1]), "=r"(R[2]), "=r"(R[3]) : "r"(addr))

#define MMA16816(c, a, b0_, b1_) \
    asm volatile("mma.sync.aligned.m16n8k16.row.col.f32.f16.f16.f32 " \
                 "{%0,%1,%2,%3},{%4,%5,%6,%7},{%8,%9},{%0,%1,%2,%3};" \
                 : "+f"(c[0]), "+f"(c[1]), "+f"(c[2]), "+f"(c[3]) \
                 : "r"(a[0]), "r"(a[1]), "r"(a[2]), "r"(a[3]), "r"(b0_), "r"(b1_))

#define PK_HI(u, v) __byte_perm(u, v, 0x5410)
#define PK_LO(u, v) __byte_perm(u, v, 0x7632)

// CTA tile 128x128, warps 2x4 (warp tile 64x32).
// MODE 0: C[(bb*E2+m)*L + l]   MODE 1: C[m*768 + n]
template <int MODE>
__global__ __launch_bounds__(256) void k_mma(const uint32_t* __restrict__ Ag,
                                             const uint16_t* __restrict__ Bg,
                                             float* __restrict__ Cg, int K) {
    __shared__ __align__(16) uint16_t Ash[2][2][128][24];  // [buf][hi/lo][row][16+pad8]
    __shared__ __align__(16) uint16_t Bsh[2][128][24];

    const int tid = threadIdx.x;
    const int lane = tid & 31, wid = tid >> 5;
    const int wm = wid >> 2, wn = wid & 3;  // 2 x 4 warps
    const int m0 = blockIdx.y * 128, n0 = blockIdx.x * 128;

    // A staging: packed u32, rows ar & ar+64, 4 u32 per load
    const int ar = tid >> 2, akq = (tid & 3) * 4;
    const uint32_t* pA0 = Ag + (size_t)(m0 + ar) * K + akq;
    const uint32_t* pA1 = pA0 + (size_t)64 * K;
    // B staging: fp16 plane, 128 rows x 2 segs of 8 fp16
    const int brrow = tid >> 1, bseg = tid & 1;
    const uint16_t* pB = Bg + (size_t)(n0 + brrow) * K + bseg * 8;

    const int NK = K >> 4;

    float acc[4][4][4];
#pragma unroll
    for (int i = 0; i < 4; i++)
#pragma unroll
        for (int j = 0; j < 4; j++)
#pragma unroll
            for (int q = 0; q < 4; q++) acc[i][j][q] = 0.f;

    uint4 ra0, ra1, rb;
    // prologue
    ra0 = *(const uint4*)pA0;
    ra1 = *(const uint4*)pA1;
    rb  = *(const uint4*)pB;
    *(uint2*)&Ash[0][0][ar][akq]      = make_uint2(PK_HI(ra0.x, ra0.y), PK_HI(ra0.z, ra0.w));
    *(uint2*)&Ash[0][1][ar][akq]      = make_uint2(PK_LO(ra0.x, ra0.y), PK_LO(ra0.z, ra0.w));
    *(uint2*)&Ash[0][0][ar + 64][akq] = make_uint2(PK_HI(ra1.x, ra1.y), PK_HI(ra1.z, ra1.w));
    *(uint2*)&Ash[0][1][ar + 64][akq] = make_uint2(PK_LO(ra1.x, ra1.y), PK_LO(ra1.z, ra1.w));
    *(uint4*)&Bsh[0][brrow][bseg * 8] = rb;
    __syncthreads();

    const int lr = lane & 15, lc = lane >> 4;
    const int brow = wn * 32 + (lane & 7) + ((lane >> 3) & 1) * 8;

    int buf = 0;
    for (int kt = 0; kt < NK; ++kt) {
        if (kt + 1 < NK) {
            ra0 = *(const uint4*)(pA0 + (kt + 1) * 16);
            ra1 = *(const uint4*)(pA1 + (kt + 1) * 16);
            rb  = *(const uint4*)(pB + (kt + 1) * 16);
        }

        uint32_t ah[4][4], al[4][4], bh[2][4];
        {
            uint32_t aH = (uint32_t)__cvta_generic_to_shared(&Ash[buf][0][wm * 64 + lr][0]) + lc * 16;
            uint32_t aL = (uint32_t)__cvta_generic_to_shared(&Ash[buf][1][wm * 64 + lr][0]) + lc * 16;
#pragma unroll
            for (int mt = 0; mt < 4; mt++) {
                LDSM4(ah[mt], aH + mt * 16 * 48);
                LDSM4(al[mt], aL + mt * 16 * 48);
            }
            uint32_t bH = (uint32_t)__cvta_generic_to_shared(&Bsh[buf][brow][0]) + lc * 16;
#pragma unroll
            for (int np = 0; np < 2; np++) {
                LDSM4(bh[np], bH + np * 16 * 48);
            }
        }
#pragma unroll
        for (int mt = 0; mt < 4; mt++) {
#pragma unroll
            for (int nt = 0; nt < 4; nt++) {
                const int np = nt >> 1, sel = nt & 1;
                MMA16816(acc[mt][nt], ah[mt], bh[np][sel], bh[np][sel + 2]);
                MMA16816(acc[mt][nt], al[mt], bh[np][sel], bh[np][sel + 2]);
            }
        }

        if (kt + 1 < NK) {
            buf ^= 1;
            *(uint2*)&Ash[buf][0][ar][akq]      = make_uint2(PK_HI(ra0.x, ra0.y), PK_HI(ra0.z, ra0.w));
            *(uint2*)&Ash[buf][1][ar][akq]      = make_uint2(PK_LO(ra0.x, ra0.y), PK_LO(ra0.z, ra0.w));
            *(uint2*)&Ash[buf][0][ar + 64][akq] = make_uint2(PK_HI(ra1.x, ra1.y), PK_HI(ra1.z, ra1.w));
            *(uint2*)&Ash[buf][1][ar + 64][akq] = make_uint2(PK_LO(ra1.x, ra1.y), PK_LO(ra1.z, ra1.w));
            *(uint4*)&Bsh[buf][brrow][bseg * 8] = rb;
            __syncthreads();
        }
    }

    // epilogue
    float* Cbase;
    int ldc;
    if (MODE == 0) {
        const int bb = n0 >> 11;
        const int l0c = n0 & (L_SEQ - 1);
        Cbase = Cg + ((size_t)bb * E2 + m0) * L_SEQ + l0c;
        ldc = L_SEQ;
    } else {
        Cbase = Cg + (size_t)m0 * D_MODEL + n0;
        ldc = D_MODEL;
    }
#pragma unroll
    for (int mt = 0; mt < 4; mt++) {
        int row = wm * 64 + mt * 16 + (lane >> 2);
#pragma unroll
        for (int nt = 0; nt < 4; nt++) {
            int col = wn * 32 + nt * 8 + (lane & 3) * 2;
            *(float2*)(Cbase + (size_t)row * ldc + col) = make_float2(acc[mt][nt][0], acc[mt][nt][1]);
            *(float2*)(Cbase + (size_t)(row + 8) * ldc + col) = make_float2(acc[mt][nt][2], acc[mt][nt][3]);
        }
    }
}

// ---------------- depthwise conv + SiLU ----------------
__global__ __launch_bounds__(256) void k_conv(const float* __restrict__ cw, const float* __restrict__ cb,
                                              const float* __restrict__ cwb, const float* __restrict__ cbb) {
    const int tid = threadIdx.x;
    const int l0 = blockIdx.x * 256;
    const int d = blockIdx.y;
    const int b = blockIdx.z;
    __shared__ float xs[262];
    const float* xp = g_xz + (b * E2 + d) * L_SEQ;
    for (int i = tid; i < 262; i += 256) {
        int l = l0 - 3 + i;
        xs[i] = (l >= 0 && l < L_SEQ) ? xp[l] : 0.f;
    }
    __syncthreads();
    float wf0 = cw[d * 4 + 0], wf1 = cw[d * 4 + 1], wf2 = cw[d * 4 + 2], wf3 = cw[d * 4 + 3];
    float wb0 = cwb[d * 4 + 0], wb1 = cwb[d * 4 + 1], wb2 = cwb[d * 4 + 2], wb3 = cwb[d * 4 + 3];
    float bf = cb[d], bback = cbb[d];
    int l = l0 + tid;
    float sf = bf + wf0 * xs[tid] + wf1 * xs[tid + 1] + wf2 * xs[tid + 2] + wf3 * xs[tid + 3];
    float sb = bback + wb0 * xs[tid + 6] + wb1 * xs[tid + 5] + wb2 * xs[tid + 4] + wb3 * xs[tid + 3];
    g_xc[0][(b * D_INNER + d) * L_SEQ + l] = siluf(sf);
    g_xc[1][(b * D_INNER + d) * L_SEQ + (L_SEQ - 1 - l)] = siluf(sb);
}

// ---------------- zero g_xdbl ----------------
__global__ __launch_bounds__(256) void k_zero(float4* p, int n4) {
    int i = blockIdx.x * blockDim.x + threadIdx.x;
    if (i < n4) p[i] = make_float4(0.f, 0.f, 0.f, 0.f);
}

// ---------------- x_dbl, split-K x4 with atomics ----------------
__global__ __launch_bounds__(256) void k_xdbl(const float* __restrict__ Wx, const float* __restrict__ Wxb) {
    __shared__ float As[16][80];
    __shared__ float Bs[16][128];
    const int tid = threadIdx.x;
    const int l0 = blockIdx.x * 128;
    const int b = blockIdx.y;
    const int br = blockIdx.z >> 2;
    const int ks = blockIdx.z & 3;
    const float* W = br ? Wxb : Wx;
    const float* xc = g_xc[br];
    const int tx = tid & 15, ty = tid >> 4;
    const int k0 = ks * (D_INNER / 4);

    float acc[5][8];
#pragma unroll
    for (int i = 0; i < 5; i++)
#pragma unroll
        for (int j = 0; j < 8; j++) acc[i][j] = 0.f;

    for (int kt = 0; kt < D_INNER / 64; ++kt) {
        __syncthreads();
        for (int lin = tid; lin < 1280; lin += 256) {
            int k = lin >> 4, i = lin & 15;
            As[i][k] = W[k * D_INNER + k0 + kt * 16 + i];
        }
        for (int lin = tid; lin < 2048; lin += 256) {
            int r = lin >> 7, c = lin & 127;
            Bs[r][c] = xc[(b * D_INNER + k0 + kt * 16 + r) * L_SEQ + l0 + c];
        }
        __syncthreads();
#pragma unroll
        for (int kk = 0; kk < 16; kk++) {
            float av[5], bv[8];
#pragma unroll
            for (int i = 0; i < 5; i++) av[i] = As[kk][ty * 5 + i];
            float4 b0 = *(const float4*)&Bs[kk][tx * 8];
            float4 b1 = *(const float4*)&Bs[kk][tx * 8 + 4];
            bv[0] = b0.x; bv[1] = b0.y; bv[2] = b0.z; bv[3] = b0.w;
            bv[4] = b1.x; bv[5] = b1.y; bv[6] = b1.z; bv[7] = b1.w;
#pragma unroll
            for (int i = 0; i < 5; i++)
#pragma unroll
                for (int j = 0; j < 8; j++) acc[i][j] = fmaf(av[i], bv[j], acc[i][j]);
        }
    }
#pragma unroll
    for (int i = 0; i < 5; i++) {
        float* op = g_xdbl[br] + (b * XD + ty * 5 + i) * L_SEQ + l0 + tx * 8;
#pragma unroll
        for (int j = 0; j < 8; j++) atomicAdd(op + j, acc[i][j]);
    }
}

// ---------------- dt projection + softplus ----------------
__global__ __launch_bounds__(256) void k_dt(const float* __restrict__ Wdt, const float* __restrict__ bdt,
                                            const float* __restrict__ Wdtb, const float* __restrict__ bdtb) {
    __shared__ float As[48][128];
    __shared__ float Bs[48][64];
    const int tid = threadIdx.x;
    const int d0 = blockIdx.x * 128;
    const int l0 = blockIdx.y * 64;
    const int zb = blockIdx.z;
    const int br = zb >> 1, b = zb & 1;
    const float* W = br ? Wdtb : Wdt;
    const float* bias = br ? bdtb : bdt;
    const float* xd = g_xdbl[br];

    for (int lin = tid * 4; lin < 6144; lin += 1024) {
        int row = lin / 48, c = lin % 48;
        float4 v = *(const float4*)(W + (d0 + row) * DR + c);
        As[c + 0][row] = v.x; As[c + 1][row] = v.y; As[c + 2][row] = v.z; As[c + 3][row] = v.w;
    }
    for (int lin = tid * 4; lin < 3072; lin += 1024) {
        int r = lin >> 6, c = lin & 63;
        *(float4*)&Bs[r][c] = *(const float4*)(xd + (b * XD + r) * L_SEQ + l0 + c);
    }
    __syncthreads();

    const int tx = tid & 15, ty = tid >> 4;
    float acc[8][4];
#pragma unroll
    for (int i = 0; i < 8; i++)
#pragma unroll
        for (int j = 0; j < 4; j++) acc[i][j] = 0.f;

#pragma unroll 4
    for (int k = 0; k < 48; k++) {
        float4 a0 = *(const float4*)&As[k][ty * 8];
        float4 a1 = *(const float4*)&As[k][ty * 8 + 4];
        float av[8] = {a0.x, a0.y, a0.z, a0.w, a1.x, a1.y, a1.z, a1.w};
        float4 bq = *(const float4*)&Bs[k][tx * 4];
        float bv[4] = {bq.x, bq.y, bq.z, bq.w};
#pragma unroll
        for (int i = 0; i < 8; i++)
#pragma unroll
            for (int j = 0; j < 4; j++) acc[i][j] = fmaf(av[i], bv[j], acc[i][j]);
    }
#pragma unroll
    for (int i = 0; i < 8; i++) {
        int d = d0 + ty * 8 + i;
        float bi = bias[d];
        float4 o;
        o.x = softplusf(acc[i][0] + bi);
        o.y = softplusf(acc[i][1] + bi);
        o.z = softplusf(acc[i][2] + bi);
        o.w = softplusf(acc[i][3] + bi);
        *(float4*)(g_dt[br] + (b * D_INNER + d) * L_SEQ + l0 + tx * 4) = o;
    }
}

// ---------------- scan pass 1 (fast path: a[n] == -(n+1) -> one exp per step) ----------------
__global__ __launch_bounds__(128) void k_scan1(const float* __restrict__ Alog, const float* __restrict__ Alogb) {
    const int tid = threadIdx.x;
    const int d = blockIdx.x * 128 + tid;
    const int chunk = blockIdx.y;
    const int zb = blockIdx.z;
    const int br = zb >> 1, b = zb & 1;
    const float* Al = br ? Alogb : Alog;
    float a[DS];
    int fast = 1;
#pragma unroll
    for (int n = 0; n < DS; n++) {
        a[n] = -expf(Al[d * DS + n]);
        fast &= (fabsf(a[n] + (float)(n + 1)) < 1e-4f * (float)(n + 1));
    }

    __shared__ float Bsh[CHL][DS + 1];
    const int l0 = chunk * CHL;
    const float* xd = g_xdbl[br] + (b * XD) * L_SEQ;
    for (int i = tid; i < CHL * DS; i += 128) {
        int n = i >> 7, t = i & (CHL - 1);
        Bsh[t][n] = xd[(DR + n) * L_SEQ + l0 + t];
    }
    __syncthreads();

    const float* dtp = g_dt[br] + (b * D_INNER + d) * L_SEQ + l0;
    const float* xp = g_xc[br] + (b * D_INNER + d) * L_SEQ + l0;
    float h[DS];
    float S = 0.f;
#pragma unroll
    for (int n = 0; n < DS; n++) h[n] = 0.f;

    if (fast) {
#pragma unroll 2
        for (int t = 0; t < CHL; t++) {
            float dt = dtp[t], x = xp[t];
            float dtx = dt * x;
            float r = __expf(-dt);
            S += dt;
            float p = 1.f;
#pragma unroll
            for (int n = 0; n < DS; n++) {
                p *= r;
                h[n] = fmaf(p, h[n], dtx * Bsh[t][n]);
            }
        }
    } else {
#pragma unroll 2
        for (int t = 0; t < CHL; t++) {
            float dt = dtp[t], x = xp[t];
            float dtx = dt * x;
            S += dt;
#pragma unroll
            for (int n = 0; n < DS; n++) {
                float dA = __expf(dt * a[n]);
                h[n] = fmaf(dA, h[n], dtx * Bsh[t][n]);
            }
        }
    }
    size_t base = ((size_t)(zb * D_INNER + d) * NCH + chunk) * DS;
#pragma unroll
    for (int n = 0; n < DS; n++) {
        g_hfin[base + n] = h[n];
        g_P[base + n] = __expf(a[n] * S);
    }
}

// ---------------- scan pass 2 ----------------
__global__ void k_scan2() {
    int id = blockIdx.x * blockDim.x + threadIdx.x;
    if (id >= 2 * BSZ * D_INNER * DS) return;
    int n = id & 15;
    int rest = id >> 4;
    int d = rest % D_INNER;
    int zb = rest / D_INNER;
    size_t base = ((size_t)(zb * D_INNER + d)) * (NCH * DS) + n;
    float H = 0.f;
#pragma unroll
    for (int c = 0; c < NCH; c++) {
        g_Hinit[base + c * DS] = H;
        H = g_P[base + c * DS] * H + g_hfin[base + c * DS];
    }
}

// ---------------- scan pass 3 ----------------
__global__ __launch_bounds__(128) void k_scan3(const float* __restrict__ Alog, const float* __restrict__ Alogb,
                                               const float* __restrict__ Dp, const float* __restrict__ Dpb) {
    const int tid = threadIdx.x;
    const int d = blockIdx.x * 128 + tid;
    const int chunk = blockIdx.y;
    const int zb = blockIdx.z;
    const int br = zb >> 1, b = zb & 1;
    const float* Al = br ? Alogb : Alog;
    float a[DS];
    int fast = 1;
#pragma unroll
    for (int n = 0; n < DS; n++) {
        a[n] = -expf(Al[d * DS + n]);
        fast &= (fabsf(a[n] + (float)(n + 1)) < 1e-4f * (float)(n + 1));
    }

    __shared__ float Bsh[CHL][DS + 1];
    __shared__ float Csh[CHL][DS + 1];
    const int l0 = chunk * CHL;
    const float* xd = g_xdbl[br] + (b * XD) * L_SEQ;
    for (int i = tid; i < CHL * DS; i += 128) {
        int n = i >> 7, t = i & (CHL - 1);
        Bsh[t][n] = xd[(DR + n) * L_SEQ + l0 + t];
        Csh[t][n] = xd[(DR + DS + n) * L_SEQ + l0 + t];
    }
    __syncthreads();

    size_t sbase = ((size_t)(zb * D_INNER + d) * NCH + chunk) * DS;
    float h[DS];
#pragma unroll
    for (int n = 0; n < DS; n++) h[n] = g_Hinit[sbase + n];
    float Dd = (br ? Dpb : Dp)[d];

    const float* dtp = g_dt[br] + (b * D_INNER + d) * L_SEQ + l0;
    const float* xp = g_xc[br] + (b * D_INNER + d) * L_SEQ + l0;
    const float* zp = g_xz + (b * E2 + D_INNER + d) * L_SEQ;
    float* op = g_acc[br] + (b * D_INNER + d) * L_SEQ + l0;

    if (fast) {
#pragma unroll 2
        for (int t = 0; t < CHL; t++) {
            float dt = dtp[t], x = xp[t];
            float dtx = dt * x;
            float r = __expf(-dt);
            float p = 1.f;
            float y = 0.f;
#pragma unroll
            for (int n = 0; n < DS; n++) {
                p *= r;
                h[n] = fmaf(p, h[n], dtx * Bsh[t][n]);
                y = fmaf(h[n], Csh[t][n], y);
            }
            int l = l0 + t;
            float zv = br ? zp[(L_SEQ - 1) - l] : zp[l];
            op[t] = (y + Dd * x) * siluf(zv);
        }
    } else {
#pragma unroll 2
        for (int t = 0; t < CHL; t++) {
            float dt = dtp[t], x = xp[t];
            float dtx = dt * x;
            float y = 0.f;
#pragma unroll
            for (int n = 0; n < DS; n++) {
                float dA = __expf(dt * a[n]);
                h[n] = fmaf(dA, h[n], dtx * Bsh[t][n]);
                y = fmaf(h[n], Csh[t][n], y);
            }
            int l = l0 + t;
            float zv = br ? zp[(L_SEQ - 1) - l] : zp[l];
            op[t] = (y + Dd * x) * siluf(zv);
        }
    }
}

// ---------------- launch ----------------
extern "C" void kernel_launch(void* const* d_in, const int* in_sizes, int n_in,
                              void* d_out, int out_size) {
    const float* hid  = (const float*)d_in[0];
    const float* Win  = (const float*)d_in[1];
    const float* cw   = (const float*)d_in[2];
    const float* cb   = (const float*)d_in[3];
    const float* cwb  = (const float*)d_in[4];
    const float* cbb  = (const float*)d_in[5];
    const float* Wx   = (const float*)d_in[6];
    const float* Wxb  = (const float*)d_in[7];
    const float* Wdt  = (const float*)d_in[8];
    const float* bdt  = (const float*)d_in[9];
    const float* Wdtb = (const float*)d_in[10];
    const float* bdtb = (const float*)d_in[11];
    const float* Alog = (const float*)d_in[12];
    const float* Alogb= (const float*)d_in[13];
    const float* Dp   = (const float*)d_in[14];
    const float* Dpb  = (const float*)d_in[15];
    const float* Wout = (const float*)d_in[16];
    float* out = (float*)d_out;

    uint32_t *WinP, *midP;
    uint16_t *hidH, *WoutH;
    float *xzP, *xdblP;
    cudaGetSymbolAddress((void**)&WinP, g_WinP);
    cudaGetSymbolAddress((void**)&hidH, g_hidH);
    cudaGetSymbolAddress((void**)&WoutH, g_WoutH);
    cudaGetSymbolAddress((void**)&midP, g_midP);
    cudaGetSymbolAddress((void**)&xzP, g_xz);
    cudaGetSymbolAddress((void**)&xdblP, g_xdbl);

    k_packu32<<<(E2 * D_MODEL / 4 + 255) / 256, 256>>>((const float4*)Win, (uint4*)WinP, E2 * D_MODEL / 4);
    k_packh<<<(NTOK * D_MODEL / 4 + 255) / 256, 256>>>((const float4*)hid, (ushort4*)hidH, NTOK * D_MODEL / 4);
    k_packh<<<(D_MODEL * D_INNER / 4 + 255) / 256, 256>>>((const float4*)Wout, (ushort4*)WoutH, D_MODEL * D_INNER / 4);

    // xz = Win @ hid^T : M=3072(e), N=4096(tok), K=768
    k_mma<0><<<dim3(NTOK / 128, E2 / 128), 256>>>(WinP, hidH, xzP, D_MODEL);

    k_conv<<<dim3(L_SEQ / 256, D_INNER, BSZ), 256>>>(cw, cb, cwb, cbb);

    k_zero<<<(2 * BSZ * XD * L_SEQ / 4 + 255) / 256, 256>>>((float4*)xdblP, 2 * BSZ * XD * L_SEQ / 4);
    k_xdbl<<<dim3(L_SEQ / 128, BSZ, 8), 256>>>(Wx, Wxb);

    k_dt<<<dim3(D_INNER / 128, L_SEQ / 64, 4), 256>>>(Wdt, bdt, Wdtb, bdtb);
    k_scan1<<<dim3(D_INNER / 128, NCH, 4), 128>>>(Alog, Alogb);
    k_scan2<<<(2 * BSZ * D_INNER * DS + 255) / 256, 256>>>();
    k_scan3<<<dim3(D_INNER / 128, NCH, 4), 128>>>(Alog, Alogb, Dp, Dpb);

    k_midT<<<dim3(L_SEQ / 32, D_INNER / 32, BSZ), dim3(32, 8)>>>();

    // out = mid @ Wout^T : M=4096(tok), N=768, K=1536
    k_mma<1><<<dim3(D_MODEL / 128, NTOK / 128), 256>>>(midP, WoutH, out, D_INNER);
}

// round 10
// speedup vs baseline: 2.1010x; 1.1017x over previous
#include <cuda_runtime.h>
#include <cuda_fp16.h>
#include <math.h>
#include <stdint.h>

#define L_SEQ 2048
#define D_MODEL 768
#define D_INNER 1536
#define E2 3072
#define DS 16
#define DR 48
#define XD 80
#define BSZ 2
#define NCH 16
#define CHL 128
#define NTOK 4096

// ---------------- scratch ----------------
__device__ float g_xz[BSZ * E2 * L_SEQ];
__device__ float g_xc[2][BSZ * D_INNER * L_SEQ];
__device__ float g_xdbl[2][BSZ * XD * L_SEQ];
__device__ float g_dt[2][BSZ * D_INNER * L_SEQ];
__device__ float g_hfin[2 * BSZ * D_INNER * NCH * DS];
__device__ float g_P[2 * BSZ * D_INNER * NCH * DS];
__device__ float g_Hinit[2 * BSZ * D_INNER * NCH * DS];
__device__ float g_acc[2][BSZ * D_INNER * L_SEQ];

// fp16 operands
__device__ uint32_t g_WinP[E2 * D_MODEL];
__device__ uint16_t g_hidH[NTOK * D_MODEL];
__device__ uint16_t g_WoutH[D_MODEL * D_INNER];
__device__ uint32_t g_midP[NTOK * D_INNER];
__device__ uint32_t g_WxP[2][128 * D_INNER];        // W_x padded 80->128 rows, packed hi/lo
__device__ uint32_t g_WdtP[2][D_INNER * 64];        // W_dt padded K 48->64, packed hi/lo
__device__ uint16_t g_xcT[2][NTOK * D_INNER];       // conv output, [token][d] fp16
__device__ uint16_t g_dtloT[2][NTOK * 64];          // dt_lo transposed, [token][64] fp16

__device__ __forceinline__ float siluf(float v) {
    return v * (1.f / (1.f + __expf(-v)));
}
__device__ __forceinline__ float softplusf(float v) {
    return v > 15.f ? v : log1pf(__expf(v));
}
__device__ __forceinline__ uint32_t pack2h(float x) {
    __half h = __float2half(x);
    __half l = __float2half(x - __half2float(h));
    return (uint32_t)__half_as_ushort(h) | ((uint32_t)__half_as_ushort(l) << 16);
}

// ---------------- pack kernels ----------------
__global__ __launch_bounds__(256) void k_packu32(const float4* __restrict__ s, uint4* __restrict__ d, int n4) {
    int i = blockIdx.x * blockDim.x + threadIdx.x;
    if (i < n4) {
        float4 v = s[i];
        d[i] = make_uint4(pack2h(v.x), pack2h(v.y), pack2h(v.z), pack2h(v.w));
    }
}
__global__ __launch_bounds__(256) void k_packh(const float4* __restrict__ s, ushort4* __restrict__ d, int n4) {
    int i = blockIdx.x * blockDim.x + threadIdx.x;
    if (i < n4) {
        float4 v = s[i];
        ushort4 o;
        o.x = __half_as_ushort(__float2half(v.x));
        o.y = __half_as_ushort(__float2half(v.y));
        o.z = __half_as_ushort(__float2half(v.z));
        o.w = __half_as_ushort(__float2half(v.w));
        d[i] = o;
    }
}
// W_x (80,1536) -> padded (128,1536) packed
__global__ __launch_bounds__(256) void k_packWx(const float* __restrict__ Wx, const float* __restrict__ Wxb) {
    int id = blockIdx.x * blockDim.x + threadIdx.x;
    if (id >= 2 * 128 * D_INNER) return;
    int br = id / (128 * D_INNER);
    int rem = id - br * 128 * D_INNER;
    int m = rem / D_INNER, k = rem - m * D_INNER;
    const float* W = br ? Wxb : Wx;
    g_WxP[br][rem] = (m < XD) ? pack2h(W[m * D_INNER + k]) : 0u;
}
// W_dt (1536,48) -> (1536,64) packed
__global__ __launch_bounds__(256) void k_packWdt(const float* __restrict__ Wdt, const float* __restrict__ Wdtb) {
    int id = blockIdx.x * blockDim.x + threadIdx.x;
    if (id >= 2 * D_INNER * 64) return;
    int br = id / (D_INNER * 64);
    int rem = id - br * D_INNER * 64;
    int m = rem >> 6, k = rem & 63;
    const float* W = br ? Wdtb : Wdt;
    g_WdtP[br][rem] = (k < DR) ? pack2h(W[m * DR + k]) : 0u;
}

// ---------------- mid transpose + combine + pack ----------------
__global__ __launch_bounds__(256) void k_midT() {
    __shared__ float t[32][33];
    int b = blockIdx.z;
    int l0 = blockIdx.x * 32, d0 = blockIdx.y * 32;
    int tx = threadIdx.x, ty = threadIdx.y;
    const float* F = g_acc[0] + (size_t)b * D_INNER * L_SEQ;
    const float* Bk = g_acc[1] + (size_t)b * D_INNER * L_SEQ;
#pragma unroll
    for (int i = 0; i < 4; i++) {
        int d = d0 + ty + i * 8;
        float f = F[(size_t)d * L_SEQ + l0 + tx];
        float r = Bk[(size_t)d * L_SEQ + (L_SEQ - 1) - (l0 + tx)];
        t[ty + i * 8][tx] = 0.5f * (f + r);
    }
    __syncthreads();
#pragma unroll
    for (int i = 0; i < 4; i++) {
        int l = l0 + ty + i * 8;
        g_midP[((size_t)(b * L_SEQ) + l) * D_INNER + d0 + tx] = pack2h(t[tx][ty + i * 8]);
    }
}

// ---------------- tensor-core GEMM: fp16 2-pass (Ah*Bh + Al*Bh) ----------------
#define LDSM4(R, addr) \
    asm volatile("ldmatrix.sync.aligned.m8n8.x4.shared.b16 {%0,%1,%2,%3},[%4];" \
                 : "=r"(R[0]), "=r"(R[1]), "=r"(R[2]), "=r"(R[3]) : "r"(addr))

#define MMA16816(c, a, b0_, b1_) \
    asm volatile("mma.sync.aligned.m16n8k16.row.col.f32.f16.f16.f32 " \
                 "{%0,%1,%2,%3},{%4,%5,%6,%7},{%8,%9},{%0,%1,%2,%3};" \
                 : "+f"(c[0]), "+f"(c[1]), "+f"(c[2]), "+f"(c[3]) \
                 : "r"(a[0]), "r"(a[1]), "r"(a[2]), "r"(a[3]), "r"(b0_), "r"(b1_))

#define PK_HI(u, v) __byte_perm(u, v, 0x5410)
#define PK_LO(u, v) __byte_perm(u, v, 0x7632)

// Shared mainloop body as a macro-free pattern: each kernel repeats the loop.
// CTA tile 128x128, warps 2x4 (warp tile 64x32).

#define GEMM_DECL_SMEM() \
    __shared__ __align__(16) uint16_t Ash[2][2][128][24]; \
    __shared__ __align__(16) uint16_t Bsh[2][128][24]

#define GEMM_THREAD_IDS() \
    const int tid = threadIdx.x; \
    const int lane = tid & 31, wid = tid >> 5; \
    const int wm = wid >> 2, wn = wid & 3; \
    const int ar = tid >> 2, akq = (tid & 3) * 4; \
    const int brrow = tid >> 1, bseg = tid & 1

#define GEMM_ACC_INIT() \
    float acc[4][4][4]; \
    _Pragma("unroll") for (int i = 0; i < 4; i++) \
    _Pragma("unroll") for (int j = 0; j < 4; j++) \
    _Pragma("unroll") for (int q = 0; q < 4; q++) acc[i][j][q] = 0.f

#define GEMM_MAINLOOP(pA0, pA1, pB, NK) \
    uint4 ra0, ra1, rb; \
    ra0 = *(const uint4*)(pA0); \
    ra1 = *(const uint4*)(pA1); \
    rb  = *(const uint4*)(pB); \
    *(uint2*)&Ash[0][0][ar][akq]      = make_uint2(PK_HI(ra0.x, ra0.y), PK_HI(ra0.z, ra0.w)); \
    *(uint2*)&Ash[0][1][ar][akq]      = make_uint2(PK_LO(ra0.x, ra0.y), PK_LO(ra0.z, ra0.w)); \
    *(uint2*)&Ash[0][0][ar + 64][akq] = make_uint2(PK_HI(ra1.x, ra1.y), PK_HI(ra1.z, ra1.w)); \
    *(uint2*)&Ash[0][1][ar + 64][akq] = make_uint2(PK_LO(ra1.x, ra1.y), PK_LO(ra1.z, ra1.w)); \
    *(uint4*)&Bsh[0][brrow][bseg * 8] = rb; \
    __syncthreads(); \
    const int lr = lane & 15, lc = lane >> 4; \
    const int brow = wn * 32 + (lane & 7) + ((lane >> 3) & 1) * 8; \
    int buf = 0; \
    for (int kt = 0; kt < (NK); ++kt) { \
        if (kt + 1 < (NK)) { \
            ra0 = *(const uint4*)((pA0) + (kt + 1) * 16); \
            ra1 = *(const uint4*)((pA1) + (kt + 1) * 16); \
            rb  = *(const uint4*)((pB) + (kt + 1) * 16); \
        } \
        uint32_t ah[4][4], al[4][4], bh[2][4]; \
        { \
            uint32_t aH = (uint32_t)__cvta_generic_to_shared(&Ash[buf][0][wm * 64 + lr][0]) + lc * 16; \
            uint32_t aL = (uint32_t)__cvta_generic_to_shared(&Ash[buf][1][wm * 64 + lr][0]) + lc * 16; \
            _Pragma("unroll") for (int mt = 0; mt < 4; mt++) { \
                LDSM4(ah[mt], aH + mt * 16 * 48); \
                LDSM4(al[mt], aL + mt * 16 * 48); \
            } \
            uint32_t bH = (uint32_t)__cvta_generic_to_shared(&Bsh[buf][brow][0]) + lc * 16; \
            _Pragma("unroll") for (int np = 0; np < 2; np++) { \
                LDSM4(bh[np], bH + np * 16 * 48); \
            } \
        } \
        _Pragma("unroll") for (int mt = 0; mt < 4; mt++) { \
            _Pragma("unroll") for (int nt = 0; nt < 4; nt++) { \
                const int np = nt >> 1, sel = nt & 1; \
                MMA16816(acc[mt][nt], ah[mt], bh[np][sel], bh[np][sel + 2]); \
                MMA16816(acc[mt][nt], al[mt], bh[np][sel], bh[np][sel + 2]); \
            } \
        } \
        if (kt + 1 < (NK)) { \
            buf ^= 1; \
            *(uint2*)&Ash[buf][0][ar][akq]      = make_uint2(PK_HI(ra0.x, ra0.y), PK_HI(ra0.z, ra0.w)); \
            *(uint2*)&Ash[buf][1][ar][akq]      = make_uint2(PK_LO(ra0.x, ra0.y), PK_LO(ra0.z, ra0.w)); \
            *(uint2*)&Ash[buf][0][ar + 64][akq] = make_uint2(PK_HI(ra1.x, ra1.y), PK_HI(ra1.z, ra1.w)); \
            *(uint2*)&Ash[buf][1][ar + 64][akq] = make_uint2(PK_LO(ra1.x, ra1.y), PK_LO(ra1.z, ra1.w)); \
            *(uint4*)&Bsh[buf][brrow][bseg * 8] = rb; \
            __syncthreads(); \
        } \
    }

// MODE 0: C[(bb*E2+m)*L + l]   MODE 1: C[m*768 + n]
template <int MODE>
__global__ __launch_bounds__(256) void k_mma(const uint32_t* __restrict__ Ag,
                                             const uint16_t* __restrict__ Bg,
                                             float* __restrict__ Cg, int K) {
    GEMM_DECL_SMEM();
    GEMM_THREAD_IDS();
    const int m0 = blockIdx.y * 128, n0 = blockIdx.x * 128;
    const uint32_t* pA0 = Ag + (size_t)(m0 + ar) * K + akq;
    const uint32_t* pA1 = pA0 + (size_t)64 * K;
    const uint16_t* pB = Bg + (size_t)(n0 + brrow) * K + bseg * 8;
    const int NK = K >> 4;
    GEMM_ACC_INIT();
    GEMM_MAINLOOP(pA0, pA1, pB, NK);

    float* Cbase;
    int ldc;
    if (MODE == 0) {
        const int bb = n0 >> 11;
        const int l0c = n0 & (L_SEQ - 1);
        Cbase = Cg + ((size_t)bb * E2 + m0) * L_SEQ + l0c;
        ldc = L_SEQ;
    } else {
        Cbase = Cg + (size_t)m0 * D_MODEL + n0;
        ldc = D_MODEL;
    }
#pragma unroll
    for (int mt = 0; mt < 4; mt++) {
        int row = wm * 64 + mt * 16 + (lane >> 2);
#pragma unroll
        for (int nt = 0; nt < 4; nt++) {
            int col = wn * 32 + nt * 8 + (lane & 3) * 2;
            *(float2*)(Cbase + (size_t)row * ldc + col) = make_float2(acc[mt][nt][0], acc[mt][nt][1]);
            *(float2*)(Cbase + (size_t)(row + 8) * ldc + col) = make_float2(acc[mt][nt][2], acc[mt][nt][3]);
        }
    }
}

// x_dbl GEMM: A = WxP[br] (128 x 1536 packed), B = xcT[br] (4096 x 1536 fp16), split-K 3, atomic epilogue
__global__ __launch_bounds__(256) void k_gx() {
    GEMM_DECL_SMEM();
    GEMM_THREAD_IDS();
    const int z = blockIdx.z;
    const int br = z / 3, ks = z - br * 3;
    const int k0 = ks * 512;
    const int K = D_INNER;
    const uint32_t* Ag = g_WxP[br];
    const uint16_t* Bg = g_xcT[br];
    const int n0 = blockIdx.x * 128;
    const uint32_t* pA0 = Ag + (size_t)ar * K + k0 + akq;
    const uint32_t* pA1 = pA0 + (size_t)64 * K;
    const uint16_t* pB = Bg + (size_t)(n0 + brrow) * K + k0 + bseg * 8;
    const int NK = 32;
    GEMM_ACC_INIT();
    GEMM_MAINLOOP(pA0, pA1, pB, NK);

    const int b = n0 >> 11;
    const int l0c = n0 & (L_SEQ - 1);
    float* xd = g_xdbl[br] + ((size_t)b * XD) * L_SEQ + l0c;
#pragma unroll
    for (int mt = 0; mt < 4; mt++) {
        int row = wm * 64 + mt * 16 + (lane >> 2);
#pragma unroll
        for (int nt = 0; nt < 4; nt++) {
            int col = wn * 32 + nt * 8 + (lane & 3) * 2;
            if (row < XD) {
                atomicAdd(xd + (size_t)row * L_SEQ + col, acc[mt][nt][0]);
                atomicAdd(xd + (size_t)row * L_SEQ + col + 1, acc[mt][nt][1]);
            }
            if (row + 8 < XD) {
                atomicAdd(xd + (size_t)(row + 8) * L_SEQ + col, acc[mt][nt][2]);
                atomicAdd(xd + (size_t)(row + 8) * L_SEQ + col + 1, acc[mt][nt][3]);
            }
        }
    }
}

// dt GEMM: A = WdtP[br] (1536 x 64 packed), B = dtloT[br] (4096 x 64 fp16), softplus epilogue
__global__ __launch_bounds__(256) void k_gdt(const float* __restrict__ bdt,
                                             const float* __restrict__ bdtb) {
    GEMM_DECL_SMEM();
    GEMM_THREAD_IDS();
    const int br = blockIdx.z;
    const int K = 64;
    const uint32_t* Ag = g_WdtP[br];
    const uint16_t* Bg = g_dtloT[br];
    const float* bias = br ? bdtb : bdt;
    const int m0 = blockIdx.y * 128, n0 = blockIdx.x * 128;
    const uint32_t* pA0 = Ag + (size_t)(m0 + ar) * K + akq;
    const uint32_t* pA1 = pA0 + (size_t)64 * K;
    const uint16_t* pB = Bg + (size_t)(n0 + brrow) * K + bseg * 8;
    const int NK = 4;
    GEMM_ACC_INIT();
    GEMM_MAINLOOP(pA0, pA1, pB, NK);

    const int b = n0 >> 11;
    const int l0c = n0 & (L_SEQ - 1);
    float* dst = g_dt[br] + ((size_t)b * D_INNER) * L_SEQ + l0c;
#pragma unroll
    for (int mt = 0; mt < 4; mt++) {
        int row = wm * 64 + mt * 16 + (lane >> 2);
        int d1 = m0 + row, d2 = d1 + 8;
        float b1 = bias[d1], b2 = bias[d2];
#pragma unroll
        for (int nt = 0; nt < 4; nt++) {
            int col = wn * 32 + nt * 8 + (lane & 3) * 2;
            *(float2*)(dst + (size_t)d1 * L_SEQ + col) =
                make_float2(softplusf(acc[mt][nt][0] + b1), softplusf(acc[mt][nt][1] + b1));
            *(float2*)(dst + (size_t)d2 * L_SEQ + col) =
                make_float2(softplusf(acc[mt][nt][2] + b2), softplusf(acc[mt][nt][3] + b2));
        }
    }
}

// ---------------- conv: 32d x 32l tiles, writes fp32 [d][l] + fp16 transposed [token][d] ----------------
__global__ __launch_bounds__(256) void k_conv(const float* __restrict__ cw, const float* __restrict__ cb,
                                              const float* __restrict__ cwb, const float* __restrict__ cbb) {
    __shared__ float xs[32][40];
    __shared__ uint16_t t0[32][33];
    __shared__ uint16_t t1[32][33];
    const int tx = threadIdx.x, ty = threadIdx.y;
    const int tid = ty * 32 + tx;
    const int l0 = blockIdx.x * 32, d0 = blockIdx.y * 32;
    const int b = blockIdx.z;

    for (int lin = tid; lin < 32 * 38; lin += 256) {
        int dd = lin / 38, ll = lin - dd * 38;
        int l = l0 - 3 + ll;
        xs[dd][ll] = (l >= 0 && l < L_SEQ) ? g_xz[((size_t)b * E2 + d0 + dd) * L_SEQ + l] : 0.f;
    }
    __syncthreads();

#pragma unroll
    for (int i = 0; i < 4; i++) {
        int dd = ty + i * 8;
        int d = d0 + dd;
        float wf0 = cw[d * 4 + 0], wf1 = cw[d * 4 + 1], wf2 = cw[d * 4 + 2], wf3 = cw[d * 4 + 3];
        float wb0 = cwb[d * 4 + 0], wb1 = cwb[d * 4 + 1], wb2 = cwb[d * 4 + 2], wb3 = cwb[d * 4 + 3];
        float sf = cb[d] + wf0 * xs[dd][tx] + wf1 * xs[dd][tx + 1] + wf2 * xs[dd][tx + 2] + wf3 * xs[dd][tx + 3];
        float sb = cbb[d] + wb0 * xs[dd][tx + 6] + wb1 * xs[dd][tx + 5] + wb2 * xs[dd][tx + 4] + wb3 * xs[dd][tx + 3];
        float vf = siluf(sf), vb = siluf(sb);
        g_xc[0][((size_t)b * D_INNER + d) * L_SEQ + l0 + tx] = vf;
        g_xc[1][((size_t)b * D_INNER + d) * L_SEQ + (L_SEQ - 1 - l0 - tx)] = vb;
        t0[tx][dd] = __half_as_ushort(__float2half(vf));
        t1[tx][dd] = __half_as_ushort(__float2half(vb));
    }
    __syncthreads();

#pragma unroll
    for (int i = 0; i < 4; i++) {
        int lrow = ty + i * 8;
        g_xcT[0][((size_t)b * L_SEQ + l0 + lrow) * D_INNER + d0 + tx] = t0[lrow][tx];
        g_xcT[1][((size_t)b * L_SEQ + (L_SEQ - 1 - l0 - lrow)) * D_INNER + d0 + tx] = t1[lrow][tx];
    }
}

// ---------------- zero g_xdbl ----------------
__global__ __launch_bounds__(256) void k_zero(float4* p, int n4) {
    int i = blockIdx.x * blockDim.x + threadIdx.x;
    if (i < n4) p[i] = make_float4(0.f, 0.f, 0.f, 0.f);
}

// ---------------- dt_lo transpose: g_xdbl rows 0..47 -> [token][64] fp16 ----------------
__global__ __launch_bounds__(256) void k_dtloT() {
    __shared__ float s[48][65];
    const int tid = threadIdx.x;
    const int l0 = blockIdx.x * 64;
    const int b = blockIdx.y;
    const int br = blockIdx.z;
    const float* xd = g_xdbl[br] + ((size_t)b * XD) * L_SEQ;
    for (int lin = tid; lin < 48 * 64; lin += 256) {
        int r = lin >> 6, ll = lin & 63;
        s[r][ll] = xd[(size_t)r * L_SEQ + l0 + ll];
    }
    __syncthreads();
    uint16_t* dst = g_dtloT[br] + ((size_t)b * L_SEQ + l0) * 64;
    for (int lin = tid; lin < 64 * 64; lin += 256) {
        int ll = lin >> 6, r = lin & 63;
        dst[(size_t)ll * 64 + r] = (r < DR) ? __half_as_ushort(__float2half(s[r][ll])) : (uint16_t)0;
    }
}

// ---------------- scan pass 1 ----------------
__global__ __launch_bounds__(128) void k_scan1(const float* __restrict__ Alog, const float* __restrict__ Alogb) {
    const int tid = threadIdx.x;
    const int d = blockIdx.x * 128 + tid;
    const int chunk = blockIdx.y;
    const int zb = blockIdx.z;
    const int br = zb >> 1, b = zb & 1;
    const float* Al = br ? Alogb : Alog;
    float a[DS];
    int fast = 1;
#pragma unroll
    for (int n = 0; n < DS; n++) {
        a[n] = -expf(Al[d * DS + n]);
        fast &= (fabsf(a[n] + (float)(n + 1)) < 1e-4f * (float)(n + 1));
    }

    __shared__ float Bsh[CHL][DS + 1];
    const int l0 = chunk * CHL;
    const float* xd = g_xdbl[br] + (b * XD) * L_SEQ;
    for (int i = tid; i < CHL * DS; i += 128) {
        int n = i >> 7, t = i & (CHL - 1);
        Bsh[t][n] = xd[(DR + n) * L_SEQ + l0 + t];
    }
    __syncthreads();

    const float* dtp = g_dt[br] + (b * D_INNER + d) * L_SEQ + l0;
    const float* xp = g_xc[br] + (b * D_INNER + d) * L_SEQ + l0;
    float h[DS];
    float S = 0.f;
#pragma unroll
    for (int n = 0; n < DS; n++) h[n] = 0.f;

    if (fast) {
#pragma unroll 2
        for (int t = 0; t < CHL; t++) {
            float dt = dtp[t], x = xp[t];
            float dtx = dt * x;
            float r = __expf(-dt);
            S += dt;
            float p = 1.f;
#pragma unroll
            for (int n = 0; n < DS; n++) {
                p *= r;
                h[n] = fmaf(p, h[n], dtx * Bsh[t][n]);
            }
        }
    } else {
#pragma unroll 2
        for (int t = 0; t < CHL; t++) {
            float dt = dtp[t], x = xp[t];
            float dtx = dt * x;
            S += dt;
#pragma unroll
            for (int n = 0; n < DS; n++) {
                float dA = __expf(dt * a[n]);
                h[n] = fmaf(dA, h[n], dtx * Bsh[t][n]);
            }
        }
    }
    size_t base = ((size_t)(zb * D_INNER + d) * NCH + chunk) * DS;
#pragma unroll
    for (int n = 0; n < DS; n++) {
        g_hfin[base + n] = h[n];
        g_P[base + n] = __expf(a[n] * S);
    }
}

// ---------------- scan pass 2 ----------------
__global__ void k_scan2() {
    int id = blockIdx.x * blockDim.x + threadIdx.x;
    if (id >= 2 * BSZ * D_INNER * DS) return;
    int n = id & 15;
    int rest = id >> 4;
    int d = rest % D_INNER;
    int zb = rest / D_INNER;
    size_t base = ((size_t)(zb * D_INNER + d)) * (NCH * DS) + n;
    float H = 0.f;
#pragma unroll
    for (int c = 0; c < NCH; c++) {
        g_Hinit[base + c * DS] = H;
        H = g_P[base + c * DS] * H + g_hfin[base + c * DS];
    }
}

// ---------------- scan pass 3 ----------------
__global__ __launch_bounds__(128) void k_scan3(const float* __restrict__ Alog, const float* __restrict__ Alogb,
                                               const float* __restrict__ Dp, const float* __restrict__ Dpb) {
    const int tid = threadIdx.x;
    const int d = blockIdx.x * 128 + tid;
    const int chunk = blockIdx.y;
    const int zb = blockIdx.z;
    const int br = zb >> 1, b = zb & 1;
    const float* Al = br ? Alogb : Alog;
    float a[DS];
    int fast = 1;
#pragma unroll
    for (int n = 0; n < DS; n++) {
        a[n] = -expf(Al[d * DS + n]);
        fast &= (fabsf(a[n] + (float)(n + 1)) < 1e-4f * (float)(n + 1));
    }

    __shared__ float Bsh[CHL][DS + 1];
    __shared__ float Csh[CHL][DS + 1];
    const int l0 = chunk * CHL;
    const float* xd = g_xdbl[br] + (b * XD) * L_SEQ;
    for (int i = tid; i < CHL * DS; i += 128) {
        int n = i >> 7, t = i & (CHL - 1);
        Bsh[t][n] = xd[(DR + n) * L_SEQ + l0 + t];
        Csh[t][n] = xd[(DR + DS + n) * L_SEQ + l0 + t];
    }
    __syncthreads();

    size_t sbase = ((size_t)(zb * D_INNER + d) * NCH + chunk) * DS;
    float h[DS];
#pragma unroll
    for (int n = 0; n < DS; n++) h[n] = g_Hinit[sbase + n];
    float Dd = (br ? Dpb : Dp)[d];

    const float* dtp = g_dt[br] + (b * D_INNER + d) * L_SEQ + l0;
    const float* xp = g_xc[br] + (b * D_INNER + d) * L_SEQ + l0;
    const float* zp = g_xz + (b * E2 + D_INNER + d) * L_SEQ;
    float* op = g_acc[br] + (b * D_INNER + d) * L_SEQ + l0;

    if (fast) {
#pragma unroll 2
        for (int t = 0; t < CHL; t++) {
            float dt = dtp[t], x = xp[t];
            float dtx = dt * x;
            float r = __expf(-dt);
            float p = 1.f;
            float y = 0.f;
#pragma unroll
            for (int n = 0; n < DS; n++) {
                p *= r;
                h[n] = fmaf(p, h[n], dtx * Bsh[t][n]);
                y = fmaf(h[n], Csh[t][n], y);
            }
            int l = l0 + t;
            float zv = br ? zp[(L_SEQ - 1) - l] : zp[l];
            op[t] = (y + Dd * x) * siluf(zv);
        }
    } else {
#pragma unroll 2
        for (int t = 0; t < CHL; t++) {
            float dt = dtp[t], x = xp[t];
            float dtx = dt * x;
            float y = 0.f;
#pragma unroll
            for (int n = 0; n < DS; n++) {
                float dA = __expf(dt * a[n]);
                h[n] = fmaf(dA, h[n], dtx * Bsh[t][n]);
                y = fmaf(h[n], Csh[t][n], y);
            }
            int l = l0 + t;
            float zv = br ? zp[(L_SEQ - 1) - l] : zp[l];
            op[t] = (y + Dd * x) * siluf(zv);
        }
    }
}

// ---------------- launch ----------------
extern "C" void kernel_launch(void* const* d_in, const int* in_sizes, int n_in,
                              void* d_out, int out_size) {
    const float* hid  = (const float*)d_in[0];
    const float* Win  = (const float*)d_in[1];
    const float* cw   = (const float*)d_in[2];
    const float* cb   = (const float*)d_in[3];
    const float* cwb  = (const float*)d_in[4];
    const float* cbb  = (const float*)d_in[5];
    const float* Wx   = (const float*)d_in[6];
    const float* Wxb  = (const float*)d_in[7];
    const float* Wdt  = (const float*)d_in[8];
    const float* bdt  = (const float*)d_in[9];
    const float* Wdtb = (const float*)d_in[10];
    const float* bdtb = (const float*)d_in[11];
    const float* Alog = (const float*)d_in[12];
    const float* Alogb= (const float*)d_in[13];
    const float* Dp   = (const float*)d_in[14];
    const float* Dpb  = (const float*)d_in[15];
    const float* Wout = (const float*)d_in[16];
    float* out = (float*)d_out;

    uint32_t *WinP, *midP;
    uint16_t *hidH, *WoutH;
    float *xzP, *xdblP;
    cudaGetSymbolAddress((void**)&WinP, g_WinP);
    cudaGetSymbolAddress((void**)&hidH, g_hidH);
    cudaGetSymbolAddress((void**)&WoutH, g_WoutH);
    cudaGetSymbolAddress((void**)&midP, g_midP);
    cudaGetSymbolAddress((void**)&xzP, g_xz);
    cudaGetSymbolAddress((void**)&xdblP, g_xdbl);

    k_packu32<<<(E2 * D_MODEL / 4 + 255) / 256, 256>>>((const float4*)Win, (uint4*)WinP, E2 * D_MODEL / 4);
    k_packh<<<(NTOK * D_MODEL / 4 + 255) / 256, 256>>>((const float4*)hid, (ushort4*)hidH, NTOK * D_MODEL / 4);
    k_packh<<<(D_MODEL * D_INNER / 4 + 255) / 256, 256>>>((const float4*)Wout, (ushort4*)WoutH, D_MODEL * D_INNER / 4);
    k_packWx<<<(2 * 128 * D_INNER + 255) / 256, 256>>>(Wx, Wxb);
    k_packWdt<<<(2 * D_INNER * 64 + 255) / 256, 256>>>(Wdt, Wdtb);

    // xz = Win @ hid^T
    k_mma<0><<<dim3(NTOK / 128, E2 / 128), 256>>>(WinP, hidH, xzP, D_MODEL);

    // conv + silu (+ fp16 transposed copy)
    k_conv<<<dim3(L_SEQ / 32, D_INNER / 32, BSZ), dim3(32, 8)>>>(cw, cb, cwb, cbb);

    // x_dbl = Wx @ xc (tensor, split-K atomic)
    k_zero<<<(2 * BSZ * XD * L_SEQ / 4 + 255) / 256, 256>>>((float4*)xdblP, 2 * BSZ * XD * L_SEQ / 4);
    k_gx<<<dim3(NTOK / 128, 1, 6), 256>>>();

    // dt = softplus(Wdt @ dt_lo + b)
    k_dtloT<<<dim3(L_SEQ / 64, BSZ, 2), 256>>>();
    k_gdt<<<dim3(NTOK / 128, D_INNER / 128, 2), 256>>>(bdt, bdtb);

    k_scan1<<<dim3(D_INNER / 128, NCH, 4), 128>>>(Alog, Alogb);
    k_scan2<<<(2 * BSZ * D_INNER * DS + 255) / 256, 256>>>();
    k_scan3<<<dim3(D_INNER / 128, NCH, 4), 128>>>(Alog, Alogb, Dp, Dpb);

    k_midT<<<dim3(L_SEQ / 32, D_INNER / 32, BSZ), dim3(32, 8)>>>();

    // out = mid @ Wout^T
    k_mma<1><<<dim3(D_MODEL / 128, NTOK / 128), 256>>>(midP, WoutH, out, D_INNER);
}

// round 11
// speedup vs baseline: 3.1310x; 1.4903x over previous
#include <cuda_runtime.h>
#include <cuda_fp16.h>
#include <math.h>
#include <stdint.h>

#define L_SEQ 2048
#define D_MODEL 768
#define D_INNER 1536
#define E2 3072
#define DS 16
#define DR 48
#define XD 80
#define BSZ 2
#define NCH 16
#define CHL 128
#define NTOK 4096

// ---------------- scratch ----------------
__device__ float g_xz[NTOK * E2];                   // [token][e]  (token = b*L + l)
__device__ float g_xcF[2][NTOK * D_INNER];          // conv+silu, token-major (br1 time-reversed)
__device__ float g_xdbl[2][BSZ * XD * L_SEQ];       // [br][b][k][l]  (l-major, staged loads only)
__device__ float g_dt[2][NTOK * D_INNER];           // token-major
__device__ float g_hfin[2 * BSZ * D_INNER * NCH * DS];
__device__ float g_P[2 * BSZ * D_INNER * NCH * DS];
__device__ float g_Hinit[2 * BSZ * D_INNER * NCH * DS];
__device__ float g_acc[2][NTOK * D_INNER];          // token-major

// fp16 operands
__device__ uint32_t g_hidP[NTOK * D_MODEL];         // packed hi/lo (A side, GEMM1)
__device__ uint16_t g_WinH[E2 * D_MODEL];           // fp16 plane (B side, GEMM1)
__device__ uint16_t g_WoutH[D_MODEL * D_INNER];     // fp16 plane (B side, GEMM2)
__device__ uint32_t g_midP[NTOK * D_INNER];         // packed (A side, GEMM2)
__device__ uint32_t g_WxP[2][128 * D_INNER];        // W_x padded 80->128 rows, packed (A side)
__device__ uint16_t g_WdtH[2][D_INNER * 64];        // W_dt padded K->64, fp16 plane (B side)
__device__ uint16_t g_xcT[2][NTOK * D_INNER];       // conv out fp16 token-major (B side gx)
__device__ uint32_t g_dtloP[2][NTOK * 64];          // dt_lo packed per-token (A side gdt)

__device__ __forceinline__ float siluf(float v) {
    return v * (1.f / (1.f + __expf(-v)));
}
__device__ __forceinline__ float softplusf(float v) {
    return v > 15.f ? v : log1pf(__expf(v));
}
__device__ __forceinline__ uint32_t pack2h(float x) {
    __half h = __float2half(x);
    __half l = __float2half(x - __half2float(h));
    return (uint32_t)__half_as_ushort(h) | ((uint32_t)__half_as_ushort(l) << 16);
}

// ---------------- pack kernels ----------------
__global__ __launch_bounds__(256) void k_packu32(const float4* __restrict__ s, uint4* __restrict__ d, int n4) {
    int i = blockIdx.x * blockDim.x + threadIdx.x;
    if (i < n4) {
        float4 v = s[i];
        d[i] = make_uint4(pack2h(v.x), pack2h(v.y), pack2h(v.z), pack2h(v.w));
    }
}
__global__ __launch_bounds__(256) void k_packh(const float4* __restrict__ s, ushort4* __restrict__ d, int n4) {
    int i = blockIdx.x * blockDim.x + threadIdx.x;
    if (i < n4) {
        float4 v = s[i];
        ushort4 o;
        o.x = __half_as_ushort(__float2half(v.x));
        o.y = __half_as_ushort(__float2half(v.y));
        o.z = __half_as_ushort(__float2half(v.z));
        o.w = __half_as_ushort(__float2half(v.w));
        d[i] = o;
    }
}
__global__ __launch_bounds__(256) void k_packWx(const float* __restrict__ Wx, const float* __restrict__ Wxb) {
    int id = blockIdx.x * blockDim.x + threadIdx.x;
    if (id >= 2 * 128 * D_INNER) return;
    int br = id / (128 * D_INNER);
    int rem = id - br * 128 * D_INNER;
    int m = rem / D_INNER, k = rem - m * D_INNER;
    const float* W = br ? Wxb : Wx;
    g_WxP[br][rem] = (m < XD) ? pack2h(W[m * D_INNER + k]) : 0u;
}
__global__ __launch_bounds__(256) void k_packWdt(const float* __restrict__ Wdt, const float* __restrict__ Wdtb) {
    int id = blockIdx.x * blockDim.x + threadIdx.x;
    if (id >= 2 * D_INNER * 64) return;
    int br = id / (D_INNER * 64);
    int rem = id - br * D_INNER * 64;
    int m = rem >> 6, k = rem & 63;
    const float* W = br ? Wdtb : Wdt;
    g_WdtH[br][rem] = (k < DR) ? __half_as_ushort(__float2half(W[m * DR + k])) : (uint16_t)0;
}

// ---------------- tensor-core GEMM: fp16 2-pass (Ah*Bh + Al*Bh) ----------------
#define LDSM4(R, addr) \
    asm volatile("ldmatrix.sync.aligned.m8n8.x4.shared.b16 {%0,%1,%2,%3},[%4];" \
                 : "=r"(R[0]), "=r"(R[1]), "=r"(R[2]), "=r"(R[3]) : "r"(addr))

#define MMA16816(c, a, b0_, b1_) \
    asm volatile("mma.sync.aligned.m16n8k16.row.col.f32.f16.f16.f32 " \
                 "{%0,%1,%2,%3},{%4,%5,%6,%7},{%8,%9},{%0,%1,%2,%3};" \
                 : "+f"(c[0]), "+f"(c[1]), "+f"(c[2]), "+f"(c[3]) \
                 : "r"(a[0]), "r"(a[1]), "r"(a[2]), "r"(a[3]), "r"(b0_), "r"(b1_))

#define PK_HI(u, v) __byte_perm(u, v, 0x5410)
#define PK_LO(u, v) __byte_perm(u, v, 0x7632)

#define GEMM_DECL_SMEM() \
    __shared__ __align__(16) uint16_t Ash[2][2][128][24]; \
    __shared__ __align__(16) uint16_t Bsh[2][128][24]

#define GEMM_THREAD_IDS() \
    const int tid = threadIdx.x; \
    const int lane = tid & 31, wid = tid >> 5; \
    const int wm = wid >> 2, wn = wid & 3; \
    const int ar = tid >> 2, akq = (tid & 3) * 4; \
    const int brrow = tid >> 1, bseg = tid & 1

#define GEMM_ACC_INIT() \
    float acc[4][4][4]; \
    _Pragma("unroll") for (int i = 0; i < 4; i++) \
    _Pragma("unroll") for (int j = 0; j < 4; j++) \
    _Pragma("unroll") for (int q = 0; q < 4; q++) acc[i][j][q] = 0.f

#define GEMM_MAINLOOP(pA0, pA1, pB, NK) \
    uint4 ra0, ra1, rb; \
    ra0 = *(const uint4*)(pA0); \
    ra1 = *(const uint4*)(pA1); \
    rb  = *(const uint4*)(pB); \
    *(uint2*)&Ash[0][0][ar][akq]      = make_uint2(PK_HI(ra0.x, ra0.y), PK_HI(ra0.z, ra0.w)); \
    *(uint2*)&Ash[0][1][ar][akq]      = make_uint2(PK_LO(ra0.x, ra0.y), PK_LO(ra0.z, ra0.w)); \
    *(uint2*)&Ash[0][0][ar + 64][akq] = make_uint2(PK_HI(ra1.x, ra1.y), PK_HI(ra1.z, ra1.w)); \
    *(uint2*)&Ash[0][1][ar + 64][akq] = make_uint2(PK_LO(ra1.x, ra1.y), PK_LO(ra1.z, ra1.w)); \
    *(uint4*)&Bsh[0][brrow][bseg * 8] = rb; \
    __syncthreads(); \
    const int lr = lane & 15, lc = lane >> 4; \
    const int brow = wn * 32 + (lane & 7) + ((lane >> 3) & 1) * 8; \
    int buf = 0; \
    for (int kt = 0; kt < (NK); ++kt) { \
        if (kt + 1 < (NK)) { \
            ra0 = *(const uint4*)((pA0) + (kt + 1) * 16); \
            ra1 = *(const uint4*)((pA1) + (kt + 1) * 16); \
            rb  = *(const uint4*)((pB) + (kt + 1) * 16); \
        } \
        uint32_t ah[4][4], al[4][4], bh[2][4]; \
        { \
            uint32_t aH = (uint32_t)__cvta_generic_to_shared(&Ash[buf][0][wm * 64 + lr][0]) + lc * 16; \
            uint32_t aL = (uint32_t)__cvta_generic_to_shared(&Ash[buf][1][wm * 64 + lr][0]) + lc * 16; \
            _Pragma("unroll") for (int mt = 0; mt < 4; mt++) { \
                LDSM4(ah[mt], aH + mt * 16 * 48); \
                LDSM4(al[mt], aL + mt * 16 * 48); \
            } \
            uint32_t bH = (uint32_t)__cvta_generic_to_shared(&Bsh[buf][brow][0]) + lc * 16; \
            _Pragma("unroll") for (int np = 0; np < 2; np++) { \
                LDSM4(bh[np], bH + np * 16 * 48); \
            } \
        } \
        _Pragma("unroll") for (int mt = 0; mt < 4; mt++) { \
            _Pragma("unroll") for (int nt = 0; nt < 4; nt++) { \
                const int np = nt >> 1, sel = nt & 1; \
                MMA16816(acc[mt][nt], ah[mt], bh[np][sel], bh[np][sel + 2]); \
                MMA16816(acc[mt][nt], al[mt], bh[np][sel], bh[np][sel + 2]); \
            } \
        } \
        if (kt + 1 < (NK)) { \
            buf ^= 1; \
            *(uint2*)&Ash[buf][0][ar][akq]      = make_uint2(PK_HI(ra0.x, ra0.y), PK_HI(ra0.z, ra0.w)); \
            *(uint2*)&Ash[buf][1][ar][akq]      = make_uint2(PK_LO(ra0.x, ra0.y), PK_LO(ra0.z, ra0.w)); \
            *(uint2*)&Ash[buf][0][ar + 64][akq] = make_uint2(PK_HI(ra1.x, ra1.y), PK_HI(ra1.z, ra1.w)); \
            *(uint2*)&Ash[buf][1][ar + 64][akq] = make_uint2(PK_LO(ra1.x, ra1.y), PK_LO(ra1.z, ra1.w)); \
            *(uint4*)&Bsh[buf][brrow][bseg * 8] = rb; \
            __syncthreads(); \
        } \
    }

// Row-major C: C[m0+row][n0+col], ldc given.  A rows = m (tokens for our uses).
__global__ __launch_bounds__(256) void k_mma(const uint32_t* __restrict__ Ag,
                                             const uint16_t* __restrict__ Bg,
                                             float* __restrict__ Cg, int K, int ldc) {
    GEMM_DECL_SMEM();
    GEMM_THREAD_IDS();
    const int m0 = blockIdx.y * 128, n0 = blockIdx.x * 128;
    const uint32_t* pA0 = Ag + (size_t)(m0 + ar) * K + akq;
    const uint32_t* pA1 = pA0 + (size_t)64 * K;
    const uint16_t* pB = Bg + (size_t)(n0 + brrow) * K + bseg * 8;
    const int NK = K >> 4;
    GEMM_ACC_INIT();
    GEMM_MAINLOOP(pA0, pA1, pB, NK);

    float* Cbase = Cg + (size_t)m0 * ldc + n0;
#pragma unroll
    for (int mt = 0; mt < 4; mt++) {
        int row = wm * 64 + mt * 16 + (lane >> 2);
#pragma unroll
        for (int nt = 0; nt < 4; nt++) {
            int col = wn * 32 + nt * 8 + (lane & 3) * 2;
            *(float2*)(Cbase + (size_t)row * ldc + col) = make_float2(acc[mt][nt][0], acc[mt][nt][1]);
            *(float2*)(Cbase + (size_t)(row + 8) * ldc + col) = make_float2(acc[mt][nt][2], acc[mt][nt][3]);
        }
    }
}

// x_dbl GEMM: A = WxP[br] (128 x 1536 packed), B = xcT[br] (4096 x 1536 fp16), split-K 3, atomic epilogue
__global__ __launch_bounds__(256) void k_gx() {
    GEMM_DECL_SMEM();
    GEMM_THREAD_IDS();
    const int z = blockIdx.z;
    const int br = z / 3, ks = z - br * 3;
    const int k0 = ks * 512;
    const int K = D_INNER;
    const uint32_t* Ag = g_WxP[br];
    const uint16_t* Bg = g_xcT[br];
    const int n0 = blockIdx.x * 128;
    const uint32_t* pA0 = Ag + (size_t)ar * K + k0 + akq;
    const uint32_t* pA1 = pA0 + (size_t)64 * K;
    const uint16_t* pB = Bg + (size_t)(n0 + brrow) * K + k0 + bseg * 8;
    const int NK = 32;
    GEMM_ACC_INIT();
    GEMM_MAINLOOP(pA0, pA1, pB, NK);

    const int b = n0 >> 11;
    const int l0c = n0 & (L_SEQ - 1);
    float* xd = g_xdbl[br] + ((size_t)b * XD) * L_SEQ + l0c;
#pragma unroll
    for (int mt = 0; mt < 4; mt++) {
        int row = wm * 64 + mt * 16 + (lane >> 2);
#pragma unroll
        for (int nt = 0; nt < 4; nt++) {
            int col = wn * 32 + nt * 8 + (lane & 3) * 2;
            if (row < XD) {
                atomicAdd(xd + (size_t)row * L_SEQ + col, acc[mt][nt][0]);
                atomicAdd(xd + (size_t)row * L_SEQ + col + 1, acc[mt][nt][1]);
            }
            if (row + 8 < XD) {
                atomicAdd(xd + (size_t)(row + 8) * L_SEQ + col, acc[mt][nt][2]);
                atomicAdd(xd + (size_t)(row + 8) * L_SEQ + col + 1, acc[mt][nt][3]);
            }
        }
    }
}

// dt GEMM: A = dtloP[br] (4096 tokens x 64 packed), B = WdtH[br] (1536 x 64 fp16)
// epilogue: g_dt[br][token][d] = softplus(acc + bias[d])  (token-major, coalesced)
__global__ __launch_bounds__(256) void k_gdt(const float* __restrict__ bdt,
                                             const float* __restrict__ bdtb) {
    GEMM_DECL_SMEM();
    GEMM_THREAD_IDS();
    const int br = blockIdx.z;
    const int K = 64;
    const uint32_t* Ag = g_dtloP[br];
    const uint16_t* Bg = g_WdtH[br];
    const float* bias = br ? bdtb : bdt;
    const int m0 = blockIdx.y * 128, n0 = blockIdx.x * 128;
    const uint32_t* pA0 = Ag + (size_t)(m0 + ar) * K + akq;
    const uint32_t* pA1 = pA0 + (size_t)64 * K;
    const uint16_t* pB = Bg + (size_t)(n0 + brrow) * K + bseg * 8;
    const int NK = 4;
    GEMM_ACC_INIT();
    GEMM_MAINLOOP(pA0, pA1, pB, NK);

    float* dst = g_dt[br] + (size_t)m0 * D_INNER + n0;
#pragma unroll
    for (int mt = 0; mt < 4; mt++) {
        int row = wm * 64 + mt * 16 + (lane >> 2);
#pragma unroll
        for (int nt = 0; nt < 4; nt++) {
            int col = wn * 32 + nt * 8 + (lane & 3) * 2;
            float b1 = bias[n0 + col], b2 = bias[n0 + col + 1];
            *(float2*)(dst + (size_t)row * D_INNER + col) =
                make_float2(softplusf(acc[mt][nt][0] + b1), softplusf(acc[mt][nt][1] + b2));
            *(float2*)(dst + (size_t)(row + 8) * D_INNER + col) =
                make_float2(softplusf(acc[mt][nt][2] + b1), softplusf(acc[mt][nt][3] + b2));
        }
    }
}

// ---------------- conv: token-major in/out, fully coalesced ----------------
__global__ __launch_bounds__(256) void k_conv(const float* __restrict__ cw, const float* __restrict__ cb,
                                              const float* __restrict__ cwb, const float* __restrict__ cbb) {
    __shared__ float xs[38][33];
    const int tx = threadIdx.x, ty = threadIdx.y;
    const int tid = ty * 32 + tx;
    const int l0 = blockIdx.x * 32, d0 = blockIdx.y * 32;
    const int b = blockIdx.z;

    for (int lin = tid; lin < 38 * 32; lin += 256) {
        int r = lin >> 5, c = lin & 31;
        int l = l0 - 3 + r;
        xs[r][c] = (l >= 0 && l < L_SEQ) ? g_xz[((size_t)b * L_SEQ + l) * E2 + d0 + c] : 0.f;
    }
    __syncthreads();

    const int d = d0 + tx;
    float wf0 = cw[d * 4 + 0], wf1 = cw[d * 4 + 1], wf2 = cw[d * 4 + 2], wf3 = cw[d * 4 + 3];
    float wb0 = cwb[d * 4 + 0], wb1 = cwb[d * 4 + 1], wb2 = cwb[d * 4 + 2], wb3 = cwb[d * 4 + 3];
    float bf = cb[d], bbk = cbb[d];

#pragma unroll
    for (int i = 0; i < 4; i++) {
        int ll = ty + i * 8;
        float sf = bf + wf0 * xs[ll][tx] + wf1 * xs[ll + 1][tx] + wf2 * xs[ll + 2][tx] + wf3 * xs[ll + 3][tx];
        float sb = bbk + wb0 * xs[ll + 6][tx] + wb1 * xs[ll + 5][tx] + wb2 * xs[ll + 4][tx] + wb3 * xs[ll + 3][tx];
        float vf = siluf(sf), vb = siluf(sb);
        size_t tf = (size_t)b * L_SEQ + l0 + ll;
        size_t tb = (size_t)b * L_SEQ + (L_SEQ - 1 - l0 - ll);
        g_xcF[0][tf * D_INNER + d] = vf;
        g_xcF[1][tb * D_INNER + d] = vb;
        g_xcT[0][tf * D_INNER + d] = __half_as_ushort(__float2half(vf));
        g_xcT[1][tb * D_INNER + d] = __half_as_ushort(__float2half(vb));
    }
}

// ---------------- zero g_xdbl ----------------
__global__ __launch_bounds__(256) void k_zero(float4* p, int n4) {
    int i = blockIdx.x * blockDim.x + threadIdx.x;
    if (i < n4) p[i] = make_float4(0.f, 0.f, 0.f, 0.f);
}

// ---------------- dt_lo transpose+pack: g_xdbl rows 0..47 -> [token][64] packed u32 ----------------
__global__ __launch_bounds__(256) void k_dtloT() {
    __shared__ float s[48][65];
    const int tid = threadIdx.x;
    const int l0 = blockIdx.x * 64;
    const int b = blockIdx.y;
    const int br = blockIdx.z;
    const float* xd = g_xdbl[br] + ((size_t)b * XD) * L_SEQ;
    for (int lin = tid; lin < 48 * 64; lin += 256) {
        int r = lin >> 6, ll = lin & 63;
        s[r][ll] = xd[(size_t)r * L_SEQ + l0 + ll];
    }
    __syncthreads();
    uint32_t* dst = g_dtloP[br] + ((size_t)b * L_SEQ + l0) * 64;
    for (int lin = tid; lin < 64 * 64; lin += 256) {
        int ll = lin >> 6, r = lin & 63;
        dst[(size_t)ll * 64 + r] = (r < DR) ? pack2h(s[r][ll]) : 0u;
    }
}

// ---------------- scan pass 1 (token-major loads) ----------------
__global__ __launch_bounds__(128) void k_scan1(const float* __restrict__ Alog, const float* __restrict__ Alogb) {
    const int tid = threadIdx.x;
    const int d = blockIdx.x * 128 + tid;
    const int chunk = blockIdx.y;
    const int zb = blockIdx.z;
    const int br = zb >> 1, b = zb & 1;
    const float* Al = br ? Alogb : Alog;
    float a[DS];
    int fast = 1;
#pragma unroll
    for (int n = 0; n < DS; n++) {
        a[n] = -expf(Al[d * DS + n]);
        fast &= (fabsf(a[n] + (float)(n + 1)) < 1e-4f * (float)(n + 1));
    }

    __shared__ float Bsh[CHL][DS + 1];
    const int l0 = chunk * CHL;
    const float* xd = g_xdbl[br] + (b * XD) * L_SEQ;
    for (int i = tid; i < CHL * DS; i += 128) {
        int n = i >> 7, t = i & (CHL - 1);
        Bsh[t][n] = xd[(DR + n) * L_SEQ + l0 + t];
    }
    __syncthreads();

    const float* dtp = g_dt[br] + ((size_t)b * L_SEQ + l0) * D_INNER + d;
    const float* xp = g_xcF[br] + ((size_t)b * L_SEQ + l0) * D_INNER + d;
    float h[DS];
    float S = 0.f;
#pragma unroll
    for (int n = 0; n < DS; n++) h[n] = 0.f;

    if (fast) {
#pragma unroll 2
        for (int t = 0; t < CHL; t++) {
            float dt = dtp[(size_t)t * D_INNER], x = xp[(size_t)t * D_INNER];
            float dtx = dt * x;
            float r = __expf(-dt);
            S += dt;
            float p = 1.f;
#pragma unroll
            for (int n = 0; n < DS; n++) {
                p *= r;
                h[n] = fmaf(p, h[n], dtx * Bsh[t][n]);
            }
        }
    } else {
#pragma unroll 2
        for (int t = 0; t < CHL; t++) {
            float dt = dtp[(size_t)t * D_INNER], x = xp[(size_t)t * D_INNER];
            float dtx = dt * x;
            S += dt;
#pragma unroll
            for (int n = 0; n < DS; n++) {
                float dA = __expf(dt * a[n]);
                h[n] = fmaf(dA, h[n], dtx * Bsh[t][n]);
            }
        }
    }
    size_t base = ((size_t)(zb * D_INNER + d) * NCH + chunk) * DS;
#pragma unroll
    for (int n = 0; n < DS; n++) {
        g_hfin[base + n] = h[n];
        g_P[base + n] = __expf(a[n] * S);
    }
}

// ---------------- scan pass 2 ----------------
__global__ void k_scan2() {
    int id = blockIdx.x * blockDim.x + threadIdx.x;
    if (id >= 2 * BSZ * D_INNER * DS) return;
    int n = id & 15;
    int rest = id >> 4;
    int d = rest % D_INNER;
    int zb = rest / D_INNER;
    size_t base = ((size_t)(zb * D_INNER + d)) * (NCH * DS) + n;
    float H = 0.f;
#pragma unroll
    for (int c = 0; c < NCH; c++) {
        g_Hinit[base + c * DS] = H;
        H = g_P[base + c * DS] * H + g_hfin[base + c * DS];
    }
}

// ---------------- scan pass 3 (token-major) ----------------
__global__ __launch_bounds__(128) void k_scan3(const float* __restrict__ Alog, const float* __restrict__ Alogb,
                                               const float* __restrict__ Dp, const float* __restrict__ Dpb) {
    const int tid = threadIdx.x;
    const int d = blockIdx.x * 128 + tid;
    const int chunk = blockIdx.y;
    const int zb = blockIdx.z;
    const int br = zb >> 1, b = zb & 1;
    const float* Al = br ? Alogb : Alog;
    float a[DS];
    int fast = 1;
#pragma unroll
    for (int n = 0; n < DS; n++) {
        a[n] = -expf(Al[d * DS + n]);
        fast &= (fabsf(a[n] + (float)(n + 1)) < 1e-4f * (float)(n + 1));
    }

    __shared__ float Bsh[CHL][DS + 1];
    __shared__ float Csh[CHL][DS + 1];
    const int l0 = chunk * CHL;
    const float* xd = g_xdbl[br] + (b * XD) * L_SEQ;
    for (int i = tid; i < CHL * DS; i += 128) {
        int n = i >> 7, t = i & (CHL - 1);
        Bsh[t][n] = xd[(DR + n) * L_SEQ + l0 + t];
        Csh[t][n] = xd[(DR + DS + n) * L_SEQ + l0 + t];
    }
    __syncthreads();

    size_t sbase = ((size_t)(zb * D_INNER + d) * NCH + chunk) * DS;
    float h[DS];
#pragma unroll
    for (int n = 0; n < DS; n++) h[n] = g_Hinit[sbase + n];
    float Dd = (br ? Dpb : Dp)[d];

    const float* dtp = g_dt[br] + ((size_t)b * L_SEQ + l0) * D_INNER + d;
    const float* xp = g_xcF[br] + ((size_t)b * L_SEQ + l0) * D_INNER + d;
    float* op = g_acc[br] + ((size_t)b * L_SEQ + l0) * D_INNER + d;
    // z: forward branch reads token l; backward branch (time-reversed) reads token L-1-l
    const float* zp;
    ptrdiff_t zstep;
    if (!br) {
        zp = g_xz + ((size_t)b * L_SEQ + l0) * E2 + D_INNER + d;
        zstep = E2;
    } else {
        zp = g_xz + ((size_t)b * L_SEQ + (L_SEQ - 1 - l0)) * E2 + D_INNER + d;
        zstep = -(ptrdiff_t)E2;
    }

    if (fast) {
#pragma unroll 2
        for (int t = 0; t < CHL; t++) {
            float dt = dtp[(size_t)t * D_INNER], x = xp[(size_t)t * D_INNER];
            float dtx = dt * x;
            float r = __expf(-dt);
            float p = 1.f;
            float y = 0.f;
#pragma unroll
            for (int n = 0; n < DS; n++) {
                p *= r;
                h[n] = fmaf(p, h[n], dtx * Bsh[t][n]);
                y = fmaf(h[n], Csh[t][n], y);
            }
            float zv = zp[(ptrdiff_t)t * zstep];
            op[(size_t)t * D_INNER] = (y + Dd * x) * siluf(zv);
        }
    } else {
#pragma unroll 2
        for (int t = 0; t < CHL; t++) {
            float dt = dtp[(size_t)t * D_INNER], x = xp[(size_t)t * D_INNER];
            float dtx = dt * x;
            float y = 0.f;
#pragma unroll
            for (int n = 0; n < DS; n++) {
                float dA = __expf(dt * a[n]);
                h[n] = fmaf(dA, h[n], dtx * Bsh[t][n]);
                y = fmaf(h[n], Csh[t][n], y);
            }
            float zv = zp[(ptrdiff_t)t * zstep];
            op[(size_t)t * D_INNER] = (y + Dd * x) * siluf(zv);
        }
    }
}

// ---------------- mid combine + pack (pure elementwise, token-major) ----------------
__global__ __launch_bounds__(256) void k_midT() {
    int i4 = blockIdx.x * blockDim.x + threadIdx.x;
    const int DV = D_INNER / 4;
    if (i4 >= NTOK * DV) return;
    int tok = i4 / DV;
    int d4 = i4 - tok * DV;
    int b = tok >> 11, l = tok & (L_SEQ - 1);
    int rtok = (b << 11) + (L_SEQ - 1 - l);
    float4 f = ((const float4*)g_acc[0])[i4];
    float4 r = ((const float4*)g_acc[1])[(size_t)rtok * DV + d4];
    uint4 o;
    o.x = pack2h(0.5f * (f.x + r.x));
    o.y = pack2h(0.5f * (f.y + r.y));
    o.z = pack2h(0.5f * (f.z + r.z));
    o.w = pack2h(0.5f * (f.w + r.w));
    ((uint4*)g_midP)[i4] = o;
}

// ---------------- launch ----------------
extern "C" void kernel_launch(void* const* d_in, const int* in_sizes, int n_in,
                              void* d_out, int out_size) {
    const float* hid  = (const float*)d_in[0];
    const float* Win  = (const float*)d_in[1];
    const float* cw   = (const float*)d_in[2];
    const float* cb   = (const float*)d_in[3];
    const float* cwb  = (const float*)d_in[4];
    const float* cbb  = (const float*)d_in[5];
    const float* Wx   = (const float*)d_in[6];
    const float* Wxb  = (const float*)d_in[7];
    const float* Wdt  = (const float*)d_in[8];
    const float* bdt  = (const float*)d_in[9];
    const float* Wdtb = (const float*)d_in[10];
    const float* bdtb = (const float*)d_in[11];
    const float* Alog = (const float*)d_in[12];
    const float* Alogb= (const float*)d_in[13];
    const float* Dp   = (const float*)d_in[14];
    const float* Dpb  = (const float*)d_in[15];
    const float* Wout = (const float*)d_in[16];
    float* out = (float*)d_out;

    uint32_t *hidP, *midP;
    uint16_t *WinH, *WoutH;
    float *xzP, *xdblP;
    cudaGetSymbolAddress((void**)&hidP, g_hidP);
    cudaGetSymbolAddress((void**)&WinH, g_WinH);
    cudaGetSymbolAddress((void**)&WoutH, g_WoutH);
    cudaGetSymbolAddress((void**)&midP, g_midP);
    cudaGetSymbolAddress((void**)&xzP, g_xz);
    cudaGetSymbolAddress((void**)&xdblP, g_xdbl);

    k_packu32<<<(NTOK * D_MODEL / 4 + 255) / 256, 256>>>((const float4*)hid, (uint4*)hidP, NTOK * D_MODEL / 4);
    k_packh<<<(E2 * D_MODEL / 4 + 255) / 256, 256>>>((const float4*)Win, (ushort4*)WinH, E2 * D_MODEL / 4);
    k_packh<<<(D_MODEL * D_INNER / 4 + 255) / 256, 256>>>((const float4*)Wout, (ushort4*)WoutH, D_MODEL * D_INNER / 4);
    k_packWx<<<(2 * 128 * D_INNER + 255) / 256, 256>>>(Wx, Wxb);
    k_packWdt<<<(2 * D_INNER * 64 + 255) / 256, 256>>>(Wdt, Wdtb);

    // xz[token][e] = hid @ Win^T : M=4096 tokens, N=3072, K=768
    k_mma<<<dim3(E2 / 128, NTOK / 128), 256>>>(hidP, WinH, xzP, D_MODEL, E2);

    // conv + silu, token-major outputs
    k_conv<<<dim3(L_SEQ / 32, D_INNER / 32, BSZ), dim3(32, 8)>>>(cw, cb, cwb, cbb);

    // x_dbl = Wx @ xc (tensor, split-K atomic)
    k_zero<<<(2 * BSZ * XD * L_SEQ / 4 + 255) / 256, 256>>>((float4*)xdblP, 2 * BSZ * XD * L_SEQ / 4);
    k_gx<<<dim3(NTOK / 128, 1, 6), 256>>>();

    // dt = softplus(dt_lo @ Wdt^T + b), token-major output
    k_dtloT<<<dim3(L_SEQ / 64, BSZ, 2), 256>>>();
    k_gdt<<<dim3(D_INNER / 128, NTOK / 128, 2), 256>>>(bdt, bdtb);

    k_scan1<<<dim3(D_INNER / 128, NCH, 4), 128>>>(Alog, Alogb);
    k_scan2<<<(2 * BSZ * D_INNER * DS + 255) / 256, 256>>>();
    k_scan3<<<dim3(D_INNER / 128, NCH, 4), 128>>>(Alog, Alogb, Dp, Dpb);

    k_midT<<<(NTOK * D_INNER / 4 + 255) / 256, 256>>>();

    // out = mid @ Wout^T : M=4096 tokens, N=768, K=1536
    k_mma<<<dim3(D_MODEL / 128, NTOK / 128), 256>>>(midP, WoutH, out, D_INNER, D_MODEL);
}

// round 12
// speedup vs baseline: 3.6774x; 1.1745x over previous
#include <cuda_runtime.h>
#include <cuda_fp16.h>
#include <math.h>
#include <stdint.h>

#define L_SEQ 2048
#define D_MODEL 768
#define D_INNER 1536
#define E2 3072
#define DS 16
#define DR 48
#define XD 80
#define BSZ 2
#define NCH 16
#define CHL 128
#define NTOK 4096

// ---------------- scratch ----------------
__device__ float g_xz[NTOK * E2];                   // [token][e]
__device__ float g_xdbl[2][BSZ * XD * L_SEQ];       // [br][b][k][l]
__device__ float g_dt[2][NTOK * D_INNER];           // token-major fp32
__device__ float g_hfin[2 * BSZ * D_INNER * NCH * DS];
__device__ float g_P[2 * BSZ * D_INNER * NCH * DS];
__device__ float g_Hinit[2 * BSZ * D_INNER * NCH * DS];
__device__ float g_acc[2][NTOK * D_INNER];          // token-major

// fp16 planes (single-pass GEMM operands)
__device__ uint16_t g_hidH[NTOK * D_MODEL];
__device__ uint16_t g_WinH[E2 * D_MODEL];
__device__ uint16_t g_WoutH[D_MODEL * D_INNER];
__device__ uint16_t g_midH[NTOK * D_INNER];
__device__ uint16_t g_WxH[2][128 * D_INNER];        // W_x padded 80->128 rows
__device__ uint16_t g_WdtH[2][D_INNER * 64];        // W_dt padded K->64
__device__ uint16_t g_xcT[2][NTOK * D_INNER];       // conv+silu out, token-major fp16
__device__ uint16_t g_dtloH[2][NTOK * 64];          // dt_lo per-token fp16

__device__ __forceinline__ float siluf(float v) {
    return v * (1.f / (1.f + __expf(-v)));
}
__device__ __forceinline__ float softplusf(float v) {
    return v > 15.f ? v : log1pf(__expf(v));
}
__device__ __forceinline__ uint16_t h16(float x) { return __half_as_ushort(__float2half(x)); }

// ---------------- pack kernels ----------------
__global__ __launch_bounds__(256) void k_packh(const float4* __restrict__ s, ushort4* __restrict__ d, int n4) {
    int i = blockIdx.x * blockDim.x + threadIdx.x;
    if (i < n4) {
        float4 v = s[i];
        ushort4 o;
        o.x = h16(v.x); o.y = h16(v.y); o.z = h16(v.z); o.w = h16(v.w);
        d[i] = o;
    }
}
__global__ __launch_bounds__(256) void k_packWx(const float* __restrict__ Wx, const float* __restrict__ Wxb) {
    int id = blockIdx.x * blockDim.x + threadIdx.x;
    if (id >= 2 * 128 * D_INNER) return;
    int br = id / (128 * D_INNER);
    int rem = id - br * 128 * D_INNER;
    int m = rem / D_INNER, k = rem - m * D_INNER;
    const float* W = br ? Wxb : Wx;
    g_WxH[br][rem] = (m < XD) ? h16(W[m * D_INNER + k]) : (uint16_t)0;
}
__global__ __launch_bounds__(256) void k_packWdt(const float* __restrict__ Wdt, const float* __restrict__ Wdtb) {
    int id = blockIdx.x * blockDim.x + threadIdx.x;
    if (id >= 2 * D_INNER * 64) return;
    int br = id / (D_INNER * 64);
    int rem = id - br * D_INNER * 64;
    int m = rem >> 6, k = rem & 63;
    const float* W = br ? Wdtb : Wdt;
    g_WdtH[br][rem] = (k < DR) ? h16(W[m * DR + k]) : (uint16_t)0;
}

// ---------------- tensor-core GEMM: single-pass fp16 ----------------
#define LDSM4(R, addr) \
    asm volatile("ldmatrix.sync.aligned.m8n8.x4.shared.b16 {%0,%1,%2,%3},[%4];" \
                 : "=r"(R[0]), "=r"(R[1]), "=r"(R[2]), "=r"(R[3]) : "r"(addr))

#define MMA16816(c, a, b0_, b1_) \
    asm volatile("mma.sync.aligned.m16n8k16.row.col.f32.f16.f16.f32 " \
                 "{%0,%1,%2,%3},{%4,%5,%6,%7},{%8,%9},{%0,%1,%2,%3};" \
                 : "+f"(c[0]), "+f"(c[1]), "+f"(c[2]), "+f"(c[3]) \
                 : "r"(a[0]), "r"(a[1]), "r"(a[2]), "r"(a[3]), "r"(b0_), "r"(b1_))

#define GEMM_DECL_SMEM() \
    __shared__ __align__(16) uint16_t Ash[2][128][24]; \
    __shared__ __align__(16) uint16_t Bsh[2][128][24]

#define GEMM_THREAD_IDS() \
    const int tid = threadIdx.x; \
    const int lane = tid & 31, wid = tid >> 5; \
    const int wm = wid >> 2, wn = wid & 3; \
    const int arow = tid >> 1, aseg = tid & 1

#define GEMM_ACC_INIT() \
    float acc[4][4][4]; \
    _Pragma("unroll") for (int i = 0; i < 4; i++) \
    _Pragma("unroll") for (int j = 0; j < 4; j++) \
    _Pragma("unroll") for (int q = 0; q < 4; q++) acc[i][j][q] = 0.f

#define GEMM_MAINLOOP(pA, pB, NK) \
    uint4 ra, rb; \
    ra = *(const uint4*)(pA); \
    rb = *(const uint4*)(pB); \
    *(uint4*)&Ash[0][arow][aseg * 8] = ra; \
    *(uint4*)&Bsh[0][arow][aseg * 8] = rb; \
    __syncthreads(); \
    const int lr = lane & 15, lc = lane >> 4; \
    const int brow = wn * 32 + (lane & 7) + ((lane >> 3) & 1) * 8; \
    int buf = 0; \
    for (int kt = 0; kt < (NK); ++kt) { \
        if (kt + 1 < (NK)) { \
            ra = *(const uint4*)((pA) + (kt + 1) * 16); \
            rb = *(const uint4*)((pB) + (kt + 1) * 16); \
        } \
        uint32_t ah[4][4], bh[2][4]; \
        { \
            uint32_t aB = (uint32_t)__cvta_generic_to_shared(&Ash[buf][wm * 64 + lr][0]) + lc * 16; \
            _Pragma("unroll") for (int mt = 0; mt < 4; mt++) { \
                LDSM4(ah[mt], aB + mt * 16 * 48); \
            } \
            uint32_t bB = (uint32_t)__cvta_generic_to_shared(&Bsh[buf][brow][0]) + lc * 16; \
            _Pragma("unroll") for (int np = 0; np < 2; np++) { \
                LDSM4(bh[np], bB + np * 16 * 48); \
            } \
        } \
        _Pragma("unroll") for (int mt = 0; mt < 4; mt++) { \
            _Pragma("unroll") for (int nt = 0; nt < 4; nt++) { \
                const int np = nt >> 1, sel = nt & 1; \
                MMA16816(acc[mt][nt], ah[mt], bh[np][sel], bh[np][sel + 2]); \
            } \
        } \
        if (kt + 1 < (NK)) { \
            buf ^= 1; \
            *(uint4*)&Ash[buf][arow][aseg * 8] = ra; \
            *(uint4*)&Bsh[buf][arow][aseg * 8] = rb; \
            __syncthreads(); \
        } \
    }

// Row-major C: C[m0+row][n0+col]
__global__ __launch_bounds__(256) void k_mma(const uint16_t* __restrict__ Ag,
                                             const uint16_t* __restrict__ Bg,
                                             float* __restrict__ Cg, int K, int ldc) {
    GEMM_DECL_SMEM();
    GEMM_THREAD_IDS();
    const int m0 = blockIdx.y * 128, n0 = blockIdx.x * 128;
    const uint16_t* pA = Ag + (size_t)(m0 + arow) * K + aseg * 8;
    const uint16_t* pB = Bg + (size_t)(n0 + arow) * K + aseg * 8;
    const int NK = K >> 4;
    GEMM_ACC_INIT();
    GEMM_MAINLOOP(pA, pB, NK);

    float* Cbase = Cg + (size_t)m0 * ldc + n0;
#pragma unroll
    for (int mt = 0; mt < 4; mt++) {
        int row = wm * 64 + mt * 16 + (lane >> 2);
#pragma unroll
        for (int nt = 0; nt < 4; nt++) {
            int col = wn * 32 + nt * 8 + (lane & 3) * 2;
            *(float2*)(Cbase + (size_t)row * ldc + col) = make_float2(acc[mt][nt][0], acc[mt][nt][1]);
            *(float2*)(Cbase + (size_t)(row + 8) * ldc + col) = make_float2(acc[mt][nt][2], acc[mt][nt][3]);
        }
    }
}

// x_dbl GEMM: A = WxH[br] (128 x 1536), B = xcT[br] (4096 x 1536), split-K 3, atomic epilogue
__global__ __launch_bounds__(256) void k_gx() {
    GEMM_DECL_SMEM();
    GEMM_THREAD_IDS();
    const int z = blockIdx.z;
    const int br = z / 3, ks = z - br * 3;
    const int k0 = ks * 512;
    const int K = D_INNER;
    const uint16_t* Ag = g_WxH[br];
    const uint16_t* Bg = g_xcT[br];
    const int n0 = blockIdx.x * 128;
    const uint16_t* pA = Ag + (size_t)arow * K + k0 + aseg * 8;
    const uint16_t* pB = Bg + (size_t)(n0 + arow) * K + k0 + aseg * 8;
    const int NK = 32;
    GEMM_ACC_INIT();
    GEMM_MAINLOOP(pA, pB, NK);

    const int b = n0 >> 11;
    const int l0c = n0 & (L_SEQ - 1);
    float* xd = g_xdbl[br] + ((size_t)b * XD) * L_SEQ + l0c;
#pragma unroll
    for (int mt = 0; mt < 4; mt++) {
        int row = wm * 64 + mt * 16 + (lane >> 2);
#pragma unroll
        for (int nt = 0; nt < 4; nt++) {
            int col = wn * 32 + nt * 8 + (lane & 3) * 2;
            if (row < XD) {
                atomicAdd(xd + (size_t)row * L_SEQ + col, acc[mt][nt][0]);
                atomicAdd(xd + (size_t)row * L_SEQ + col + 1, acc[mt][nt][1]);
            }
            if (row + 8 < XD) {
                atomicAdd(xd + (size_t)(row + 8) * L_SEQ + col, acc[mt][nt][2]);
                atomicAdd(xd + (size_t)(row + 8) * L_SEQ + col + 1, acc[mt][nt][3]);
            }
        }
    }
}

// dt GEMM: A = dtloH[br] (4096 x 64), B = WdtH[br] (1536 x 64); softplus epilogue, token-major out
__global__ __launch_bounds__(256) void k_gdt(const float* __restrict__ bdt,
                                             const float* __restrict__ bdtb) {
    GEMM_DECL_SMEM();
    GEMM_THREAD_IDS();
    const int br = blockIdx.z;
    const int K = 64;
    const uint16_t* Ag = g_dtloH[br];
    const uint16_t* Bg = g_WdtH[br];
    const float* bias = br ? bdtb : bdt;
    const int m0 = blockIdx.y * 128, n0 = blockIdx.x * 128;
    const uint16_t* pA = Ag + (size_t)(m0 + arow) * K + aseg * 8;
    const uint16_t* pB = Bg + (size_t)(n0 + arow) * K + aseg * 8;
    const int NK = 4;
    GEMM_ACC_INIT();
    GEMM_MAINLOOP(pA, pB, NK);

    float* dst = g_dt[br] + (size_t)m0 * D_INNER + n0;
#pragma unroll
    for (int mt = 0; mt < 4; mt++) {
        int row = wm * 64 + mt * 16 + (lane >> 2);
#pragma unroll
        for (int nt = 0; nt < 4; nt++) {
            int col = wn * 32 + nt * 8 + (lane & 3) * 2;
            float b1 = bias[n0 + col], b2 = bias[n0 + col + 1];
            *(float2*)(dst + (size_t)row * D_INNER + col) =
                make_float2(softplusf(acc[mt][nt][0] + b1), softplusf(acc[mt][nt][1] + b2));
            *(float2*)(dst + (size_t)(row + 8) * D_INNER + col) =
                make_float2(softplusf(acc[mt][nt][2] + b1), softplusf(acc[mt][nt][3] + b2));
        }
    }
}

// ---------------- conv: token-major, fp16 outputs only ----------------
__global__ __launch_bounds__(256) void k_conv(const float* __restrict__ cw, const float* __restrict__ cb,
                                              const float* __restrict__ cwb, const float* __restrict__ cbb) {
    __shared__ float xs[38][33];
    const int tx = threadIdx.x, ty = threadIdx.y;
    const int tid = ty * 32 + tx;
    const int l0 = blockIdx.x * 32, d0 = blockIdx.y * 32;
    const int b = blockIdx.z;

    for (int lin = tid; lin < 38 * 32; lin += 256) {
        int r = lin >> 5, c = lin & 31;
        int l = l0 - 3 + r;
        xs[r][c] = (l >= 0 && l < L_SEQ) ? g_xz[((size_t)b * L_SEQ + l) * E2 + d0 + c] : 0.f;
    }
    __syncthreads();

    const int d = d0 + tx;
    float wf0 = cw[d * 4 + 0], wf1 = cw[d * 4 + 1], wf2 = cw[d * 4 + 2], wf3 = cw[d * 4 + 3];
    float wb0 = cwb[d * 4 + 0], wb1 = cwb[d * 4 + 1], wb2 = cwb[d * 4 + 2], wb3 = cwb[d * 4 + 3];
    float bf = cb[d], bbk = cbb[d];

#pragma unroll
    for (int i = 0; i < 4; i++) {
        int ll = ty + i * 8;
        float sf = bf + wf0 * xs[ll][tx] + wf1 * xs[ll + 1][tx] + wf2 * xs[ll + 2][tx] + wf3 * xs[ll + 3][tx];
        float sb = bbk + wb0 * xs[ll + 6][tx] + wb1 * xs[ll + 5][tx] + wb2 * xs[ll + 4][tx] + wb3 * xs[ll + 3][tx];
        size_t tf = (size_t)b * L_SEQ + l0 + ll;
        size_t tb = (size_t)b * L_SEQ + (L_SEQ - 1 - l0 - ll);
        g_xcT[0][tf * D_INNER + d] = h16(siluf(sf));
        g_xcT[1][tb * D_INNER + d] = h16(siluf(sb));
    }
}

// ---------------- zero g_xdbl ----------------
__global__ __launch_bounds__(256) void k_zero(float4* p, int n4) {
    int i = blockIdx.x * blockDim.x + threadIdx.x;
    if (i < n4) p[i] = make_float4(0.f, 0.f, 0.f, 0.f);
}

// ---------------- dt_lo transpose: g_xdbl rows 0..47 -> [token][64] fp16 ----------------
__global__ __launch_bounds__(256) void k_dtloT() {
    __shared__ float s[48][65];
    const int tid = threadIdx.x;
    const int l0 = blockIdx.x * 64;
    const int b = blockIdx.y;
    const int br = blockIdx.z;
    const float* xd = g_xdbl[br] + ((size_t)b * XD) * L_SEQ;
    for (int lin = tid; lin < 48 * 64; lin += 256) {
        int r = lin >> 6, ll = lin & 63;
        s[r][ll] = xd[(size_t)r * L_SEQ + l0 + ll];
    }
    __syncthreads();
    uint16_t* dst = g_dtloH[br] + ((size_t)b * L_SEQ + l0) * 64;
    for (int lin = tid; lin < 64 * 64; lin += 256) {
        int ll = lin >> 6, r = lin & 63;
        dst[(size_t)ll * 64 + r] = (r < DR) ? h16(s[r][ll]) : (uint16_t)0;
    }
}

// ---------------- scan pass 1 (token-major, fp16 x) ----------------
__global__ __launch_bounds__(128) void k_scan1(const float* __restrict__ Alog, const float* __restrict__ Alogb) {
    const int tid = threadIdx.x;
    const int d = blockIdx.x * 128 + tid;
    const int chunk = blockIdx.y;
    const int zb = blockIdx.z;
    const int br = zb >> 1, b = zb & 1;
    const float* Al = br ? Alogb : Alog;
    float a[DS];
    int fast = 1;
#pragma unroll
    for (int n = 0; n < DS; n++) {
        a[n] = -expf(Al[d * DS + n]);
        fast &= (fabsf(a[n] + (float)(n + 1)) < 1e-4f * (float)(n + 1));
    }

    __shared__ float Bsh[CHL][DS + 1];
    const int l0 = chunk * CHL;
    const float* xd = g_xdbl[br] + (b * XD) * L_SEQ;
    for (int i = tid; i < CHL * DS; i += 128) {
        int n = i >> 7, t = i & (CHL - 1);
        Bsh[t][n] = xd[(DR + n) * L_SEQ + l0 + t];
    }
    __syncthreads();

    const float* dtp = g_dt[br] + ((size_t)b * L_SEQ + l0) * D_INNER + d;
    const __half* xp = (const __half*)g_xcT[br] + ((size_t)b * L_SEQ + l0) * D_INNER + d;
    float h[DS];
    float S = 0.f;
#pragma unroll
    for (int n = 0; n < DS; n++) h[n] = 0.f;

    if (fast) {
#pragma unroll 2
        for (int t = 0; t < CHL; t++) {
            float dt = dtp[(size_t)t * D_INNER];
            float x = __half2float(xp[(size_t)t * D_INNER]);
            float dtx = dt * x;
            float r = __expf(-dt);
            S += dt;
            float p = 1.f;
#pragma unroll
            for (int n = 0; n < DS; n++) {
                p *= r;
                h[n] = fmaf(p, h[n], dtx * Bsh[t][n]);
            }
        }
    } else {
#pragma unroll 2
        for (int t = 0; t < CHL; t++) {
            float dt = dtp[(size_t)t * D_INNER];
            float x = __half2float(xp[(size_t)t * D_INNER]);
            float dtx = dt * x;
            S += dt;
#pragma unroll
            for (int n = 0; n < DS; n++) {
                float dA = __expf(dt * a[n]);
                h[n] = fmaf(dA, h[n], dtx * Bsh[t][n]);
            }
        }
    }
    size_t base = ((size_t)(zb * D_INNER + d) * NCH + chunk) * DS;
#pragma unroll
    for (int n = 0; n < DS; n++) {
        g_hfin[base + n] = h[n];
        g_P[base + n] = __expf(a[n] * S);
    }
}

// ---------------- scan pass 2 ----------------
__global__ void k_scan2() {
    int id = blockIdx.x * blockDim.x + threadIdx.x;
    if (id >= 2 * BSZ * D_INNER * DS) return;
    int n = id & 15;
    int rest = id >> 4;
    int d = rest % D_INNER;
    int zb = rest / D_INNER;
    size_t base = ((size_t)(zb * D_INNER + d)) * (NCH * DS) + n;
    float H = 0.f;
#pragma unroll
    for (int c = 0; c < NCH; c++) {
        g_Hinit[base + c * DS] = H;
        H = g_P[base + c * DS] * H + g_hfin[base + c * DS];
    }
}

// ---------------- scan pass 3 (token-major, fp16 x) ----------------
__global__ __launch_bounds__(128) void k_scan3(const float* __restrict__ Alog, const float* __restrict__ Alogb,
                                               const float* __restrict__ Dp, const float* __restrict__ Dpb) {
    const int tid = threadIdx.x;
    const int d = blockIdx.x * 128 + tid;
    const int chunk = blockIdx.y;
    const int zb = blockIdx.z;
    const int br = zb >> 1, b = zb & 1;
    const float* Al = br ? Alogb : Alog;
    float a[DS];
    int fast = 1;
#pragma unroll
    for (int n = 0; n < DS; n++) {
        a[n] = -expf(Al[d * DS + n]);
        fast &= (fabsf(a[n] + (float)(n + 1)) < 1e-4f * (float)(n + 1));
    }

    __shared__ float Bsh[CHL][DS + 1];
    __shared__ float Csh[CHL][DS + 1];
    const int l0 = chunk * CHL;
    const float* xd = g_xdbl[br] + (b * XD) * L_SEQ;
    for (int i = tid; i < CHL * DS; i += 128) {
        int n = i >> 7, t = i & (CHL - 1);
        Bsh[t][n] = xd[(DR + n) * L_SEQ + l0 + t];
        Csh[t][n] = xd[(DR + DS + n) * L_SEQ + l0 + t];
    }
    __syncthreads();

    size_t sbase = ((size_t)(zb * D_INNER + d) * NCH + chunk) * DS;
    float h[DS];
#pragma unroll
    for (int n = 0; n < DS; n++) h[n] = g_Hinit[sbase + n];
    float Dd = (br ? Dpb : Dp)[d];

    const float* dtp = g_dt[br] + ((size_t)b * L_SEQ + l0) * D_INNER + d;
    const __half* xp = (const __half*)g_xcT[br] + ((size_t)b * L_SEQ + l0) * D_INNER + d;
    float* op = g_acc[br] + ((size_t)b * L_SEQ + l0) * D_INNER + d;
    const float* zp;
    ptrdiff_t zstep;
    if (!br) {
        zp = g_xz + ((size_t)b * L_SEQ + l0) * E2 + D_INNER + d;
        zstep = E2;
    } else {
        zp = g_xz + ((size_t)b * L_SEQ + (L_SEQ - 1 - l0)) * E2 + D_INNER + d;
        zstep = -(ptrdiff_t)E2;
    }

    if (fast) {
#pragma unroll 2
        for (int t = 0; t < CHL; t++) {
            float dt = dtp[(size_t)t * D_INNER];
            float x = __half2float(xp[(size_t)t * D_INNER]);
            float dtx = dt * x;
            float r = __expf(-dt);
            float p = 1.f;
            float y = 0.f;
#pragma unroll
            for (int n = 0; n < DS; n++) {
                p *= r;
                h[n] = fmaf(p, h[n], dtx * Bsh[t][n]);
                y = fmaf(h[n], Csh[t][n], y);
            }
            float zv = zp[(ptrdiff_t)t * zstep];
            op[(size_t)t * D_INNER] = (y + Dd * x) * siluf(zv);
        }
    } else {
#pragma unroll 2
        for (int t = 0; t < CHL; t++) {
            float dt = dtp[(size_t)t * D_INNER];
            float x = __half2float(xp[(size_t)t * D_INNER]);
            float dtx = dt * x;
            float y = 0.f;
#pragma unroll
            for (int n = 0; n < DS; n++) {
                float dA = __expf(dt * a[n]);
                h[n] = fmaf(dA, h[n], dtx * Bsh[t][n]);
                y = fmaf(h[n], Csh[t][n], y);
            }
            float zv = zp[(ptrdiff_t)t * zstep];
            op[(size_t)t * D_INNER] = (y + Dd * x) * siluf(zv);
        }
    }
}

// ---------------- mid combine + fp16 pack (elementwise, token-major) ----------------
__global__ __launch_bounds__(256) void k_midT() {
    int i4 = blockIdx.x * blockDim.x + threadIdx.x;
    const int DV = D_INNER / 4;
    if (i4 >= NTOK * DV) return;
    int tok = i4 / DV;
    int d4 = i4 - tok * DV;
    int b = tok >> 11, l = tok & (L_SEQ - 1);
    int rtok = (b << 11) + (L_SEQ - 1 - l);
    float4 f = ((const float4*)g_acc[0])[i4];
    float4 r = ((const float4*)g_acc[1])[(size_t)rtok * DV + d4];
    ushort4 o;
    o.x = h16(0.5f * (f.x + r.x));
    o.y = h16(0.5f * (f.y + r.y));
    o.z = h16(0.5f * (f.z + r.z));
    o.w = h16(0.5f * (f.w + r.w));
    ((ushort4*)g_midH)[i4] = o;
}

// ---------------- launch ----------------
extern "C" void kernel_launch(void* const* d_in, const int* in_sizes, int n_in,
                              void* d_out, int out_size) {
    const float* hid  = (const float*)d_in[0];
    const float* Win  = (const float*)d_in[1];
    const float* cw   = (const float*)d_in[2];
    const float* cb   = (const float*)d_in[3];
    const float* cwb  = (const float*)d_in[4];
    const float* cbb  = (const float*)d_in[5];
    const float* Wx   = (const float*)d_in[6];
    const float* Wxb  = (const float*)d_in[7];
    const float* Wdt  = (const float*)d_in[8];
    const float* bdt  = (const float*)d_in[9];
    const float* Wdtb = (const float*)d_in[10];
    const float* bdtb = (const float*)d_in[11];
    const float* Alog = (const float*)d_in[12];
    const float* Alogb= (const float*)d_in[13];
    const float* Dp   = (const float*)d_in[14];
    const float* Dpb  = (const float*)d_in[15];
    const float* Wout = (const float*)d_in[16];
    float* out = (float*)d_out;

    uint16_t *hidH, *WinH, *WoutH, *midH;
    float *xzP, *xdblP;
    cudaGetSymbolAddress((void**)&hidH, g_hidH);
    cudaGetSymbolAddress((void**)&WinH, g_WinH);
    cudaGetSymbolAddress((void**)&WoutH, g_WoutH);
    cudaGetSymbolAddress((void**)&midH, g_midH);
    cudaGetSymbolAddress((void**)&xzP, g_xz);
    cudaGetSymbolAddress((void**)&xdblP, g_xdbl);

    k_packh<<<(NTOK * D_MODEL / 4 + 255) / 256, 256>>>((const float4*)hid, (ushort4*)hidH, NTOK * D_MODEL / 4);
    k_packh<<<(E2 * D_MODEL / 4 + 255) / 256, 256>>>((const float4*)Win, (ushort4*)WinH, E2 * D_MODEL / 4);
    k_packh<<<(D_MODEL * D_INNER / 4 + 255) / 256, 256>>>((const float4*)Wout, (ushort4*)WoutH, D_MODEL * D_INNER / 4);
    k_packWx<<<(2 * 128 * D_INNER + 255) / 256, 256>>>(Wx, Wxb);
    k_packWdt<<<(2 * D_INNER * 64 + 255) / 256, 256>>>(Wdt, Wdtb);

    // xz[token][e] = hid @ Win^T
    k_mma<<<dim3(E2 / 128, NTOK / 128), 256>>>(hidH, WinH, xzP, D_MODEL, E2);

    // conv + silu -> fp16 token-major
    k_conv<<<dim3(L_SEQ / 32, D_INNER / 32, BSZ), dim3(32, 8)>>>(cw, cb, cwb, cbb);

    // x_dbl = Wx @ xc
    k_zero<<<(2 * BSZ * XD * L_SEQ / 4 + 255) / 256, 256>>>((float4*)xdblP, 2 * BSZ * XD * L_SEQ / 4);
    k_gx<<<dim3(NTOK / 128, 1, 6), 256>>>();

    // dt = softplus(dt_lo @ Wdt^T + b)
    k_dtloT<<<dim3(L_SEQ / 64, BSZ, 2), 256>>>();
    k_gdt<<<dim3(D_INNER / 128, NTOK / 128, 2), 256>>>(bdt, bdtb);

    k_scan1<<<dim3(D_INNER / 128, NCH, 4), 128>>>(Alog, Alogb);
    k_scan2<<<(2 * BSZ * D_INNER * DS + 255) / 256, 256>>>();
    k_scan3<<<dim3(D_INNER / 128, NCH, 4), 128>>>(Alog, Alogb, Dp, Dpb);

    k_midT<<<(NTOK * D_INNER / 4 + 255) / 256, 256>>>();

    // out = mid @ Wout^T
    k_mma<<<dim3(D_MODEL / 128, NTOK / 128), 256>>>(midH, WoutH, out, D_INNER, D_MODEL);
}